// round 12
// baseline (speedup 1.0000x reference)
#include <cuda_runtime.h>
#include <cuda_fp16.h>
#include <cstdint>
#include <math.h>

#define Bdim 128
#define Sdim 128
#define Ddim 256
#define Hdim 8
#define HDim 32
#define Fdim 2048
#define Ldim 4
#define BHdim (Bdim*Hdim)     /* 1024 */
#define NR (Bdim*Sdim)        /* 16384 rows */
#define QKVS 768              /* fused qkv row stride */

// ---------------- scratch (device globals; no allocation allowed) ----------
__device__ float g_x[NR*Ddim];
__device__ float g_qkv[(size_t)NR*QKVS];
__device__ float g_ctx[NR*Ddim];
__device__ float g_tmp[NR*Ddim];
__device__ float g_eb[(size_t)BHdim*Sdim*Sdim];   // [bh][j][i]
__device__ float g_at[(size_t)BHdim*Sdim*Sdim];   // [bh][i][j]
// fp16 hi/lo activation pairs
__device__ __half g_xh[NR*Ddim];
__device__ __half g_xl[NR*Ddim];
__device__ __half g_ch[NR*Ddim];
__device__ __half g_cl[NR*Ddim];
__device__ __half g_ffh[(size_t)NR*Fdim];
__device__ __half g_ffl[(size_t)NR*Fdim];
// transposed fp16 weights [N][K]
__device__ __half g_wqkvT[(size_t)Ldim*3*Ddim*Ddim];
__device__ __half g_woT[(size_t)Ldim*Ddim*Ddim];
__device__ __half g_w1T[(size_t)Ldim*Fdim*Ddim];
__device__ __half g_w2T[(size_t)Ldim*Ddim*Fdim];
__device__ float g_bqkv[Ldim*QKVS];

// ==================== helpers =============================================
__device__ __forceinline__ uint32_t smem_u32(const void* p) {
    uint32_t a;
    asm("{ .reg .u64 t; cvta.to.shared.u64 t, %1; cvt.u32.u64 %0, t; }"
        : "=r"(a) : "l"(p));
    return a;
}
#define LDSM_X4(R0,R1,R2,R3,ADDR) \
    asm volatile("ldmatrix.sync.aligned.m8n8.x4.shared.b16 {%0,%1,%2,%3}, [%4];" \
        : "=r"(R0), "=r"(R1), "=r"(R2), "=r"(R3) : "r"(ADDR) : "memory")
#define CP16(dst, src) \
    asm volatile("cp.async.cg.shared.global [%0], [%1], 16;" :: "r"(dst), "l"(src))

#define MBARRIER_INIT(addr, cnt) \
    asm volatile("mbarrier.init.shared.b64 [%0], %1;" \
        :: "r"((uint32_t)(addr)), "r"((uint32_t)(cnt)) : "memory")
#define MBARRIER_ARRIVE(addr) \
    asm volatile("mbarrier.arrive.shared.b64 _, [%0];" \
        :: "r"((uint32_t)(addr)) : "memory")
// .noinc: deferred completion-arrive counts against the init count.
#define CPASYNC_MBAR_ARRIVE(addr) \
    asm volatile("cp.async.mbarrier.arrive.noinc.shared.b64 [%0];" \
        :: "r"((uint32_t)(addr)) : "memory")
#define MBARRIER_WAIT_PARITY(addr, par) do { \
    uint32_t _m = (uint32_t)(addr), _p = (uint32_t)(par), _d; \
    asm volatile("{\n\t.reg .pred p;\n\t" \
        "mbarrier.try_wait.parity.acquire.cta.shared::cta.b64 p, [%1], %2;\n\t" \
        "selp.b32 %0, 1, 0, p;\n\t}" : "=r"(_d) : "r"(_m), "r"(_p) : "memory"); \
    if (!_d) { \
        asm volatile("{\n\t.reg .pred P1;\n\t" \
            "WL_%=:\n\t" \
            "mbarrier.try_wait.parity.acquire.cta.shared::cta.b64 P1, [%0], %1, 0x989680;\n\t" \
            "@P1 bra.uni WD_%=;\n\t" \
            "bra.uni WL_%=;\n\t" \
            "WD_%=:\n\t}" :: "r"(_m), "r"(_p) : "memory"); \
    } } while(0)

__device__ __forceinline__ void mma_f16(
    float& c0, float& c1, float& c2, float& c3,
    uint32_t a0, uint32_t a1, uint32_t a2, uint32_t a3,
    uint32_t b0, uint32_t b1)
{
    asm volatile(
        "mma.sync.aligned.m16n8k16.row.col.f32.f16.f16.f32 "
        "{%0,%1,%2,%3}, {%4,%5,%6,%7}, {%8,%9}, {%0,%1,%2,%3};"
        : "+f"(c0), "+f"(c1), "+f"(c2), "+f"(c3)
        : "r"(a0), "r"(a1), "r"(a2), "r"(a3), "r"(b0), "r"(b1));
}

__device__ __forceinline__ void split16(float v, __half& h, __half& l) {
    h = __float2half_rn(v);
    l = __float2half_rn(v - __half2float(h));
}

// ==================== fp16 split-A mma GEMM ================================
// C[M,N] = (Ah+Al)[M,K] @ BT[N,K]^T + bias. 256 threads, CTA tile 128x128,
// 8 warps (4m x 2n), warp tile 32x64. 3-stage pipeline with warp-0 producer:
//   full[s]: count 32, cp.async.noinc arrives (warp 0's lanes)
//   empty[s]: count 8, lane-0-per-warp arrives
// NO __syncthreads in the mainloop.
#define CH 32
#define SKH 40                          /* smem halves per row (32 + 8 pad) */
#define TILEB (128 * SKH * 2)           /* 10240 B per tile */
#define CHUNKB (3 * TILEB)              /* AH + AL + B per stage */
#define NSTG 3
#define GSMB (NSTG * CHUNKB)            /* 92160 B */

template<bool RELU, bool OUTH>
__global__ __launch_bounds__(256, 2) void mma_gemm(
    const __half* __restrict__ Ah, const __half* __restrict__ Al,
    const __half* __restrict__ BT, const float* __restrict__ bias,
    float* __restrict__ C, __half* __restrict__ Ch, __half* __restrict__ Cl,
    int M, int N, int K)
{
    extern __shared__ __half sh[];
    __shared__ __align__(8) unsigned long long mbar[2 * NSTG];
    const uint32_t s0 = smem_u32(sh);
    const uint32_t mbF = smem_u32(&mbar[0]);
    const uint32_t mbE = smem_u32(&mbar[NSTG]);
    const int tid = threadIdx.x;
    const int lane = tid & 31, wid = tid >> 5;
    const int wm = (wid >> 1) * 32, wn = (wid & 1) * 64;
    const int m0 = blockIdx.y * 128, n0 = blockIdx.x * 128;
    const int nch = K / CH;             // >= 8 always

    if (tid < NSTG)                MBARRIER_INIT(mbF + tid * 8, 32);
    else if (tid < 2 * NSTG)       MBARRIER_INIT(mbE + (tid - NSTG) * 8, 8);
    __syncthreads();

    const uint32_t a_loff = (uint32_t)(((lane & 15) * SKH + ((lane >> 4) << 3)) * 2);
    const uint32_t b_loff = (uint32_t)((((lane & 7) + ((lane >> 4) << 3)) * SKH
                                        + (((lane >> 3) & 1) << 3)) * 2);

    // producer state (warp 0's lanes): one row per lane, 4 row-blocks x 4 segs
    const __half* pA = Ah + (size_t)(m0 + lane) * K;
    const __half* pL = Al + (size_t)(m0 + lane) * K;
    const __half* pB = BT + (size_t)(n0 + lane) * K;

    auto issue = [&](int c) {           // called by warp 0 only (all 32 lanes)
        const uint32_t stg = s0 + (uint32_t)((c % NSTG) * CHUNKB);
        const uint32_t dl = stg + (uint32_t)(lane * SKH * 2);
#pragma unroll
        for (int rb = 0; rb < 4; ++rb)
#pragma unroll
            for (int sg = 0; sg < 4; ++sg) {
                const size_t so = (size_t)(rb * 32) * K + (size_t)c * CH + sg * 8;
                const uint32_t doff = (uint32_t)(rb * 32 * SKH * 2 + sg * 16);
                CP16(dl + doff,              pA + so);
                CP16(dl + TILEB + doff,      pL + so);
                CP16(dl + 2 * TILEB + doff,  pB + so);
            }
        CPASYNC_MBAR_ARRIVE(mbF + (c % NSTG) * 8);
    };

    float acc[2][8][4];
#pragma unroll
    for (int mt = 0; mt < 2; ++mt)
#pragma unroll
        for (int nt = 0; nt < 8; ++nt)
#pragma unroll
            for (int e = 0; e < 4; ++e) acc[mt][nt][e] = 0.f;

    if (wid == 0) { issue(0); issue(1); issue(2); }

    for (int c = 0; c < nch; ++c) {
        const int s = c % NSTG, g = c / NSTG;
        MBARRIER_WAIT_PARITY(mbF + s * 8, g & 1);

        const uint32_t stg = s0 + (uint32_t)(s * CHUNKB);
        const uint32_t ahb = stg + (uint32_t)(wm * SKH * 2) + a_loff;
        const uint32_t alb = ahb + TILEB;
        const uint32_t bhb = stg + 2 * TILEB + (uint32_t)(wn * SKH * 2) + b_loff;
#pragma unroll
        for (int ss = 0; ss < 2; ++ss) {
            const uint32_t kb2 = ss * 32;   // 16 halves = 32 bytes
            uint32_t bfr[8][2];
#pragma unroll
            for (int p = 0; p < 4; ++p) {
                uint32_t r0, r1, r2, r3;
                LDSM_X4(r0, r1, r2, r3,
                        bhb + (uint32_t)(p * 16 * SKH * 2) + kb2);
                bfr[p*2][0] = r0; bfr[p*2][1] = r1;
                bfr[p*2+1][0] = r2; bfr[p*2+1][1] = r3;
            }
            uint32_t ah[2][4], al[2][4];
#pragma unroll
            for (int mt = 0; mt < 2; ++mt) {
                LDSM_X4(ah[mt][0], ah[mt][1], ah[mt][2], ah[mt][3],
                        ahb + (uint32_t)(mt * 16 * SKH * 2) + kb2);
                LDSM_X4(al[mt][0], al[mt][1], al[mt][2], al[mt][3],
                        alb + (uint32_t)(mt * 16 * SKH * 2) + kb2);
            }
#pragma unroll
            for (int nt = 0; nt < 8; ++nt)
#pragma unroll
                for (int mt = 0; mt < 2; ++mt)
                    mma_f16(acc[mt][nt][0], acc[mt][nt][1],
                            acc[mt][nt][2], acc[mt][nt][3],
                            ah[mt][0], ah[mt][1], ah[mt][2], ah[mt][3],
                            bfr[nt][0], bfr[nt][1]);
#pragma unroll
            for (int nt = 0; nt < 8; ++nt)
#pragma unroll
                for (int mt = 0; mt < 2; ++mt)
                    mma_f16(acc[mt][nt][0], acc[mt][nt][1],
                            acc[mt][nt][2], acc[mt][nt][3],
                            al[mt][0], al[mt][1], al[mt][2], al[mt][3],
                            bfr[nt][0], bfr[nt][1]);
        }

        if (lane == 0) MBARRIER_ARRIVE(mbE + s * 8);   // consumed stage s
        if (wid == 0 && c + NSTG < nch) {
            MBARRIER_WAIT_PARITY(mbE + s * 8, g & 1);  // all 8 warps done
            issue(c + NSTG);
        }
    }

    const int qr = lane >> 2, qc = lane & 3;
#pragma unroll
    for (int mt = 0; mt < 2; ++mt) {
        const int r = m0 + wm + mt * 16 + qr;
#pragma unroll
        for (int nt = 0; nt < 8; ++nt) {
            const int col = n0 + wn + nt * 8 + qc * 2;
            float b0 = bias[col], b1 = bias[col + 1];
            float v00 = acc[mt][nt][0] + b0, v01 = acc[mt][nt][1] + b1;
            float v10 = acc[mt][nt][2] + b0, v11 = acc[mt][nt][3] + b1;
            if (RELU) {
                v00 = fmaxf(v00, 0.f); v01 = fmaxf(v01, 0.f);
                v10 = fmaxf(v10, 0.f); v11 = fmaxf(v11, 0.f);
            }
            if (OUTH) {
                __half h00, l00, h01, l01, h10, l10, h11, l11;
                split16(v00, h00, l00); split16(v01, h01, l01);
                split16(v10, h10, l10); split16(v11, h11, l11);
                *(__half2*)(Ch + (size_t)r * N + col)       = __halves2half2(h00, h01);
                *(__half2*)(Cl + (size_t)r * N + col)       = __halves2half2(l00, l01);
                *(__half2*)(Ch + (size_t)(r + 8) * N + col) = __halves2half2(h10, h11);
                *(__half2*)(Cl + (size_t)(r + 8) * N + col) = __halves2half2(l10, l11);
            } else {
                *(float2*)(C + (size_t)r * N + col)       = make_float2(v00, v01);
                *(float2*)(C + (size_t)(r + 8) * N + col) = make_float2(v10, v11);
            }
        }
    }
}

// ============ fused weight transpose -> fp16 [N][K] (single launch) ========
__global__ __launch_bounds__(256) void tr_all(
    const float* __restrict__ Wq, const float* __restrict__ Wk,
    const float* __restrict__ Wv, const float* __restrict__ Wo,
    const float* __restrict__ W1, const float* __restrict__ W2,
    __half* __restrict__ wqkvT, __half* __restrict__ woT,
    __half* __restrict__ w1T, __half* __restrict__ w2T)
{
    __shared__ float t[32][33];
    const int tb = blockIdx.x;
    const float* src; __half* dst; int K, N, kx, nx;
    if (tb < 768) {
        int w = tb / 256, r = tb % 256, l = r / 64, q = r % 64;
        src = (w == 0 ? Wq : (w == 1 ? Wk : Wv)) + (size_t)l * 65536;
        dst = wqkvT + (size_t)l * 196608 + (size_t)w * 65536;
        K = 256; N = 256; kx = (q / 8) * 32; nx = (q % 8) * 32;
    } else if (tb < 1024) {
        int r = tb - 768, l = r / 64, q = r % 64;
        src = Wo + (size_t)l * 65536; dst = woT + (size_t)l * 65536;
        K = 256; N = 256; kx = (q / 8) * 32; nx = (q % 8) * 32;
    } else if (tb < 3072) {
        int r = tb - 1024, l = r / 512, q = r % 512;
        src = W1 + (size_t)l * 524288; dst = w1T + (size_t)l * 524288;
        K = 256; N = 2048; kx = (q / 64) * 32; nx = (q % 64) * 32;
    } else {
        int r = tb - 3072, l = r / 512, q = r % 512;
        src = W2 + (size_t)l * 524288; dst = w2T + (size_t)l * 524288;
        K = 2048; N = 256; kx = (q / 8) * 32; nx = (q % 8) * 32;
    }
    const int x = threadIdx.x & 31, y = threadIdx.x >> 5;
#pragma unroll
    for (int yy = y; yy < 32; yy += 8)
        t[yy][x] = src[(size_t)(kx + yy) * N + nx + x];
    __syncthreads();
#pragma unroll
    for (int yy = y; yy < 32; yy += 8)
        dst[(size_t)(nx + yy) * K + kx + x] = __float2half_rn(t[x][yy]);
}

// ---- prep: copy facts -> x + hi/lo split ----------------------------------
__global__ void prep_kernel(const float* __restrict__ facts, float* __restrict__ x,
                            __half* __restrict__ xh, __half* __restrict__ xl)
{
    size_t idx = (size_t)blockIdx.x * 256 + threadIdx.x;
    float v = facts[idx];
    x[idx] = v;
    __half h, l;
    split16(v, h, l);
    xh[idx] = h; xl[idx] = l;
}

__global__ void pack_bias(const float* bq, const float* bk, const float* bv,
                          float* out)
{
    int idx = blockIdx.x * 256 + threadIdx.x;
    if (idx >= Ldim * QKVS) return;
    int l = idx / QKVS, j = idx % QKVS;
    float v;
    if (j < 256)      v = bq[l * 256 + j];
    else if (j < 512) v = bk[l * 256 + j - 256];
    else              v = bv[l * 256 + j - 512];
    out[idx] = v;
}

// -------- edge-key bias: eb[bh][j][i] = sum_d ek[j,i,d] * q[bh,j,d] --------
__global__ __launch_bounds__(256) void ebias_kernel(
    const float* __restrict__ qkv, const float* __restrict__ ek,
    float* __restrict__ eb)
{
    const int j   = blockIdx.x;
    const int bh0 = blockIdx.y * 128;
    __shared__ float Qs[32][132];
    __shared__ float Es[32][132];
    const int tid = threadIdx.x;
    {
        const int r = tid >> 1;
        const int half = tid & 1;
        const int bh = bh0 + r;
        const int b = bh >> 3, h = bh & 7;
        const float* qp = qkv + (size_t)(b * Sdim + j) * QKVS + h * HDim + half * 16;
        const float* ep = ek + (size_t)(j * Sdim + r) * HDim + half * 16;
#pragma unroll
        for (int c = 0; c < 4; c++) {
            float4 vq = *(const float4*)(qp + c * 4);
            float4 ve = *(const float4*)(ep + c * 4);
            int d = half * 16 + c * 4;
            Qs[d+0][r] = vq.x; Qs[d+1][r] = vq.y; Qs[d+2][r] = vq.z; Qs[d+3][r] = vq.w;
            Es[d+0][r] = ve.x; Es[d+1][r] = ve.y; Es[d+2][r] = ve.z; Es[d+3][r] = ve.w;
        }
    }
    __syncthreads();
    const int ty = tid >> 4, tx = tid & 15;
    float acc[8][8];
#pragma unroll
    for (int i = 0; i < 8; i++)
#pragma unroll
        for (int c = 0; c < 8; c++) acc[i][c] = 0.f;
#pragma unroll
    for (int d = 0; d < 32; d++) {
        float af[8], bf[8];
        *(float4*)&af[0] = *(const float4*)&Qs[d][ty * 8];
        *(float4*)&af[4] = *(const float4*)&Qs[d][ty * 8 + 4];
        *(float4*)&bf[0] = *(const float4*)&Es[d][tx * 8];
        *(float4*)&bf[4] = *(const float4*)&Es[d][tx * 8 + 4];
#pragma unroll
        for (int i = 0; i < 8; i++)
#pragma unroll
            for (int c = 0; c < 8; c++) acc[i][c] += af[i] * bf[c];
    }
#pragma unroll
    for (int i = 0; i < 8; i++) {
        float* op = eb + ((size_t)(bh0 + ty * 8 + i) * Sdim + j) * Sdim + tx * 8;
        *(float4*)(op)     = *(float4*)&acc[i][0];
        *(float4*)(op + 4) = *(float4*)&acc[i][4];
    }
}

// -------- attention per (b,h) ---------------------------------------------
#define ATT_FLOATS (2*32*132 + 128*32 + 128*129)
#define ATT_BYTES  (ATT_FLOATS * 4)
__global__ __launch_bounds__(256) void attn_kernel(
    const float* __restrict__ qkv, const float* __restrict__ eb,
    const unsigned char* __restrict__ mask,
    float* __restrict__ attn_out, float* __restrict__ ctx)
{
    extern __shared__ float sm[];
    float (*Qs)[132] = (float(*)[132])sm;
    float (*Ks)[132] = (float(*)[132])(sm + 32 * 132);
    float (*Vs)[32]  = (float(*)[32]) (sm + 2 * 32 * 132);
    float (*Sc)[129] = (float(*)[129])(sm + 2 * 32 * 132 + 128 * 32);
    const int bh = blockIdx.x;
    const int b = bh >> 3, h = bh & 7;
    const int tid = threadIdx.x;

    {
        const int r = tid >> 1;
        const int half = tid & 1;
        const float* base = qkv + (size_t)(b * Sdim + r) * QKVS + h * HDim + half * 16;
        const float* qp = base;
        const float* kp = base + 256;
        const float* vp = base + 512;
#pragma unroll
        for (int c = 0; c < 4; c++) {
            int d = half * 16 + c * 4;
            float4 vq = *(const float4*)(qp + c * 4);
            float4 vk = *(const float4*)(kp + c * 4);
            Qs[d+0][r] = vq.x; Qs[d+1][r] = vq.y; Qs[d+2][r] = vq.z; Qs[d+3][r] = vq.w;
            Ks[d+0][r] = vk.x; Ks[d+1][r] = vk.y; Ks[d+2][r] = vk.z; Ks[d+3][r] = vk.w;
            *(float4*)&Vs[r][d] = *(const float4*)(vp + c * 4);
        }
        const int warp = tid >> 5, lane = tid & 31;
        for (int jj = warp; jj < Sdim; jj += 8) {
            float4 t = *(const float4*)(eb + ((size_t)bh * Sdim + jj) * Sdim + lane * 4);
            Sc[lane*4+0][jj] = t.x; Sc[lane*4+1][jj] = t.y;
            Sc[lane*4+2][jj] = t.z; Sc[lane*4+3][jj] = t.w;
        }
    }
    __syncthreads();

    const int ty = tid >> 4, tx = tid & 15;
    const int i0 = ty * 8, j0 = tx * 8;
    float acc[8][8];
#pragma unroll
    for (int i = 0; i < 8; i++)
#pragma unroll
        for (int j = 0; j < 8; j++) acc[i][j] = 0.f;
#pragma unroll
    for (int d = 0; d < 32; d++) {
        float af[8], bf[8];
        *(float4*)&af[0] = *(const float4*)&Qs[d][i0];
        *(float4*)&af[4] = *(const float4*)&Qs[d][i0 + 4];
        *(float4*)&bf[0] = *(const float4*)&Ks[d][j0];
        *(float4*)&bf[4] = *(const float4*)&Ks[d][j0 + 4];
#pragma unroll
        for (int i = 0; i < 8; i++)
#pragma unroll
            for (int j = 0; j < 8; j++) acc[i][j] += af[i] * bf[j];
    }
    const float scale = 0.17677669529663687f;
    const float NEGINF = -__int_as_float(0x7f800000);
#pragma unroll
    for (int ii = 0; ii < 8; ii++) {
        unsigned long long mv =
            *(const unsigned long long*)(mask + ((size_t)bh * Sdim + i0 + ii) * Sdim + j0);
#pragma unroll
        for (int jj = 0; jj < 8; jj++) {
            float s = (acc[ii][jj] + Sc[i0 + ii][j0 + jj]) * scale;
            if ((mv >> (8 * jj)) & 0xffULL) s = NEGINF;
            Sc[i0 + ii][j0 + jj] = s;
        }
    }
    __syncthreads();

    {
        const int warp = tid >> 5, lane = tid & 31;
        for (int r = warp; r < Sdim; r += 8) {
            float vals[4];
#pragma unroll
            for (int c = 0; c < 4; c++) vals[c] = Sc[r][lane + 32 * c];
            float m = fmaxf(fmaxf(vals[0], vals[1]), fmaxf(vals[2], vals[3]));
#pragma unroll
            for (int o = 16; o > 0; o >>= 1) m = fmaxf(m, __shfl_xor_sync(0xffffffffu, m, o));
            float ssum = 0.f;
#pragma unroll
            for (int c = 0; c < 4; c++) { vals[c] = __expf(vals[c] - m); ssum += vals[c]; }
#pragma unroll
            for (int o = 16; o > 0; o >>= 1) ssum += __shfl_xor_sync(0xffffffffu, ssum, o);
            float inv = 1.f / ssum;
            float* ap = attn_out + ((size_t)bh * Sdim + r) * Sdim;
#pragma unroll
            for (int c = 0; c < 4; c++) {
                float p = vals[c] * inv;
                Sc[r][lane + 32 * c] = p;
                ap[lane + 32 * c] = p;
            }
        }
    }
    __syncthreads();

    const int ig = tid >> 3;
    const int dg = tid & 7;
    float o[4][4];
#pragma unroll
    for (int c = 0; c < 4; c++)
#pragma unroll
        for (int e = 0; e < 4; e++) o[c][e] = 0.f;
    for (int j = 0; j < Sdim; j++) {
        float4 vv = *(const float4*)&Vs[j][dg * 4];
#pragma unroll
        for (int c = 0; c < 4; c++) {
            float p = Sc[ig * 4 + c][j];
            o[c][0] += p * vv.x; o[c][1] += p * vv.y;
            o[c][2] += p * vv.z; o[c][3] += p * vv.w;
        }
    }
#pragma unroll
    for (int c = 0; c < 4; c++) {
        float* cp = ctx + (size_t)(b * Sdim + ig * 4 + c) * Ddim + h * HDim + dg * 4;
        *(float4*)cp = make_float4(o[c][0], o[c][1], o[c][2], o[c][3]);
    }
}

// -------- edge-value: ctx += attn @ ev, then hi/lo split out ---------------
#define EV_FLOATS (128*132 + 128*32)
#define EV_BYTES  (EV_FLOATS * 4)
__global__ __launch_bounds__(256) void ev_kernel(
    const float* __restrict__ attn, const float* __restrict__ ev,
    const float* __restrict__ ctx,
    __half* __restrict__ ch, __half* __restrict__ cl)
{
    const int i   = blockIdx.x;
    const int bh0 = blockIdx.y * 128;
    extern __shared__ float sm2[];
    float (*As)[132]  = (float(*)[132])sm2;
    float (*Evs)[32]  = (float(*)[32])(sm2 + 128 * 132);
    const int tid = threadIdx.x;
    {
        const int warp = tid >> 5, lane = tid & 31;
        for (int r = warp; r < 128; r += 8) {
            const float* p = attn + ((size_t)(bh0 + r) * Sdim + i) * Sdim + lane * 4;
            *(float4*)&As[r][lane * 4] = *(const float4*)p;
        }
        const int r2 = tid >> 1, half = tid & 1;
        const float* ep = ev + (size_t)(i * Sdim + r2) * HDim + half * 16;
#pragma unroll
        for (int c = 0; c < 4; c++)
            *(float4*)&Evs[r2][half * 16 + c * 4] = *(const float4*)(ep + c * 4);
    }
    __syncthreads();
    const int tg = tid >> 3;
    const int dg = tid & 7;
    float o[4][4];
#pragma unroll
    for (int c = 0; c < 4; c++)
#pragma unroll
        for (int e = 0; e < 4; e++) o[c][e] = 0.f;
    for (int j = 0; j < Sdim; j++) {
        float4 bv = *(const float4*)&Evs[j][dg * 4];
#pragma unroll
        for (int c = 0; c < 4; c++) {
            float a = As[tg * 4 + c][j];
            o[c][0] += a * bv.x; o[c][1] += a * bv.y;
            o[c][2] += a * bv.z; o[c][3] += a * bv.w;
        }
    }
#pragma unroll
    for (int c = 0; c < 4; c++) {
        const int bh = bh0 + tg * 4 + c;
        const int b = bh >> 3, h = bh & 7;
        const size_t idx = (size_t)(b * Sdim + i) * Ddim + h * HDim + dg * 4;
        float4 cur = *(const float4*)(ctx + idx);
        cur.x += o[c][0]; cur.y += o[c][1]; cur.z += o[c][2]; cur.w += o[c][3];
        __half hh[4], ll[4];
        split16(cur.x, hh[0], ll[0]); split16(cur.y, hh[1], ll[1]);
        split16(cur.z, hh[2], ll[2]); split16(cur.w, hh[3], ll[3]);
        *(__half2*)(ch + idx)     = __halves2half2(hh[0], hh[1]);
        *(__half2*)(ch + idx + 2) = __halves2half2(hh[2], hh[3]);
        *(__half2*)(cl + idx)     = __halves2half2(ll[0], ll[1]);
        *(__half2*)(cl + idx + 2) = __halves2half2(ll[2], ll[3]);
    }
}

// ---------------- layer norm (+ hi/lo split out) ---------------------------
__global__ __launch_bounds__(256) void ln_kernel(
    const float* __restrict__ in1, const float* __restrict__ in2, float alpha,
    const float* __restrict__ g, const float* __restrict__ b,
    float* __restrict__ out, __half* __restrict__ outh, __half* __restrict__ outl)
{
    const int warp = threadIdx.x >> 5, lane = threadIdx.x & 31;
    const int row = blockIdx.x * 8 + warp;
    const float* p1 = in1 + (size_t)row * Ddim;
    float v[8];
#pragma unroll
    for (int c = 0; c < 8; c++) {
        int col = lane + 32 * c;
        float t = alpha * p1[col];
        if (in2) t += in2[(size_t)row * Ddim + col];
        v[c] = t;
    }
    float s = 0.f;
#pragma unroll
    for (int c = 0; c < 8; c++) s += v[c];
#pragma unroll
    for (int o = 16; o > 0; o >>= 1) s += __shfl_xor_sync(0xffffffffu, s, o);
    float mu = s * (1.f / Ddim);
    float var = 0.f;
#pragma unroll
    for (int c = 0; c < 8; c++) { float d = v[c] - mu; var += d * d; }
#pragma unroll
    for (int o = 16; o > 0; o >>= 1) var += __shfl_xor_sync(0xffffffffu, var, o);
    var *= (1.f / Ddim);
    float inv = rsqrtf(var + 1e-5f);
#pragma unroll
    for (int c = 0; c < 8; c++) {
        int col = lane + 32 * c;
        float r = (v[c] - mu) * inv * g[col] + b[col];
        out[(size_t)row * Ddim + col] = r;
        __half h, l;
        split16(r, h, l);
        outh[(size_t)row * Ddim + col] = h;
        outl[(size_t)row * Ddim + col] = l;
    }
}

__global__ void out_transpose(const float* __restrict__ x, float* __restrict__ out)
{
    size_t idx = (size_t)blockIdx.x * 256 + threadIdx.x;
    int d = (int)(idx % Ddim);
    size_t sb = idx / Ddim;
    int bcol = (int)(sb % Bdim);
    int s = (int)(sb / Bdim);
    out[idx] = x[((size_t)bcol * Sdim + s) * Ddim + d];
}

// ---------------- host -----------------------------------------------------
extern "C" void kernel_launch(void* const* d_in, const int* in_sizes, int n_in,
                              void* d_out, int out_size)
{
    const float* facts = (const float*)d_in[0];
    const float* ekey  = (const float*)d_in[1];
    const float* evalp = (const float*)d_in[2];
    const unsigned char* mask = (const unsigned char*)d_in[3];
    const float *Wq, *Wk, *Wv, *Wo, *bq, *bk, *bv, *bo;
    if (in_sizes[5] == Ldim * Ddim) {
        Wq = (const float*)d_in[4];  bq = (const float*)d_in[5];
        Wk = (const float*)d_in[6];  bk = (const float*)d_in[7];
        Wv = (const float*)d_in[8];  bv = (const float*)d_in[9];
        Wo = (const float*)d_in[10]; bo = (const float*)d_in[11];
    } else {
        Wq = (const float*)d_in[4];  Wk = (const float*)d_in[5];
        Wv = (const float*)d_in[6];  Wo = (const float*)d_in[7];
        bq = (const float*)d_in[8];  bk = (const float*)d_in[9];
        bv = (const float*)d_in[10]; bo = (const float*)d_in[11];
    }
    const float* ln1g = (const float*)d_in[12];
    const float* ln1b = (const float*)d_in[13];
    const float* W1   = (const float*)d_in[14];
    const float* b1   = (const float*)d_in[15];
    const float* W2   = (const float*)d_in[16];
    const float* b2   = (const float*)d_in[17];
    const float* ln2g = (const float*)d_in[18];
    const float* ln2b = (const float*)d_in[19];

    float *x, *qkv, *ctx, *tmp, *eb, *at, *bqkvp;
    __half *xh, *xl, *ch, *cl, *ffh, *ffl;
    __half *wqkvT, *woT, *w1T, *w2T;
    cudaGetSymbolAddress((void**)&x,    g_x);
    cudaGetSymbolAddress((void**)&qkv,  g_qkv);
    cudaGetSymbolAddress((void**)&ctx,  g_ctx);
    cudaGetSymbolAddress((void**)&tmp,  g_tmp);
    cudaGetSymbolAddress((void**)&eb,   g_eb);
    cudaGetSymbolAddress((void**)&at,   g_at);
    cudaGetSymbolAddress((void**)&xh,   g_xh);
    cudaGetSymbolAddress((void**)&xl,   g_xl);
    cudaGetSymbolAddress((void**)&ch,   g_ch);
    cudaGetSymbolAddress((void**)&cl,   g_cl);
    cudaGetSymbolAddress((void**)&ffh,  g_ffh);
    cudaGetSymbolAddress((void**)&ffl,  g_ffl);
    cudaGetSymbolAddress((void**)&wqkvT, g_wqkvT);
    cudaGetSymbolAddress((void**)&woT,  g_woT);
    cudaGetSymbolAddress((void**)&w1T,  g_w1T);
    cudaGetSymbolAddress((void**)&w2T,  g_w2T);
    cudaGetSymbolAddress((void**)&bqkvp, g_bqkv);

    cudaFuncSetAttribute(mma_gemm<false,false>, cudaFuncAttributeMaxDynamicSharedMemorySize, GSMB);
    cudaFuncSetAttribute(mma_gemm<true,true>,   cudaFuncAttributeMaxDynamicSharedMemorySize, GSMB);
    cudaFuncSetAttribute(attn_kernel, cudaFuncAttributeMaxDynamicSharedMemorySize, ATT_BYTES);
    cudaFuncSetAttribute(ev_kernel,   cudaFuncAttributeMaxDynamicSharedMemorySize, EV_BYTES);

    // launch order: 0 tr_all, 1 prep, 2 pack_bias, 3 QKV gemm (<- ncu target)
    tr_all<<<5120, 256>>>(Wq, Wk, Wv, Wo, W1, W2, wqkvT, woT, w1T, w2T);        // 0
    prep_kernel<<<NR * Ddim / 256, 256>>>(facts, x, xh, xl);                    // 1
    pack_bias<<<(Ldim * QKVS + 255) / 256, 256>>>(bq, bk, bv, bqkvp);           // 2

    for (int l = 0; l < Ldim; l++) {
        mma_gemm<false,false><<<dim3(QKVS / 128, NR / 128), 256, GSMB>>>(
            xh, xl, wqkvT + (size_t)l * 3 * Ddim * Ddim, bqkvp + l * QKVS,
            qkv, nullptr, nullptr, NR, QKVS, Ddim);                             // 3 (l=0)

        ebias_kernel<<<dim3(Sdim, BHdim / 128), 256>>>(qkv, ekey, eb);
        attn_kernel<<<BHdim, 256, ATT_BYTES>>>(qkv, eb, mask, at, ctx);
        ev_kernel<<<dim3(Sdim, BHdim / 128), 256, EV_BYTES>>>(at, evalp, ctx, ch, cl);

        mma_gemm<false,false><<<dim3(Ddim / 128, NR / 128), 256, GSMB>>>(
            ch, cl, woT + (size_t)l * Ddim * Ddim, bo + l * Ddim,
            tmp, nullptr, nullptr, NR, Ddim, Ddim);
        ln_kernel<<<NR / 8, 256>>>(tmp, x, 1.f, ln1g + l * Ddim, ln1b + l * Ddim,
                                   x, xh, xl);

        mma_gemm<true,true><<<dim3(Fdim / 128, NR / 128), 256, GSMB>>>(
            xh, xl, w1T + (size_t)l * Fdim * Ddim, b1 + l * Fdim,
            nullptr, ffh, ffl, NR, Fdim, Ddim);
        mma_gemm<false,false><<<dim3(Ddim / 128, NR / 128), 256, GSMB>>>(
            ffh, ffl, w2T + (size_t)l * Ddim * Fdim, b2 + l * Ddim,
            tmp, nullptr, nullptr, NR, Ddim, Fdim);
        ln_kernel<<<NR / 8, 256>>>(tmp, nullptr, 2.f, ln2g + l * Ddim, ln2b + l * Ddim,
                                   x, xh, xl);
    }

    out_transpose<<<NR * Ddim / 256, 256>>>(x, (float*)d_out);
}

// round 13
// speedup vs baseline: 1.0557x; 1.0557x over previous
#include <cuda_runtime.h>
#include <cuda_fp16.h>
#include <cstdint>
#include <math.h>

#define Bdim 128
#define Sdim 128
#define Ddim 256
#define Hdim 8
#define HDim 32
#define Fdim 2048
#define Ldim 4
#define BHdim (Bdim*Hdim)     /* 1024 */
#define NR (Bdim*Sdim)        /* 16384 rows */
#define QKVS 768              /* fused qkv row stride */
#define EKN (Sdim*Sdim*HDim)  /* 524288 */

// ---------------- scratch (device globals; no allocation allowed) ----------
__device__ float g_x[NR*Ddim];
__device__ float g_qkv[(size_t)NR*QKVS];
__device__ float g_ctx[NR*Ddim];
__device__ float g_tmp[NR*Ddim];
__device__ float g_eb[(size_t)BHdim*Sdim*Sdim];   // [bh][j][i]
__device__ float g_at[(size_t)BHdim*Sdim*Sdim];   // [bh][i][j]
// fp16 hi/lo activation pairs
__device__ __half g_xh[NR*Ddim];
__device__ __half g_xl[NR*Ddim];
__device__ __half g_ch[NR*Ddim];
__device__ __half g_cl[NR*Ddim];
__device__ __half g_ffh[(size_t)NR*Fdim];
__device__ __half g_ffl[(size_t)NR*Fdim];
__device__ __half g_qh[NR*Ddim];       // q section of qkv, hi/lo
__device__ __half g_ql[NR*Ddim];
__device__ __half g_ekh[EKN];
__device__ __half g_ekl[EKN];
// transposed fp16 weights [N][K]
__device__ __half g_wqkvT[(size_t)Ldim*3*Ddim*Ddim];
__device__ __half g_woT[(size_t)Ldim*Ddim*Ddim];
__device__ __half g_w1T[(size_t)Ldim*Fdim*Ddim];
__device__ __half g_w2T[(size_t)Ldim*Ddim*Fdim];
__device__ float g_bqkv[Ldim*QKVS];

// ==================== helpers =============================================
__device__ __forceinline__ uint32_t smem_u32(const void* p) {
    uint32_t a;
    asm("{ .reg .u64 t; cvta.to.shared.u64 t, %1; cvt.u32.u64 %0, t; }"
        : "=r"(a) : "l"(p));
    return a;
}
#define LDSM_X4(R0,R1,R2,R3,ADDR) \
    asm volatile("ldmatrix.sync.aligned.m8n8.x4.shared.b16 {%0,%1,%2,%3}, [%4];" \
        : "=r"(R0), "=r"(R1), "=r"(R2), "=r"(R3) : "r"(ADDR) : "memory")
#define CP16(dst, src) \
    asm volatile("cp.async.cg.shared.global [%0], [%1], 16;" :: "r"(dst), "l"(src))
#define CPCOMMIT() asm volatile("cp.async.commit_group;" ::: "memory")
#define CPWAIT1()  asm volatile("cp.async.wait_group 1;" ::: "memory")
#define CPWAIT0()  asm volatile("cp.async.wait_group 0;" ::: "memory")
#define CPWAITALL() asm volatile("cp.async.wait_all;" ::: "memory")

__device__ __forceinline__ void mma_f16(
    float& c0, float& c1, float& c2, float& c3,
    uint32_t a0, uint32_t a1, uint32_t a2, uint32_t a3,
    uint32_t b0, uint32_t b1)
{
    asm volatile(
        "mma.sync.aligned.m16n8k16.row.col.f32.f16.f16.f32 "
        "{%0,%1,%2,%3}, {%4,%5,%6,%7}, {%8,%9}, {%0,%1,%2,%3};"
        : "+f"(c0), "+f"(c1), "+f"(c2), "+f"(c3)
        : "r"(a0), "r"(a1), "r"(a2), "r"(a3), "r"(b0), "r"(b1));
}

__device__ __forceinline__ void split16(float v, __half& h, __half& l) {
    h = __float2half_rn(v);
    l = __float2half_rn(v - __half2float(h));
}

// ==================== fp16 split-A mma GEMM (cp.async, 3-stage) ============
// C[M,N] = (Ah+Al)[M,K] @ BT[N,K]^T + bias. Optional relu + fp16 hi/lo out.
// 256 threads, CTA tile 128x128, 8 warps (4m x 2n), warp tile 32x64.
// If Qh/Ql non-null: also store hi/lo split of C for cols < 256 (q section).
#define CH 32
#define SKH 40                          /* smem halves per row (32 + 8 pad) */
#define TILEB (128 * SKH * 2)           /* 10240 B per tile */
#define CHUNKB (3 * TILEB)              /* AH + AL + B per stage */
#define NSTG 3
#define GSMB (NSTG * CHUNKB)            /* 92160 B */

template<bool RELU, bool OUTH>
__global__ __launch_bounds__(256, 2) void mma_gemm(
    const __half* __restrict__ Ah, const __half* __restrict__ Al,
    const __half* __restrict__ BT, const float* __restrict__ bias,
    float* __restrict__ C, __half* __restrict__ Ch, __half* __restrict__ Cl,
    __half* __restrict__ Qh, __half* __restrict__ Ql,
    int M, int N, int K)
{
    extern __shared__ __half sh[];
    const uint32_t s0 = smem_u32(sh);
    const int tid = threadIdx.x;
    const int lane = tid & 31, wid = tid >> 5;
    const int wm = (wid >> 1) * 32, wn = (wid & 1) * 64;
    const int m0 = blockIdx.y * 128, n0 = blockIdx.x * 128;
    const int nch = K / CH;
    const int srow = tid >> 1, shalf = tid & 1;
    const int rev = wid & 1;

    const __half* Abase = Ah + (size_t)(m0 + srow) * K + shalf * 16;
    const __half* Lbase = Al + (size_t)(m0 + srow) * K + shalf * 16;
    const __half* Bbase = BT + (size_t)(n0 + srow) * K + shalf * 16;
    const uint32_t sdst = (uint32_t)((srow * SKH + shalf * 16) * 2);

    const uint32_t a_loff = (uint32_t)(((lane & 15) * SKH + ((lane >> 4) << 3)) * 2);
    const uint32_t b_loff = (uint32_t)((((lane & 7) + ((lane >> 4) << 3)) * SKH
                                        + (((lane >> 3) & 1) << 3)) * 2);

    auto issue = [&](int c) {
        const uint32_t base = s0 + (uint32_t)((c % NSTG) * CHUNKB) + sdst;
        const __half* ap = Abase + c * CH;
        const __half* lp = Lbase + c * CH;
        const __half* bp = Bbase + c * CH;
        CP16(base,              ap);     CP16(base + 16,              ap + 8);
        CP16(base + TILEB,      lp);     CP16(base + TILEB + 16,      lp + 8);
        CP16(base + 2 * TILEB,  bp);     CP16(base + 2 * TILEB + 16,  bp + 8);
        CPCOMMIT();
    };

    float acc[2][8][4];
#pragma unroll
    for (int mt = 0; mt < 2; ++mt)
#pragma unroll
        for (int nt = 0; nt < 8; ++nt)
#pragma unroll
            for (int e = 0; e < 4; ++e) acc[mt][nt][e] = 0.f;

    issue(0);
    if (nch > 1) issue(1);

    for (int c = 0; c < nch; ++c) {
        if (c + 1 < nch) { CPWAIT1(); } else { CPWAIT0(); }
        __syncthreads();
        if (c + 2 < nch) issue(c + 2);

        const uint32_t stg = s0 + (uint32_t)((c % NSTG) * CHUNKB);
        const uint32_t ahb = stg + (uint32_t)(wm * SKH * 2) + a_loff;
        const uint32_t alb = ahb + TILEB;
        const uint32_t bhb = stg + 2 * TILEB + (uint32_t)(wn * SKH * 2) + b_loff;
#pragma unroll
        for (int s0i = 0; s0i < 2; ++s0i) {
            const int s = rev ? (1 - s0i) : s0i;
            const uint32_t kb2 = s * 32;
            uint32_t bfr[8][2];
#pragma unroll
            for (int p = 0; p < 4; ++p) {
                uint32_t r0, r1, r2, r3;
                LDSM_X4(r0, r1, r2, r3,
                        bhb + (uint32_t)(p * 16 * SKH * 2) + kb2);
                bfr[p*2][0] = r0; bfr[p*2][1] = r1;
                bfr[p*2+1][0] = r2; bfr[p*2+1][1] = r3;
            }
            uint32_t ah[2][4], al[2][4];
#pragma unroll
            for (int mt = 0; mt < 2; ++mt) {
                LDSM_X4(ah[mt][0], ah[mt][1], ah[mt][2], ah[mt][3],
                        ahb + (uint32_t)(mt * 16 * SKH * 2) + kb2);
                LDSM_X4(al[mt][0], al[mt][1], al[mt][2], al[mt][3],
                        alb + (uint32_t)(mt * 16 * SKH * 2) + kb2);
            }
#pragma unroll
            for (int nt = 0; nt < 8; ++nt)
#pragma unroll
                for (int mt = 0; mt < 2; ++mt)
                    mma_f16(acc[mt][nt][0], acc[mt][nt][1],
                            acc[mt][nt][2], acc[mt][nt][3],
                            ah[mt][0], ah[mt][1], ah[mt][2], ah[mt][3],
                            bfr[nt][0], bfr[nt][1]);
#pragma unroll
            for (int nt = 0; nt < 8; ++nt)
#pragma unroll
                for (int mt = 0; mt < 2; ++mt)
                    mma_f16(acc[mt][nt][0], acc[mt][nt][1],
                            acc[mt][nt][2], acc[mt][nt][3],
                            al[mt][0], al[mt][1], al[mt][2], al[mt][3],
                            bfr[nt][0], bfr[nt][1]);
        }
    }

    const int qr = lane >> 2, qc = lane & 3;
#pragma unroll
    for (int mt = 0; mt < 2; ++mt) {
        const int r = m0 + wm + mt * 16 + qr;
#pragma unroll
        for (int nt = 0; nt < 8; ++nt) {
            const int col = n0 + wn + nt * 8 + qc * 2;
            float b0 = bias[col], b1 = bias[col + 1];
            float v00 = acc[mt][nt][0] + b0, v01 = acc[mt][nt][1] + b1;
            float v10 = acc[mt][nt][2] + b0, v11 = acc[mt][nt][3] + b1;
            if (RELU) {
                v00 = fmaxf(v00, 0.f); v01 = fmaxf(v01, 0.f);
                v10 = fmaxf(v10, 0.f); v11 = fmaxf(v11, 0.f);
            }
            if (OUTH) {
                __half h00, l00, h01, l01, h10, l10, h11, l11;
                split16(v00, h00, l00); split16(v01, h01, l01);
                split16(v10, h10, l10); split16(v11, h11, l11);
                *(__half2*)(Ch + (size_t)r * N + col)       = __halves2half2(h00, h01);
                *(__half2*)(Cl + (size_t)r * N + col)       = __halves2half2(l00, l01);
                *(__half2*)(Ch + (size_t)(r + 8) * N + col) = __halves2half2(h10, h11);
                *(__half2*)(Cl + (size_t)(r + 8) * N + col) = __halves2half2(l10, l11);
            } else {
                *(float2*)(C + (size_t)r * N + col)       = make_float2(v00, v01);
                *(float2*)(C + (size_t)(r + 8) * N + col) = make_float2(v10, v11);
                if (Qh && col < 256) {    // q section hi/lo for ebias_mma
                    __half h00, l00, h01, l01, h10, l10, h11, l11;
                    split16(v00, h00, l00); split16(v01, h01, l01);
                    split16(v10, h10, l10); split16(v11, h11, l11);
                    *(__half2*)(Qh + (size_t)r * 256 + col)       = __halves2half2(h00, h01);
                    *(__half2*)(Ql + (size_t)r * 256 + col)       = __halves2half2(l00, l01);
                    *(__half2*)(Qh + (size_t)(r + 8) * 256 + col) = __halves2half2(h10, h11);
                    *(__half2*)(Ql + (size_t)(r + 8) * 256 + col) = __halves2half2(l10, l11);
                }
            }
        }
    }
}

// ==================== ebias via fp16 3-pass mma ============================
// eb[bh][j][i] = sum_d ek[j,i,d] * q[bh-row (b,j), d]; per block: fixed j,
// 128 bh-rows x 128 i-cols x K=32. Both operands split; passes hh+lh+hl.
#define EBT 5120   /* halves per 128x40 tile */
__global__ __launch_bounds__(256) void ebias_mma(
    const __half* __restrict__ qh, const __half* __restrict__ ql,
    const __half* __restrict__ ekh, const __half* __restrict__ ekl,
    float* __restrict__ eb)
{
    __shared__ __half sm[4 * EBT];     // Ah Al Bh Bl
    const uint32_t s0 = smem_u32(sm);
    const int j = blockIdx.x;
    const int bh0 = blockIdx.y * 128;
    const int tid = threadIdx.x;
    const int lane = tid & 31, wid = tid >> 5;
    const int wm = (wid >> 1) * 32, wn = (wid & 1) * 64;

    {   // copy: 64 threads per tensor, rows u and u+64, 4 segs of 8 halves
        const int t = tid >> 6, u = tid & 63;
#pragma unroll
        for (int rr = 0; rr < 2; ++rr) {
            const int r = u + rr * 64;
            const __half* srcb;
            size_t soff;
            if (t < 2) {
                const int bh = bh0 + r;
                const int b = bh >> 3, h = bh & 7;
                soff = (size_t)(b * Sdim + j) * 256 + h * HDim;
                srcb = (t == 0 ? qh : ql);
            } else {
                soff = ((size_t)j * Sdim + r) * HDim;
                srcb = (t == 2 ? ekh : ekl);
            }
            const uint32_t dst = s0 + (uint32_t)((t * EBT + r * SKH) * 2);
#pragma unroll
            for (int sg = 0; sg < 4; ++sg)
                CP16(dst + sg * 16, srcb + soff + sg * 8);
        }
    }
    CPWAITALL();
    __syncthreads();

    const uint32_t a_loff = (uint32_t)(((lane & 15) * SKH + ((lane >> 4) << 3)) * 2);
    const uint32_t b_loff = (uint32_t)((((lane & 7) + ((lane >> 4) << 3)) * SKH
                                        + (((lane >> 3) & 1) << 3)) * 2);
    const uint32_t Ahb = s0 + (uint32_t)(wm * SKH * 2) + a_loff;
    const uint32_t Alb = Ahb + EBT * 2;
    const uint32_t Bhb = s0 + (uint32_t)(2 * EBT * 2) + (uint32_t)(wn * SKH * 2) + b_loff;
    const uint32_t Blb = Bhb + EBT * 2;

    float acc[2][8][4];
#pragma unroll
    for (int mt = 0; mt < 2; ++mt)
#pragma unroll
        for (int nt = 0; nt < 8; ++nt)
#pragma unroll
            for (int e = 0; e < 4; ++e) acc[mt][nt][e] = 0.f;

#pragma unroll
    for (int ss = 0; ss < 2; ++ss) {
        const uint32_t kb2 = ss * 32;
        uint32_t bhf[8][2], blf[8][2];
#pragma unroll
        for (int p = 0; p < 4; ++p) {
            uint32_t r0, r1, r2, r3;
            LDSM_X4(r0, r1, r2, r3, Bhb + (uint32_t)(p * 16 * SKH * 2) + kb2);
            bhf[p*2][0] = r0; bhf[p*2][1] = r1;
            bhf[p*2+1][0] = r2; bhf[p*2+1][1] = r3;
            LDSM_X4(r0, r1, r2, r3, Blb + (uint32_t)(p * 16 * SKH * 2) + kb2);
            blf[p*2][0] = r0; blf[p*2][1] = r1;
            blf[p*2+1][0] = r2; blf[p*2+1][1] = r3;
        }
        uint32_t ah[2][4], al[2][4];
#pragma unroll
        for (int mt = 0; mt < 2; ++mt) {
            LDSM_X4(ah[mt][0], ah[mt][1], ah[mt][2], ah[mt][3],
                    Ahb + (uint32_t)(mt * 16 * SKH * 2) + kb2);
            LDSM_X4(al[mt][0], al[mt][1], al[mt][2], al[mt][3],
                    Alb + (uint32_t)(mt * 16 * SKH * 2) + kb2);
        }
#pragma unroll
        for (int nt = 0; nt < 8; ++nt)
#pragma unroll
            for (int mt = 0; mt < 2; ++mt) {
                mma_f16(acc[mt][nt][0], acc[mt][nt][1], acc[mt][nt][2], acc[mt][nt][3],
                        ah[mt][0], ah[mt][1], ah[mt][2], ah[mt][3],
                        bhf[nt][0], bhf[nt][1]);
                mma_f16(acc[mt][nt][0], acc[mt][nt][1], acc[mt][nt][2], acc[mt][nt][3],
                        al[mt][0], al[mt][1], al[mt][2], al[mt][3],
                        bhf[nt][0], bhf[nt][1]);
                mma_f16(acc[mt][nt][0], acc[mt][nt][1], acc[mt][nt][2], acc[mt][nt][3],
                        ah[mt][0], ah[mt][1], ah[mt][2], ah[mt][3],
                        blf[nt][0], blf[nt][1]);
            }
    }

    const int qr = lane >> 2, qc = lane & 3;
#pragma unroll
    for (int mt = 0; mt < 2; ++mt) {
        const int row = wm + mt * 16 + qr;
#pragma unroll
        for (int nt = 0; nt < 8; ++nt) {
            const int col = wn + nt * 8 + qc * 2;
            float* p0 = eb + ((size_t)(bh0 + row) * Sdim + j) * Sdim + col;
            float* p1 = eb + ((size_t)(bh0 + row + 8) * Sdim + j) * Sdim + col;
            *(float2*)p0 = make_float2(acc[mt][nt][0], acc[mt][nt][1]);
            *(float2*)p1 = make_float2(acc[mt][nt][2], acc[mt][nt][3]);
        }
    }
}

// ============ fused weight transpose -> fp16 [N][K] (single launch) ========
__global__ __launch_bounds__(256) void tr_all(
    const float* __restrict__ Wq, const float* __restrict__ Wk,
    const float* __restrict__ Wv, const float* __restrict__ Wo,
    const float* __restrict__ W1, const float* __restrict__ W2,
    __half* __restrict__ wqkvT, __half* __restrict__ woT,
    __half* __restrict__ w1T, __half* __restrict__ w2T)
{
    __shared__ float t[32][33];
    const int tb = blockIdx.x;
    const float* src; __half* dst; int K, N, kx, nx;
    if (tb < 768) {
        int w = tb / 256, r = tb % 256, l = r / 64, q = r % 64;
        src = (w == 0 ? Wq : (w == 1 ? Wk : Wv)) + (size_t)l * 65536;
        dst = wqkvT + (size_t)l * 196608 + (size_t)w * 65536;
        K = 256; N = 256; kx = (q / 8) * 32; nx = (q % 8) * 32;
    } else if (tb < 1024) {
        int r = tb - 768, l = r / 64, q = r % 64;
        src = Wo + (size_t)l * 65536; dst = woT + (size_t)l * 65536;
        K = 256; N = 256; kx = (q / 8) * 32; nx = (q % 8) * 32;
    } else if (tb < 3072) {
        int r = tb - 1024, l = r / 512, q = r % 512;
        src = W1 + (size_t)l * 524288; dst = w1T + (size_t)l * 524288;
        K = 256; N = 2048; kx = (q / 64) * 32; nx = (q % 64) * 32;
    } else {
        int r = tb - 3072, l = r / 512, q = r % 512;
        src = W2 + (size_t)l * 524288; dst = w2T + (size_t)l * 524288;
        K = 2048; N = 256; kx = (q / 8) * 32; nx = (q % 8) * 32;
    }
    const int x = threadIdx.x & 31, y = threadIdx.x >> 5;
#pragma unroll
    for (int yy = y; yy < 32; yy += 8)
        t[yy][x] = src[(size_t)(kx + yy) * N + nx + x];
    __syncthreads();
#pragma unroll
    for (int yy = y; yy < 32; yy += 8)
        dst[(size_t)(nx + yy) * K + kx + x] = __float2half_rn(t[x][yy]);
}

// ---- prep: x + split, ek split, bias pack (one launch) --------------------
__global__ void prep_kernel(const float* __restrict__ facts, float* __restrict__ x,
                            __half* __restrict__ xh, __half* __restrict__ xl,
                            const float* __restrict__ ekey,
                            __half* __restrict__ ekh, __half* __restrict__ ekl,
                            const float* __restrict__ bq, const float* __restrict__ bk,
                            const float* __restrict__ bv, float* __restrict__ bqkv)
{
    size_t idx = (size_t)blockIdx.x * 256 + threadIdx.x;
    float v = facts[idx];
    x[idx] = v;
    __half h, l;
    split16(v, h, l);
    xh[idx] = h; xl[idx] = l;
    if (idx < EKN) {
        float e = ekey[idx];
        __half eh, el;
        split16(e, eh, el);
        ekh[idx] = eh; ekl[idx] = el;
    }
    if (idx < Ldim * QKVS) {
        int li = (int)(idx / QKVS), ji = (int)(idx % QKVS);
        float bvv;
        if (ji < 256)      bvv = bq[li * 256 + ji];
        else if (ji < 512) bvv = bk[li * 256 + ji - 256];
        else               bvv = bv[li * 256 + ji - 512];
        bqkv[idx] = bvv;
    }
}

// -------- attention per (b,h) ---------------------------------------------
#define ATT_FLOATS (2*32*132 + 128*32 + 128*129)
#define ATT_BYTES  (ATT_FLOATS * 4)
__global__ __launch_bounds__(256) void attn_kernel(
    const float* __restrict__ qkv, const float* __restrict__ eb,
    const unsigned char* __restrict__ mask,
    float* __restrict__ attn_out, float* __restrict__ ctx)
{
    extern __shared__ float sm[];
    float (*Qs)[132] = (float(*)[132])sm;
    float (*Ks)[132] = (float(*)[132])(sm + 32 * 132);
    float (*Vs)[32]  = (float(*)[32]) (sm + 2 * 32 * 132);
    float (*Sc)[129] = (float(*)[129])(sm + 2 * 32 * 132 + 128 * 32);
    const int bh = blockIdx.x;
    const int b = bh >> 3, h = bh & 7;
    const int tid = threadIdx.x;

    {
        const int r = tid >> 1;
        const int half = tid & 1;
        const float* base = qkv + (size_t)(b * Sdim + r) * QKVS + h * HDim + half * 16;
        const float* qp = base;
        const float* kp = base + 256;
        const float* vp = base + 512;
#pragma unroll
        for (int c = 0; c < 4; c++) {
            int d = half * 16 + c * 4;
            float4 vq = *(const float4*)(qp + c * 4);
            float4 vk = *(const float4*)(kp + c * 4);
            Qs[d+0][r] = vq.x; Qs[d+1][r] = vq.y; Qs[d+2][r] = vq.z; Qs[d+3][r] = vq.w;
            Ks[d+0][r] = vk.x; Ks[d+1][r] = vk.y; Ks[d+2][r] = vk.z; Ks[d+3][r] = vk.w;
            *(float4*)&Vs[r][d] = *(const float4*)(vp + c * 4);
        }
        const int warp = tid >> 5, lane = tid & 31;
        for (int jj = warp; jj < Sdim; jj += 8) {
            float4 t = *(const float4*)(eb + ((size_t)bh * Sdim + jj) * Sdim + lane * 4);
            Sc[lane*4+0][jj] = t.x; Sc[lane*4+1][jj] = t.y;
            Sc[lane*4+2][jj] = t.z; Sc[lane*4+3][jj] = t.w;
        }
    }
    __syncthreads();

    const int ty = tid >> 4, tx = tid & 15;
    const int i0 = ty * 8, j0 = tx * 8;
    float acc[8][8];
#pragma unroll
    for (int i = 0; i < 8; i++)
#pragma unroll
        for (int j = 0; j < 8; j++) acc[i][j] = 0.f;
#pragma unroll
    for (int d = 0; d < 32; d++) {
        float af[8], bf[8];
        *(float4*)&af[0] = *(const float4*)&Qs[d][i0];
        *(float4*)&af[4] = *(const float4*)&Qs[d][i0 + 4];
        *(float4*)&bf[0] = *(const float4*)&Ks[d][j0];
        *(float4*)&bf[4] = *(const float4*)&Ks[d][j0 + 4];
#pragma unroll
        for (int i = 0; i < 8; i++)
#pragma unroll
            for (int j = 0; j < 8; j++) acc[i][j] += af[i] * bf[j];
    }
    const float scale = 0.17677669529663687f;
    const float NEGINF = -__int_as_float(0x7f800000);
#pragma unroll
    for (int ii = 0; ii < 8; ii++) {
        unsigned long long mv =
            *(const unsigned long long*)(mask + ((size_t)bh * Sdim + i0 + ii) * Sdim + j0);
#pragma unroll
        for (int jj = 0; jj < 8; jj++) {
            float s = (acc[ii][jj] + Sc[i0 + ii][j0 + jj]) * scale;
            if ((mv >> (8 * jj)) & 0xffULL) s = NEGINF;
            Sc[i0 + ii][j0 + jj] = s;
        }
    }
    __syncthreads();

    {
        const int warp = tid >> 5, lane = tid & 31;
        for (int r = warp; r < Sdim; r += 8) {
            float vals[4];
#pragma unroll
            for (int c = 0; c < 4; c++) vals[c] = Sc[r][lane + 32 * c];
            float m = fmaxf(fmaxf(vals[0], vals[1]), fmaxf(vals[2], vals[3]));
#pragma unroll
            for (int o = 16; o > 0; o >>= 1) m = fmaxf(m, __shfl_xor_sync(0xffffffffu, m, o));
            float ssum = 0.f;
#pragma unroll
            for (int c = 0; c < 4; c++) { vals[c] = __expf(vals[c] - m); ssum += vals[c]; }
#pragma unroll
            for (int o = 16; o > 0; o >>= 1) ssum += __shfl_xor_sync(0xffffffffu, ssum, o);
            float inv = 1.f / ssum;
            float* ap = attn_out + ((size_t)bh * Sdim + r) * Sdim;
#pragma unroll
            for (int c = 0; c < 4; c++) {
                float p = vals[c] * inv;
                Sc[r][lane + 32 * c] = p;
                ap[lane + 32 * c] = p;
            }
        }
    }
    __syncthreads();

    const int ig = tid >> 3;
    const int dg = tid & 7;
    float o[4][4];
#pragma unroll
    for (int c = 0; c < 4; c++)
#pragma unroll
        for (int e = 0; e < 4; e++) o[c][e] = 0.f;
    for (int j = 0; j < Sdim; j++) {
        float4 vv = *(const float4*)&Vs[j][dg * 4];
#pragma unroll
        for (int c = 0; c < 4; c++) {
            float p = Sc[ig * 4 + c][j];
            o[c][0] += p * vv.x; o[c][1] += p * vv.y;
            o[c][2] += p * vv.z; o[c][3] += p * vv.w;
        }
    }
#pragma unroll
    for (int c = 0; c < 4; c++) {
        float* cp = ctx + (size_t)(b * Sdim + ig * 4 + c) * Ddim + h * HDim + dg * 4;
        *(float4*)cp = make_float4(o[c][0], o[c][1], o[c][2], o[c][3]);
    }
}

// -------- edge-value: ctx += attn @ ev, then hi/lo split out ---------------
#define EV_FLOATS (128*132 + 128*32)
#define EV_BYTES  (EV_FLOATS * 4)
__global__ __launch_bounds__(256) void ev_kernel(
    const float* __restrict__ attn, const float* __restrict__ ev,
    const float* __restrict__ ctx,
    __half* __restrict__ ch, __half* __restrict__ cl)
{
    const int i   = blockIdx.x;
    const int bh0 = blockIdx.y * 128;
    extern __shared__ float sm2[];
    float (*As)[132]  = (float(*)[132])sm2;
    float (*Evs)[32]  = (float(*)[32])(sm2 + 128 * 132);
    const int tid = threadIdx.x;
    {
        const int warp = tid >> 5, lane = tid & 31;
        for (int r = warp; r < 128; r += 8) {
            const float* p = attn + ((size_t)(bh0 + r) * Sdim + i) * Sdim + lane * 4;
            *(float4*)&As[r][lane * 4] = *(const float4*)p;
        }
        const int r2 = tid >> 1, half = tid & 1;
        const float* ep = ev + (size_t)(i * Sdim + r2) * HDim + half * 16;
#pragma unroll
        for (int c = 0; c < 4; c++)
            *(float4*)&Evs[r2][half * 16 + c * 4] = *(const float4*)(ep + c * 4);
    }
    __syncthreads();
    const int tg = tid >> 3;
    const int dg = tid & 7;
    float o[4][4];
#pragma unroll
    for (int c = 0; c < 4; c++)
#pragma unroll
        for (int e = 0; e < 4; e++) o[c][e] = 0.f;
    for (int j = 0; j < Sdim; j++) {
        float4 bv = *(const float4*)&Evs[j][dg * 4];
#pragma unroll
        for (int c = 0; c < 4; c++) {
            float a = As[tg * 4 + c][j];
            o[c][0] += a * bv.x; o[c][1] += a * bv.y;
            o[c][2] += a * bv.z; o[c][3] += a * bv.w;
        }
    }
#pragma unroll
    for (int c = 0; c < 4; c++) {
        const int bh = bh0 + tg * 4 + c;
        const int b = bh >> 3, h = bh & 7;
        const size_t idx = (size_t)(b * Sdim + i) * Ddim + h * HDim + dg * 4;
        float4 cur = *(const float4*)(ctx + idx);
        cur.x += o[c][0]; cur.y += o[c][1]; cur.z += o[c][2]; cur.w += o[c][3];
        __half hh[4], ll[4];
        split16(cur.x, hh[0], ll[0]); split16(cur.y, hh[1], ll[1]);
        split16(cur.z, hh[2], ll[2]); split16(cur.w, hh[3], ll[3]);
        *(__half2*)(ch + idx)     = __halves2half2(hh[0], hh[1]);
        *(__half2*)(ch + idx + 2) = __halves2half2(hh[2], hh[3]);
        *(__half2*)(cl + idx)     = __halves2half2(ll[0], ll[1]);
        *(__half2*)(cl + idx + 2) = __halves2half2(ll[2], ll[3]);
    }
}

// ---------------- layer norm (+ hi/lo split out) ---------------------------
__global__ __launch_bounds__(256) void ln_kernel(
    const float* __restrict__ in1, const float* __restrict__ in2, float alpha,
    const float* __restrict__ g, const float* __restrict__ b,
    float* __restrict__ out, __half* __restrict__ outh, __half* __restrict__ outl)
{
    const int warp = threadIdx.x >> 5, lane = threadIdx.x & 31;
    const int row = blockIdx.x * 8 + warp;
    const float* p1 = in1 + (size_t)row * Ddim;
    float v[8];
#pragma unroll
    for (int c = 0; c < 8; c++) {
        int col = lane + 32 * c;
        float t = alpha * p1[col];
        if (in2) t += in2[(size_t)row * Ddim + col];
        v[c] = t;
    }
    float s = 0.f;
#pragma unroll
    for (int c = 0; c < 8; c++) s += v[c];
#pragma unroll
    for (int o = 16; o > 0; o >>= 1) s += __shfl_xor_sync(0xffffffffu, s, o);
    float mu = s * (1.f / Ddim);
    float var = 0.f;
#pragma unroll
    for (int c = 0; c < 8; c++) { float d = v[c] - mu; var += d * d; }
#pragma unroll
    for (int o = 16; o > 0; o >>= 1) var += __shfl_xor_sync(0xffffffffu, var, o);
    var *= (1.f / Ddim);
    float inv = rsqrtf(var + 1e-5f);
#pragma unroll
    for (int c = 0; c < 8; c++) {
        int col = lane + 32 * c;
        float r = (v[c] - mu) * inv * g[col] + b[col];
        out[(size_t)row * Ddim + col] = r;
        __half h, l;
        split16(r, h, l);
        outh[(size_t)row * Ddim + col] = h;
        outl[(size_t)row * Ddim + col] = l;
    }
}

__global__ void out_transpose(const float* __restrict__ x, float* __restrict__ out)
{
    size_t idx = (size_t)blockIdx.x * 256 + threadIdx.x;
    int d = (int)(idx % Ddim);
    size_t sb = idx / Ddim;
    int bcol = (int)(sb % Bdim);
    int s = (int)(sb / Bdim);
    out[idx] = x[((size_t)bcol * Sdim + s) * Ddim + d];
}

// ---------------- host -----------------------------------------------------
extern "C" void kernel_launch(void* const* d_in, const int* in_sizes, int n_in,
                              void* d_out, int out_size)
{
    const float* facts = (const float*)d_in[0];
    const float* ekey  = (const float*)d_in[1];
    const float* evalp = (const float*)d_in[2];
    const unsigned char* mask = (const unsigned char*)d_in[3];
    const float *Wq, *Wk, *Wv, *Wo, *bq, *bk, *bv, *bo;
    if (in_sizes[5] == Ldim * Ddim) {
        Wq = (const float*)d_in[4];  bq = (const float*)d_in[5];
        Wk = (const float*)d_in[6];  bk = (const float*)d_in[7];
        Wv = (const float*)d_in[8];  bv = (const float*)d_in[9];
        Wo = (const float*)d_in[10]; bo = (const float*)d_in[11];
    } else {
        Wq = (const float*)d_in[4];  Wk = (const float*)d_in[5];
        Wv = (const float*)d_in[6];  Wo = (const float*)d_in[7];
        bq = (const float*)d_in[8];  bk = (const float*)d_in[9];
        bv = (const float*)d_in[10]; bo = (const float*)d_in[11];
    }
    const float* ln1g = (const float*)d_in[12];
    const float* ln1b = (const float*)d_in[13];
    const float* W1   = (const float*)d_in[14];
    const float* b1   = (const float*)d_in[15];
    const float* W2   = (const float*)d_in[16];
    const float* b2   = (const float*)d_in[17];
    const float* ln2g = (const float*)d_in[18];
    const float* ln2b = (const float*)d_in[19];

    float *x, *qkv, *ctx, *tmp, *eb, *at, *bqkvp;
    __half *xh, *xl, *ch, *cl, *ffh, *ffl, *qh, *ql, *ekh, *ekl;
    __half *wqkvT, *woT, *w1T, *w2T;
    cudaGetSymbolAddress((void**)&x,    g_x);
    cudaGetSymbolAddress((void**)&qkv,  g_qkv);
    cudaGetSymbolAddress((void**)&ctx,  g_ctx);
    cudaGetSymbolAddress((void**)&tmp,  g_tmp);
    cudaGetSymbolAddress((void**)&eb,   g_eb);
    cudaGetSymbolAddress((void**)&at,   g_at);
    cudaGetSymbolAddress((void**)&xh,   g_xh);
    cudaGetSymbolAddress((void**)&xl,   g_xl);
    cudaGetSymbolAddress((void**)&ch,   g_ch);
    cudaGetSymbolAddress((void**)&cl,   g_cl);
    cudaGetSymbolAddress((void**)&ffh,  g_ffh);
    cudaGetSymbolAddress((void**)&ffl,  g_ffl);
    cudaGetSymbolAddress((void**)&qh,   g_qh);
    cudaGetSymbolAddress((void**)&ql,   g_ql);
    cudaGetSymbolAddress((void**)&ekh,  g_ekh);
    cudaGetSymbolAddress((void**)&ekl,  g_ekl);
    cudaGetSymbolAddress((void**)&wqkvT, g_wqkvT);
    cudaGetSymbolAddress((void**)&woT,  g_woT);
    cudaGetSymbolAddress((void**)&w1T,  g_w1T);
    cudaGetSymbolAddress((void**)&w2T,  g_w2T);
    cudaGetSymbolAddress((void**)&bqkvp, g_bqkv);

    cudaFuncSetAttribute(mma_gemm<false,false>, cudaFuncAttributeMaxDynamicSharedMemorySize, GSMB);
    cudaFuncSetAttribute(mma_gemm<true,true>,   cudaFuncAttributeMaxDynamicSharedMemorySize, GSMB);
    cudaFuncSetAttribute(attn_kernel, cudaFuncAttributeMaxDynamicSharedMemorySize, ATT_BYTES);
    cudaFuncSetAttribute(ev_kernel,   cudaFuncAttributeMaxDynamicSharedMemorySize, EV_BYTES);

    // launches: 0 tr_all, 1 prep(+ek split+bias), 2 QKV, 3 ebias_mma (ncu)
    tr_all<<<5120, 256>>>(Wq, Wk, Wv, Wo, W1, W2, wqkvT, woT, w1T, w2T);        // 0
    prep_kernel<<<NR * Ddim / 256, 256>>>(facts, x, xh, xl,
                                          ekey, ekh, ekl, bq, bk, bv, bqkvp);   // 1

    for (int l = 0; l < Ldim; l++) {
        mma_gemm<false,false><<<dim3(QKVS / 128, NR / 128), 256, GSMB>>>(
            xh, xl, wqkvT + (size_t)l * 3 * Ddim * Ddim, bqkvp + l * QKVS,
            qkv, nullptr, nullptr, qh, ql, NR, QKVS, Ddim);                     // 2 (l=0)

        ebias_mma<<<dim3(Sdim, BHdim / 128), 256>>>(qh, ql, ekh, ekl, eb);      // 3 (l=0)
        attn_kernel<<<BHdim, 256, ATT_BYTES>>>(qkv, eb, mask, at, ctx);
        ev_kernel<<<dim3(Sdim, BHdim / 128), 256, EV_BYTES>>>(at, evalp, ctx, ch, cl);

        mma_gemm<false,false><<<dim3(Ddim / 128, NR / 128), 256, GSMB>>>(
            ch, cl, woT + (size_t)l * Ddim * Ddim, bo + l * Ddim,
            tmp, nullptr, nullptr, nullptr, nullptr, NR, Ddim, Ddim);
        ln_kernel<<<NR / 8, 256>>>(tmp, x, 1.f, ln1g + l * Ddim, ln1b + l * Ddim,
                                   x, xh, xl);

        mma_gemm<true,true><<<dim3(Fdim / 128, NR / 128), 256, GSMB>>>(
            xh, xl, w1T + (size_t)l * Fdim * Ddim, b1 + l * Fdim,
            nullptr, ffh, ffl, nullptr, nullptr, NR, Fdim, Ddim);
        mma_gemm<false,false><<<dim3(Ddim / 128, NR / 128), 256, GSMB>>>(
            ffh, ffl, w2T + (size_t)l * Ddim * Fdim, b2 + l * Ddim,
            tmp, nullptr, nullptr, nullptr, nullptr, NR, Ddim, Fdim);
        ln_kernel<<<NR / 8, 256>>>(tmp, nullptr, 2.f, ln2g + l * Ddim, ln2b + l * Ddim,
                                   x, xh, xl);
    }

    out_transpose<<<NR * Ddim / 256, 256>>>(x, (float*)d_out);
}

// round 14
// speedup vs baseline: 1.1411x; 1.0809x over previous
#include <cuda_runtime.h>
#include <cuda_fp16.h>
#include <cstdint>
#include <math.h>

#define Bdim 128
#define Sdim 128
#define Ddim 256
#define Hdim 8
#define HDim 32
#define Fdim 2048
#define Ldim 4
#define BHdim (Bdim*Hdim)     /* 1024 */
#define NR (Bdim*Sdim)        /* 16384 rows */
#define QKVS 768              /* fused qkv row stride */
#define EKN (Sdim*Sdim*HDim)  /* 524288 */

// ---------------- scratch (device globals; no allocation allowed) ----------
__device__ float g_x[NR*Ddim];
__device__ float g_qkv[(size_t)NR*QKVS];
__device__ float g_ctx[NR*Ddim];
__device__ float g_tmp[NR*Ddim];
__device__ float g_eb[(size_t)BHdim*Sdim*Sdim];   // [bh][j][i]
__device__ __half g_ath[(size_t)BHdim*Sdim*Sdim]; // P hi  [bh][i][j]
__device__ __half g_atl[(size_t)BHdim*Sdim*Sdim]; // P lo
// fp16 hi/lo activation pairs
__device__ __half g_xh[NR*Ddim];
__device__ __half g_xl[NR*Ddim];
__device__ __half g_ch[NR*Ddim];
__device__ __half g_cl[NR*Ddim];
__device__ __half g_ffh[(size_t)NR*Fdim];
__device__ __half g_ffl[(size_t)NR*Fdim];
__device__ __half g_qh[NR*Ddim];       // q section of qkv, hi/lo
__device__ __half g_ql[NR*Ddim];
__device__ __half g_ekh[EKN];
__device__ __half g_ekl[EKN];
// transposed fp16 weights [N][K]
__device__ __half g_wqkvT[(size_t)Ldim*3*Ddim*Ddim];
__device__ __half g_woT[(size_t)Ldim*Ddim*Ddim];
__device__ __half g_w1T[(size_t)Ldim*Fdim*Ddim];
__device__ __half g_w2T[(size_t)Ldim*Ddim*Fdim];
__device__ float g_bqkv[Ldim*QKVS];

// ==================== helpers =============================================
__device__ __forceinline__ uint32_t smem_u32(const void* p) {
    uint32_t a;
    asm("{ .reg .u64 t; cvta.to.shared.u64 t, %1; cvt.u32.u64 %0, t; }"
        : "=r"(a) : "l"(p));
    return a;
}
#define LDSM_X4(R0,R1,R2,R3,ADDR) \
    asm volatile("ldmatrix.sync.aligned.m8n8.x4.shared.b16 {%0,%1,%2,%3}, [%4];" \
        : "=r"(R0), "=r"(R1), "=r"(R2), "=r"(R3) : "r"(ADDR) : "memory")
#define CP16(dst, src) \
    asm volatile("cp.async.cg.shared.global [%0], [%1], 16;" :: "r"(dst), "l"(src))
#define CPCOMMIT() asm volatile("cp.async.commit_group;" ::: "memory")
#define CPWAIT1()  asm volatile("cp.async.wait_group 1;" ::: "memory")
#define CPWAIT0()  asm volatile("cp.async.wait_group 0;" ::: "memory")
#define CPWAITALL() asm volatile("cp.async.wait_all;" ::: "memory")

__device__ __forceinline__ void mma_f16(
    float& c0, float& c1, float& c2, float& c3,
    uint32_t a0, uint32_t a1, uint32_t a2, uint32_t a3,
    uint32_t b0, uint32_t b1)
{
    asm volatile(
        "mma.sync.aligned.m16n8k16.row.col.f32.f16.f16.f32 "
        "{%0,%1,%2,%3}, {%4,%5,%6,%7}, {%8,%9}, {%0,%1,%2,%3};"
        : "+f"(c0), "+f"(c1), "+f"(c2), "+f"(c3)
        : "r"(a0), "r"(a1), "r"(a2), "r"(a3), "r"(b0), "r"(b1));
}

__device__ __forceinline__ void split16(float v, __half& h, __half& l) {
    h = __float2half_rn(v);
    l = __float2half_rn(v - __half2float(h));
}

// ==================== fp16 split-A mma GEMM (cp.async, 3-stage) ============
#define CH 32
#define SKH 40                          /* smem halves per row (32 + 8 pad) */
#define TILEB (128 * SKH * 2)           /* 10240 B per tile */
#define CHUNKB (3 * TILEB)
#define NSTG 3
#define GSMB (NSTG * CHUNKB)            /* 92160 B */

template<bool RELU, bool OUTH>
__global__ __launch_bounds__(256, 2) void mma_gemm(
    const __half* __restrict__ Ah, const __half* __restrict__ Al,
    const __half* __restrict__ BT, const float* __restrict__ bias,
    float* __restrict__ C, __half* __restrict__ Ch, __half* __restrict__ Cl,
    __half* __restrict__ Qh, __half* __restrict__ Ql,
    int M, int N, int K)
{
    extern __shared__ __half sh[];
    const uint32_t s0 = smem_u32(sh);
    const int tid = threadIdx.x;
    const int lane = tid & 31, wid = tid >> 5;
    const int wm = (wid >> 1) * 32, wn = (wid & 1) * 64;
    const int m0 = blockIdx.y * 128, n0 = blockIdx.x * 128;
    const int nch = K / CH;
    const int srow = tid >> 1, shalf = tid & 1;
    const int rev = wid & 1;

    const __half* Abase = Ah + (size_t)(m0 + srow) * K + shalf * 16;
    const __half* Lbase = Al + (size_t)(m0 + srow) * K + shalf * 16;
    const __half* Bbase = BT + (size_t)(n0 + srow) * K + shalf * 16;
    const uint32_t sdst = (uint32_t)((srow * SKH + shalf * 16) * 2);

    const uint32_t a_loff = (uint32_t)(((lane & 15) * SKH + ((lane >> 4) << 3)) * 2);
    const uint32_t b_loff = (uint32_t)((((lane & 7) + ((lane >> 4) << 3)) * SKH
                                        + (((lane >> 3) & 1) << 3)) * 2);

    auto issue = [&](int c) {
        const uint32_t base = s0 + (uint32_t)((c % NSTG) * CHUNKB) + sdst;
        const __half* ap = Abase + c * CH;
        const __half* lp = Lbase + c * CH;
        const __half* bp = Bbase + c * CH;
        CP16(base,              ap);     CP16(base + 16,              ap + 8);
        CP16(base + TILEB,      lp);     CP16(base + TILEB + 16,      lp + 8);
        CP16(base + 2 * TILEB,  bp);     CP16(base + 2 * TILEB + 16,  bp + 8);
        CPCOMMIT();
    };

    float acc[2][8][4];
#pragma unroll
    for (int mt = 0; mt < 2; ++mt)
#pragma unroll
        for (int nt = 0; nt < 8; ++nt)
#pragma unroll
            for (int e = 0; e < 4; ++e) acc[mt][nt][e] = 0.f;

    issue(0);
    if (nch > 1) issue(1);

    for (int c = 0; c < nch; ++c) {
        if (c + 1 < nch) { CPWAIT1(); } else { CPWAIT0(); }
        __syncthreads();
        if (c + 2 < nch) issue(c + 2);

        const uint32_t stg = s0 + (uint32_t)((c % NSTG) * CHUNKB);
        const uint32_t ahb = stg + (uint32_t)(wm * SKH * 2) + a_loff;
        const uint32_t alb = ahb + TILEB;
        const uint32_t bhb = stg + 2 * TILEB + (uint32_t)(wn * SKH * 2) + b_loff;
#pragma unroll
        for (int s0i = 0; s0i < 2; ++s0i) {
            const int s = rev ? (1 - s0i) : s0i;
            const uint32_t kb2 = s * 32;
            uint32_t bfr[8][2];
#pragma unroll
            for (int p = 0; p < 4; ++p) {
                uint32_t r0, r1, r2, r3;
                LDSM_X4(r0, r1, r2, r3,
                        bhb + (uint32_t)(p * 16 * SKH * 2) + kb2);
                bfr[p*2][0] = r0; bfr[p*2][1] = r1;
                bfr[p*2+1][0] = r2; bfr[p*2+1][1] = r3;
            }
            uint32_t ah[2][4], al[2][4];
#pragma unroll
            for (int mt = 0; mt < 2; ++mt) {
                LDSM_X4(ah[mt][0], ah[mt][1], ah[mt][2], ah[mt][3],
                        ahb + (uint32_t)(mt * 16 * SKH * 2) + kb2);
                LDSM_X4(al[mt][0], al[mt][1], al[mt][2], al[mt][3],
                        alb + (uint32_t)(mt * 16 * SKH * 2) + kb2);
            }
#pragma unroll
            for (int nt = 0; nt < 8; ++nt)
#pragma unroll
                for (int mt = 0; mt < 2; ++mt)
                    mma_f16(acc[mt][nt][0], acc[mt][nt][1],
                            acc[mt][nt][2], acc[mt][nt][3],
                            ah[mt][0], ah[mt][1], ah[mt][2], ah[mt][3],
                            bfr[nt][0], bfr[nt][1]);
#pragma unroll
            for (int nt = 0; nt < 8; ++nt)
#pragma unroll
                for (int mt = 0; mt < 2; ++mt)
                    mma_f16(acc[mt][nt][0], acc[mt][nt][1],
                            acc[mt][nt][2], acc[mt][nt][3],
                            al[mt][0], al[mt][1], al[mt][2], al[mt][3],
                            bfr[nt][0], bfr[nt][1]);
        }
    }

    const int qr = lane >> 2, qc = lane & 3;
#pragma unroll
    for (int mt = 0; mt < 2; ++mt) {
        const int r = m0 + wm + mt * 16 + qr;
#pragma unroll
        for (int nt = 0; nt < 8; ++nt) {
            const int col = n0 + wn + nt * 8 + qc * 2;
            float b0 = bias[col], b1 = bias[col + 1];
            float v00 = acc[mt][nt][0] + b0, v01 = acc[mt][nt][1] + b1;
            float v10 = acc[mt][nt][2] + b0, v11 = acc[mt][nt][3] + b1;
            if (RELU) {
                v00 = fmaxf(v00, 0.f); v01 = fmaxf(v01, 0.f);
                v10 = fmaxf(v10, 0.f); v11 = fmaxf(v11, 0.f);
            }
            if (OUTH) {
                __half h00, l00, h01, l01, h10, l10, h11, l11;
                split16(v00, h00, l00); split16(v01, h01, l01);
                split16(v10, h10, l10); split16(v11, h11, l11);
                *(__half2*)(Ch + (size_t)r * N + col)       = __halves2half2(h00, h01);
                *(__half2*)(Cl + (size_t)r * N + col)       = __halves2half2(l00, l01);
                *(__half2*)(Ch + (size_t)(r + 8) * N + col) = __halves2half2(h10, h11);
                *(__half2*)(Cl + (size_t)(r + 8) * N + col) = __halves2half2(l10, l11);
            } else {
                *(float2*)(C + (size_t)r * N + col)       = make_float2(v00, v01);
                *(float2*)(C + (size_t)(r + 8) * N + col) = make_float2(v10, v11);
                if (Qh && col < 256) {
                    __half h00, l00, h01, l01, h10, l10, h11, l11;
                    split16(v00, h00, l00); split16(v01, h01, l01);
                    split16(v10, h10, l10); split16(v11, h11, l11);
                    *(__half2*)(Qh + (size_t)r * 256 + col)       = __halves2half2(h00, h01);
                    *(__half2*)(Ql + (size_t)r * 256 + col)       = __halves2half2(l00, l01);
                    *(__half2*)(Qh + (size_t)(r + 8) * 256 + col) = __halves2half2(h10, h11);
                    *(__half2*)(Ql + (size_t)(r + 8) * 256 + col) = __halves2half2(l10, l11);
                }
            }
        }
    }
}

// ==================== ebias via fp16 3-pass mma ============================
#define EBT 5120   /* halves per 128x40 tile */
__global__ __launch_bounds__(256) void ebias_mma(
    const __half* __restrict__ qh, const __half* __restrict__ ql,
    const __half* __restrict__ ekh, const __half* __restrict__ ekl,
    float* __restrict__ eb)
{
    __shared__ __half sm[4 * EBT];     // Ah Al Bh Bl
    const uint32_t s0 = smem_u32(sm);
    const int j = blockIdx.x;
    const int bh0 = blockIdx.y * 128;
    const int tid = threadIdx.x;
    const int lane = tid & 31, wid = tid >> 5;
    const int wm = (wid >> 1) * 32, wn = (wid & 1) * 64;

    {
        const int t = tid >> 6, u = tid & 63;
#pragma unroll
        for (int rr = 0; rr < 2; ++rr) {
            const int r = u + rr * 64;
            const __half* srcb;
            size_t soff;
            if (t < 2) {
                const int bh = bh0 + r;
                const int b = bh >> 3, h = bh & 7;
                soff = (size_t)(b * Sdim + j) * 256 + h * HDim;
                srcb = (t == 0 ? qh : ql);
            } else {
                soff = ((size_t)j * Sdim + r) * HDim;
                srcb = (t == 2 ? ekh : ekl);
            }
            const uint32_t dst = s0 + (uint32_t)((t * EBT + r * SKH) * 2);
#pragma unroll
            for (int sg = 0; sg < 4; ++sg)
                CP16(dst + sg * 16, srcb + soff + sg * 8);
        }
    }
    CPWAITALL();
    __syncthreads();

    const uint32_t a_loff = (uint32_t)(((lane & 15) * SKH + ((lane >> 4) << 3)) * 2);
    const uint32_t b_loff = (uint32_t)((((lane & 7) + ((lane >> 4) << 3)) * SKH
                                        + (((lane >> 3) & 1) << 3)) * 2);
    const uint32_t Ahb = s0 + (uint32_t)(wm * SKH * 2) + a_loff;
    const uint32_t Alb = Ahb + EBT * 2;
    const uint32_t Bhb = s0 + (uint32_t)(2 * EBT * 2) + (uint32_t)(wn * SKH * 2) + b_loff;
    const uint32_t Blb = Bhb + EBT * 2;

    float acc[2][8][4];
#pragma unroll
    for (int mt = 0; mt < 2; ++mt)
#pragma unroll
        for (int nt = 0; nt < 8; ++nt)
#pragma unroll
            for (int e = 0; e < 4; ++e) acc[mt][nt][e] = 0.f;

#pragma unroll
    for (int ss = 0; ss < 2; ++ss) {
        const uint32_t kb2 = ss * 32;
        uint32_t bhf[8][2], blf[8][2];
#pragma unroll
        for (int p = 0; p < 4; ++p) {
            uint32_t r0, r1, r2, r3;
            LDSM_X4(r0, r1, r2, r3, Bhb + (uint32_t)(p * 16 * SKH * 2) + kb2);
            bhf[p*2][0] = r0; bhf[p*2][1] = r1;
            bhf[p*2+1][0] = r2; bhf[p*2+1][1] = r3;
            LDSM_X4(r0, r1, r2, r3, Blb + (uint32_t)(p * 16 * SKH * 2) + kb2);
            blf[p*2][0] = r0; blf[p*2][1] = r1;
            blf[p*2+1][0] = r2; blf[p*2+1][1] = r3;
        }
        uint32_t ah[2][4], al[2][4];
#pragma unroll
        for (int mt = 0; mt < 2; ++mt) {
            LDSM_X4(ah[mt][0], ah[mt][1], ah[mt][2], ah[mt][3],
                    Ahb + (uint32_t)(mt * 16 * SKH * 2) + kb2);
            LDSM_X4(al[mt][0], al[mt][1], al[mt][2], al[mt][3],
                    Alb + (uint32_t)(mt * 16 * SKH * 2) + kb2);
        }
#pragma unroll
        for (int nt = 0; nt < 8; ++nt)
#pragma unroll
            for (int mt = 0; mt < 2; ++mt) {
                mma_f16(acc[mt][nt][0], acc[mt][nt][1], acc[mt][nt][2], acc[mt][nt][3],
                        ah[mt][0], ah[mt][1], ah[mt][2], ah[mt][3],
                        bhf[nt][0], bhf[nt][1]);
                mma_f16(acc[mt][nt][0], acc[mt][nt][1], acc[mt][nt][2], acc[mt][nt][3],
                        al[mt][0], al[mt][1], al[mt][2], al[mt][3],
                        bhf[nt][0], bhf[nt][1]);
                mma_f16(acc[mt][nt][0], acc[mt][nt][1], acc[mt][nt][2], acc[mt][nt][3],
                        ah[mt][0], ah[mt][1], ah[mt][2], ah[mt][3],
                        blf[nt][0], blf[nt][1]);
            }
    }

    const int qr = lane >> 2, qc = lane & 3;
#pragma unroll
    for (int mt = 0; mt < 2; ++mt) {
        const int row = wm + mt * 16 + qr;
#pragma unroll
        for (int nt = 0; nt < 8; ++nt) {
            const int col = wn + nt * 8 + qc * 2;
            float* p0 = eb + ((size_t)(bh0 + row) * Sdim + j) * Sdim + col;
            float* p1 = eb + ((size_t)(bh0 + row + 8) * Sdim + j) * Sdim + col;
            *(float2*)p0 = make_float2(acc[mt][nt][0], acc[mt][nt][1]);
            *(float2*)p1 = make_float2(acc[mt][nt][2], acc[mt][nt][3]);
        }
    }
}

// ==================== edge-value via fp16 3-pass mma =======================
// ctx_out = ctx + P @ evT, per block: fixed i, 128 bh x 32 d x 128 j.
#define EVSK 136                        /* 128 + 8 pad halves */
#define EVA_B (128 * EVSK * 2)          /* 34816 B per P tile */
#define EVB_B (32 * EVSK * 2)           /* 8704 B per evT tile */
#define EVM_BYTES (2 * EVA_B + 2 * EVB_B)  /* 87040 B */
__global__ __launch_bounds__(256) void ev_mma(
    const __half* __restrict__ ath, const __half* __restrict__ atl,
    const float* __restrict__ ev, const float* __restrict__ ctx,
    __half* __restrict__ ch, __half* __restrict__ cl)
{
    extern __shared__ __half es[];
    const uint32_t s0 = smem_u32(es);
    const int i = blockIdx.x, bh0 = blockIdx.y * 128;
    const int tid = threadIdx.x, lane = tid & 31, wid = tid >> 5;

    // A copy (P hi/lo): 128 rows x 16 segs of 16B, via cp.async
#pragma unroll
    for (int ss = 0; ss < 8; ++ss) {
        const int seg = tid + ss * 256;          // 0..2047
        const int r = seg >> 4, sg = seg & 15;
        const size_t src = ((size_t)(bh0 + r) * Sdim + i) * Sdim + sg * 8;
        const uint32_t dst = s0 + (uint32_t)((r * EVSK + sg * 8) * 2);
        CP16(dst, ath + src);
        CP16(dst + EVA_B, atl + src);
    }
    // B transpose+split: evT[d][j] from ev[i][j][d]
    {
        const float* evp = ev + (size_t)i * Sdim * HDim;
        const uint32_t Bh0 = s0 + 2 * EVA_B;
#pragma unroll
        for (int e = 0; e < 16; ++e) {
            const int idx = e * 256 + tid;       // 0..4095
            const int d = idx & 31, jj = idx >> 5;
            float v = evp[idx];
            __half h, l;
            split16(v, h, l);
            es[(Bh0 - s0) / 2 + d * EVSK + jj] = h;
            es[(Bh0 - s0) / 2 + EVB_B / 2 + d * EVSK + jj] = l;
        }
    }
    CPWAITALL();
    __syncthreads();

    const uint32_t a_loff = (uint32_t)(((lane & 15) * EVSK + ((lane >> 4) << 3)) * 2);
    const uint32_t b_loff = (uint32_t)((((lane & 7) + ((lane >> 4) << 3)) * EVSK
                                        + (((lane >> 3) & 1) << 3)) * 2);
    const uint32_t Ahb = s0 + (uint32_t)(wid * 16 * EVSK * 2) + a_loff;
    const uint32_t Alb = Ahb + EVA_B;
    const uint32_t Bhb = s0 + 2 * EVA_B + b_loff;
    const uint32_t Blb = Bhb + EVB_B;

    float acc[4][4];
#pragma unroll
    for (int nt = 0; nt < 4; ++nt)
#pragma unroll
        for (int e = 0; e < 4; ++e) acc[nt][e] = 0.f;

#pragma unroll
    for (int ks = 0; ks < 8; ++ks) {
        const uint32_t kb2 = ks * 32;
        uint32_t bhf[4][2], blf[4][2];
#pragma unroll
        for (int p = 0; p < 2; ++p) {
            uint32_t r0, r1, r2, r3;
            LDSM_X4(r0, r1, r2, r3, Bhb + (uint32_t)(p * 16 * EVSK * 2) + kb2);
            bhf[p*2][0] = r0; bhf[p*2][1] = r1;
            bhf[p*2+1][0] = r2; bhf[p*2+1][1] = r3;
            LDSM_X4(r0, r1, r2, r3, Blb + (uint32_t)(p * 16 * EVSK * 2) + kb2);
            blf[p*2][0] = r0; blf[p*2][1] = r1;
            blf[p*2+1][0] = r2; blf[p*2+1][1] = r3;
        }
        uint32_t ah[4], al[4];
        LDSM_X4(ah[0], ah[1], ah[2], ah[3], Ahb + kb2);
        LDSM_X4(al[0], al[1], al[2], al[3], Alb + kb2);
#pragma unroll
        for (int nt = 0; nt < 4; ++nt) {
            mma_f16(acc[nt][0], acc[nt][1], acc[nt][2], acc[nt][3],
                    ah[0], ah[1], ah[2], ah[3], bhf[nt][0], bhf[nt][1]);
            mma_f16(acc[nt][0], acc[nt][1], acc[nt][2], acc[nt][3],
                    al[0], al[1], al[2], al[3], bhf[nt][0], bhf[nt][1]);
            mma_f16(acc[nt][0], acc[nt][1], acc[nt][2], acc[nt][3],
                    ah[0], ah[1], ah[2], ah[3], blf[nt][0], blf[nt][1]);
        }
    }

    const int qr = lane >> 2, qc = lane & 3;
    const int row0 = wid * 16 + qr;
#pragma unroll
    for (int nt = 0; nt < 4; ++nt) {
        const int d0 = nt * 8 + qc * 2;
#pragma unroll
        for (int rr = 0; rr < 2; ++rr) {
            const int bh = bh0 + row0 + rr * 8;
            const int b = bh >> 3, h = bh & 7;
            const size_t idx = (size_t)(b * Sdim + i) * Ddim + h * HDim + d0;
            float2 cur = *(const float2*)(ctx + idx);
            float v0 = cur.x + acc[nt][rr * 2 + 0];
            float v1 = cur.y + acc[nt][rr * 2 + 1];
            __half h0, l0, h1, l1;
            split16(v0, h0, l0); split16(v1, h1, l1);
            *(__half2*)(ch + idx) = __halves2half2(h0, h1);
            *(__half2*)(cl + idx) = __halves2half2(l0, l1);
        }
    }
}

// ============ fused weight transpose -> fp16 [N][K] (single launch) ========
__global__ __launch_bounds__(256) void tr_all(
    const float* __restrict__ Wq, const float* __restrict__ Wk,
    const float* __restrict__ Wv, const float* __restrict__ Wo,
    const float* __restrict__ W1, const float* __restrict__ W2,
    __half* __restrict__ wqkvT, __half* __restrict__ woT,
    __half* __restrict__ w1T, __half* __restrict__ w2T)
{
    __shared__ float t[32][33];
    const int tb = blockIdx.x;
    const float* src; __half* dst; int K, N, kx, nx;
    if (tb < 768) {
        int w = tb / 256, r = tb % 256, l = r / 64, q = r % 64;
        src = (w == 0 ? Wq : (w == 1 ? Wk : Wv)) + (size_t)l * 65536;
        dst = wqkvT + (size_t)l * 196608 + (size_t)w * 65536;
        K = 256; N = 256; kx = (q / 8) * 32; nx = (q % 8) * 32;
    } else if (tb < 1024) {
        int r = tb - 768, l = r / 64, q = r % 64;
        src = Wo + (size_t)l * 65536; dst = woT + (size_t)l * 65536;
        K = 256; N = 256; kx = (q / 8) * 32; nx = (q % 8) * 32;
    } else if (tb < 3072) {
        int r = tb - 1024, l = r / 512, q = r % 512;
        src = W1 + (size_t)l * 524288; dst = w1T + (size_t)l * 524288;
        K = 256; N = 2048; kx = (q / 64) * 32; nx = (q % 64) * 32;
    } else {
        int r = tb - 3072, l = r / 512, q = r % 512;
        src = W2 + (size_t)l * 524288; dst = w2T + (size_t)l * 524288;
        K = 2048; N = 256; kx = (q / 8) * 32; nx = (q % 8) * 32;
    }
    const int x = threadIdx.x & 31, y = threadIdx.x >> 5;
#pragma unroll
    for (int yy = y; yy < 32; yy += 8)
        t[yy][x] = src[(size_t)(kx + yy) * N + nx + x];
    __syncthreads();
#pragma unroll
    for (int yy = y; yy < 32; yy += 8)
        dst[(size_t)(nx + yy) * K + kx + x] = __float2half_rn(t[x][yy]);
}

// ---- prep: x + split, ek split, bias pack (one launch) --------------------
__global__ void prep_kernel(const float* __restrict__ facts, float* __restrict__ x,
                            __half* __restrict__ xh, __half* __restrict__ xl,
                            const float* __restrict__ ekey,
                            __half* __restrict__ ekh, __half* __restrict__ ekl,
                            const float* __restrict__ bq, const float* __restrict__ bk,
                            const float* __restrict__ bv, float* __restrict__ bqkv)
{
    size_t idx = (size_t)blockIdx.x * 256 + threadIdx.x;
    float v = facts[idx];
    x[idx] = v;
    __half h, l;
    split16(v, h, l);
    xh[idx] = h; xl[idx] = l;
    if (idx < EKN) {
        float e = ekey[idx];
        __half eh, el;
        split16(e, eh, el);
        ekh[idx] = eh; ekl[idx] = el;
    }
    if (idx < Ldim * QKVS) {
        int li = (int)(idx / QKVS), ji = (int)(idx % QKVS);
        float bvv;
        if (ji < 256)      bvv = bq[li * 256 + ji];
        else if (ji < 512) bvv = bk[li * 256 + ji - 256];
        else               bvv = bv[li * 256 + ji - 512];
        bqkv[idx] = bvv;
    }
}

// -------- attention per (b,h): P emitted as fp16 hi/lo ---------------------
#define ATT_FLOATS (2*32*132 + 128*32 + 128*129)
#define ATT_BYTES  (ATT_FLOATS * 4)
__global__ __launch_bounds__(256) void attn_kernel(
    const float* __restrict__ qkv, const float* __restrict__ eb,
    const unsigned char* __restrict__ mask,
    __half* __restrict__ ath, __half* __restrict__ atl,
    float* __restrict__ ctx)
{
    extern __shared__ float sm[];
    float (*Qs)[132] = (float(*)[132])sm;
    float (*Ks)[132] = (float(*)[132])(sm + 32 * 132);
    float (*Vs)[32]  = (float(*)[32]) (sm + 2 * 32 * 132);
    float (*Sc)[129] = (float(*)[129])(sm + 2 * 32 * 132 + 128 * 32);
    const int bh = blockIdx.x;
    const int b = bh >> 3, h = bh & 7;
    const int tid = threadIdx.x;

    {
        const int r = tid >> 1;
        const int half = tid & 1;
        const float* base = qkv + (size_t)(b * Sdim + r) * QKVS + h * HDim + half * 16;
        const float* qp = base;
        const float* kp = base + 256;
        const float* vp = base + 512;
#pragma unroll
        for (int c = 0; c < 4; c++) {
            int d = half * 16 + c * 4;
            float4 vq = *(const float4*)(qp + c * 4);
            float4 vk = *(const float4*)(kp + c * 4);
            Qs[d+0][r] = vq.x; Qs[d+1][r] = vq.y; Qs[d+2][r] = vq.z; Qs[d+3][r] = vq.w;
            Ks[d+0][r] = vk.x; Ks[d+1][r] = vk.y; Ks[d+2][r] = vk.z; Ks[d+3][r] = vk.w;
            *(float4*)&Vs[r][d] = *(const float4*)(vp + c * 4);
        }
        const int warp = tid >> 5, lane = tid & 31;
        for (int jj = warp; jj < Sdim; jj += 8) {
            float4 t = *(const float4*)(eb + ((size_t)bh * Sdim + jj) * Sdim + lane * 4);
            Sc[lane*4+0][jj] = t.x; Sc[lane*4+1][jj] = t.y;
            Sc[lane*4+2][jj] = t.z; Sc[lane*4+3][jj] = t.w;
        }
    }
    __syncthreads();

    const int ty = tid >> 4, tx = tid & 15;
    const int i0 = ty * 8, j0 = tx * 8;
    float acc[8][8];
#pragma unroll
    for (int i = 0; i < 8; i++)
#pragma unroll
        for (int j = 0; j < 8; j++) acc[i][j] = 0.f;
#pragma unroll
    for (int d = 0; d < 32; d++) {
        float af[8], bf[8];
        *(float4*)&af[0] = *(const float4*)&Qs[d][i0];
        *(float4*)&af[4] = *(const float4*)&Qs[d][i0 + 4];
        *(float4*)&bf[0] = *(const float4*)&Ks[d][j0];
        *(float4*)&bf[4] = *(const float4*)&Ks[d][j0 + 4];
#pragma unroll
        for (int i = 0; i < 8; i++)
#pragma unroll
            for (int j = 0; j < 8; j++) acc[i][j] += af[i] * bf[j];
    }
    const float scale = 0.17677669529663687f;
    const float NEGINF = -__int_as_float(0x7f800000);
#pragma unroll
    for (int ii = 0; ii < 8; ii++) {
        unsigned long long mv =
            *(const unsigned long long*)(mask + ((size_t)bh * Sdim + i0 + ii) * Sdim + j0);
#pragma unroll
        for (int jj = 0; jj < 8; jj++) {
            float s = (acc[ii][jj] + Sc[i0 + ii][j0 + jj]) * scale;
            if ((mv >> (8 * jj)) & 0xffULL) s = NEGINF;
            Sc[i0 + ii][j0 + jj] = s;
        }
    }
    __syncthreads();

    {
        const int warp = tid >> 5, lane = tid & 31;
        for (int r = warp; r < Sdim; r += 8) {
            float vals[4];
#pragma unroll
            for (int c = 0; c < 4; c++) vals[c] = Sc[r][lane + 32 * c];
            float m = fmaxf(fmaxf(vals[0], vals[1]), fmaxf(vals[2], vals[3]));
#pragma unroll
            for (int o = 16; o > 0; o >>= 1) m = fmaxf(m, __shfl_xor_sync(0xffffffffu, m, o));
            float ssum = 0.f;
#pragma unroll
            for (int c = 0; c < 4; c++) { vals[c] = __expf(vals[c] - m); ssum += vals[c]; }
#pragma unroll
            for (int o = 16; o > 0; o >>= 1) ssum += __shfl_xor_sync(0xffffffffu, ssum, o);
            float inv = 1.f / ssum;
            __half* hp = ath + ((size_t)bh * Sdim + r) * Sdim;
            __half* lp = atl + ((size_t)bh * Sdim + r) * Sdim;
#pragma unroll
            for (int c = 0; c < 4; c++) {
                float p = vals[c] * inv;
                Sc[r][lane + 32 * c] = p;
                __half hh_, ll_;
                split16(p, hh_, ll_);
                hp[lane + 32 * c] = hh_;
                lp[lane + 32 * c] = ll_;
            }
        }
    }
    __syncthreads();

    const int ig = tid >> 3;
    const int dg = tid & 7;
    float o[4][4];
#pragma unroll
    for (int c = 0; c < 4; c++)
#pragma unroll
        for (int e = 0; e < 4; e++) o[c][e] = 0.f;
    for (int j = 0; j < Sdim; j++) {
        float4 vv = *(const float4*)&Vs[j][dg * 4];
#pragma unroll
        for (int c = 0; c < 4; c++) {
            float p = Sc[ig * 4 + c][j];
            o[c][0] += p * vv.x; o[c][1] += p * vv.y;
            o[c][2] += p * vv.z; o[c][3] += p * vv.w;
        }
    }
#pragma unroll
    for (int c = 0; c < 4; c++) {
        float* cp = ctx + (size_t)(b * Sdim + ig * 4 + c) * Ddim + h * HDim + dg * 4;
        *(float4*)cp = make_float4(o[c][0], o[c][1], o[c][2], o[c][3]);
    }
}

// ---------------- layer norm (+ hi/lo split out) ---------------------------
__global__ __launch_bounds__(256) void ln_kernel(
    const float* __restrict__ in1, const float* __restrict__ in2, float alpha,
    const float* __restrict__ g, const float* __restrict__ b,
    float* __restrict__ out, __half* __restrict__ outh, __half* __restrict__ outl)
{
    const int warp = threadIdx.x >> 5, lane = threadIdx.x & 31;
    const int row = blockIdx.x * 8 + warp;
    const float* p1 = in1 + (size_t)row * Ddim;
    float v[8];
#pragma unroll
    for (int c = 0; c < 8; c++) {
        int col = lane + 32 * c;
        float t = alpha * p1[col];
        if (in2) t += in2[(size_t)row * Ddim + col];
        v[c] = t;
    }
    float s = 0.f;
#pragma unroll
    for (int c = 0; c < 8; c++) s += v[c];
#pragma unroll
    for (int o = 16; o > 0; o >>= 1) s += __shfl_xor_sync(0xffffffffu, s, o);
    float mu = s * (1.f / Ddim);
    float var = 0.f;
#pragma unroll
    for (int c = 0; c < 8; c++) { float d = v[c] - mu; var += d * d; }
#pragma unroll
    for (int o = 16; o > 0; o >>= 1) var += __shfl_xor_sync(0xffffffffu, var, o);
    var *= (1.f / Ddim);
    float inv = rsqrtf(var + 1e-5f);
#pragma unroll
    for (int c = 0; c < 8; c++) {
        int col = lane + 32 * c;
        float r = (v[c] - mu) * inv * g[col] + b[col];
        out[(size_t)row * Ddim + col] = r;
        __half h, l;
        split16(r, h, l);
        outh[(size_t)row * Ddim + col] = h;
        outl[(size_t)row * Ddim + col] = l;
    }
}

__global__ void out_transpose(const float* __restrict__ x, float* __restrict__ out)
{
    size_t idx = (size_t)blockIdx.x * 256 + threadIdx.x;
    int d = (int)(idx % Ddim);
    size_t sb = idx / Ddim;
    int bcol = (int)(sb % Bdim);
    int s = (int)(sb / Bdim);
    out[idx] = x[((size_t)bcol * Sdim + s) * Ddim + d];
}

// ---------------- host -----------------------------------------------------
extern "C" void kernel_launch(void* const* d_in, const int* in_sizes, int n_in,
                              void* d_out, int out_size)
{
    const float* facts = (const float*)d_in[0];
    const float* ekey  = (const float*)d_in[1];
    const float* evalp = (const float*)d_in[2];
    const unsigned char* mask = (const unsigned char*)d_in[3];
    const float *Wq, *Wk, *Wv, *Wo, *bq, *bk, *bv, *bo;
    if (in_sizes[5] == Ldim * Ddim) {
        Wq = (const float*)d_in[4];  bq = (const float*)d_in[5];
        Wk = (const float*)d_in[6];  bk = (const float*)d_in[7];
        Wv = (const float*)d_in[8];  bv = (const float*)d_in[9];
        Wo = (const float*)d_in[10]; bo = (const float*)d_in[11];
    } else {
        Wq = (const float*)d_in[4];  Wk = (const float*)d_in[5];
        Wv = (const float*)d_in[6];  Wo = (const float*)d_in[7];
        bq = (const float*)d_in[8];  bk = (const float*)d_in[9];
        bv = (const float*)d_in[10]; bo = (const float*)d_in[11];
    }
    const float* ln1g = (const float*)d_in[12];
    const float* ln1b = (const float*)d_in[13];
    const float* W1   = (const float*)d_in[14];
    const float* b1   = (const float*)d_in[15];
    const float* W2   = (const float*)d_in[16];
    const float* b2   = (const float*)d_in[17];
    const float* ln2g = (const float*)d_in[18];
    const float* ln2b = (const float*)d_in[19];

    float *x, *qkv, *ctx, *tmp, *eb, *bqkvp;
    __half *ath, *atl;
    __half *xh, *xl, *ch, *cl, *ffh, *ffl, *qh, *ql, *ekh, *ekl;
    __half *wqkvT, *woT, *w1T, *w2T;
    cudaGetSymbolAddress((void**)&x,    g_x);
    cudaGetSymbolAddress((void**)&qkv,  g_qkv);
    cudaGetSymbolAddress((void**)&ctx,  g_ctx);
    cudaGetSymbolAddress((void**)&tmp,  g_tmp);
    cudaGetSymbolAddress((void**)&eb,   g_eb);
    cudaGetSymbolAddress((void**)&ath,  g_ath);
    cudaGetSymbolAddress((void**)&atl,  g_atl);
    cudaGetSymbolAddress((void**)&xh,   g_xh);
    cudaGetSymbolAddress((void**)&xl,   g_xl);
    cudaGetSymbolAddress((void**)&ch,   g_ch);
    cudaGetSymbolAddress((void**)&cl,   g_cl);
    cudaGetSymbolAddress((void**)&ffh,  g_ffh);
    cudaGetSymbolAddress((void**)&ffl,  g_ffl);
    cudaGetSymbolAddress((void**)&qh,   g_qh);
    cudaGetSymbolAddress((void**)&ql,   g_ql);
    cudaGetSymbolAddress((void**)&ekh,  g_ekh);
    cudaGetSymbolAddress((void**)&ekl,  g_ekl);
    cudaGetSymbolAddress((void**)&wqkvT, g_wqkvT);
    cudaGetSymbolAddress((void**)&woT,  g_woT);
    cudaGetSymbolAddress((void**)&w1T,  g_w1T);
    cudaGetSymbolAddress((void**)&w2T,  g_w2T);
    cudaGetSymbolAddress((void**)&bqkvp, g_bqkv);

    cudaFuncSetAttribute(mma_gemm<false,false>, cudaFuncAttributeMaxDynamicSharedMemorySize, GSMB);
    cudaFuncSetAttribute(mma_gemm<true,true>,   cudaFuncAttributeMaxDynamicSharedMemorySize, GSMB);
    cudaFuncSetAttribute(attn_kernel, cudaFuncAttributeMaxDynamicSharedMemorySize, ATT_BYTES);
    cudaFuncSetAttribute(ev_mma,      cudaFuncAttributeMaxDynamicSharedMemorySize, EVM_BYTES);

    // launches: 0 tr_all, 1 prep, 2 QKV, 3 ebias_mma (ncu target)
    tr_all<<<5120, 256>>>(Wq, Wk, Wv, Wo, W1, W2, wqkvT, woT, w1T, w2T);        // 0
    prep_kernel<<<NR * Ddim / 256, 256>>>(facts, x, xh, xl,
                                          ekey, ekh, ekl, bq, bk, bv, bqkvp);   // 1

    for (int l = 0; l < Ldim; l++) {
        mma_gemm<false,false><<<dim3(QKVS / 128, NR / 128), 256, GSMB>>>(
            xh, xl, wqkvT + (size_t)l * 3 * Ddim * Ddim, bqkvp + l * QKVS,
            qkv, nullptr, nullptr, qh, ql, NR, QKVS, Ddim);                     // 2 (l=0)

        ebias_mma<<<dim3(Sdim, BHdim / 128), 256>>>(qh, ql, ekh, ekl, eb);      // 3 (l=0)
        attn_kernel<<<BHdim, 256, ATT_BYTES>>>(qkv, eb, mask, ath, atl, ctx);
        ev_mma<<<dim3(Sdim, BHdim / 128), 256, EVM_BYTES>>>(ath, atl, evalp,
                                                            ctx, ch, cl);

        mma_gemm<false,false><<<dim3(Ddim / 128, NR / 128), 256, GSMB>>>(
            ch, cl, woT + (size_t)l * Ddim * Ddim, bo + l * Ddim,
            tmp, nullptr, nullptr, nullptr, nullptr, NR, Ddim, Ddim);
        ln_kernel<<<NR / 8, 256>>>(tmp, x, 1.f, ln1g + l * Ddim, ln1b + l * Ddim,
                                   x, xh, xl);

        mma_gemm<true,true><<<dim3(Fdim / 128, NR / 128), 256, GSMB>>>(
            xh, xl, w1T + (size_t)l * Fdim * Ddim, b1 + l * Fdim,
            nullptr, ffh, ffl, nullptr, nullptr, NR, Fdim, Ddim);
        mma_gemm<false,false><<<dim3(Ddim / 128, NR / 128), 256, GSMB>>>(
            ffh, ffl, w2T + (size_t)l * Ddim * Fdim, b2 + l * Ddim,
            tmp, nullptr, nullptr, nullptr, nullptr, NR, Ddim, Fdim);
        ln_kernel<<<NR / 8, 256>>>(tmp, nullptr, 2.f, ln2g + l * Ddim, ln2b + l * Ddim,
                                   x, xh, xl);
    }

    out_transpose<<<NR * Ddim / 256, 256>>>(x, (float*)d_out);
}

// round 15
// speedup vs baseline: 1.2296x; 1.0775x over previous
#include <cuda_runtime.h>
#include <cuda_fp16.h>
#include <cstdint>
#include <math.h>

#define Bdim 128
#define Sdim 128
#define Ddim 256
#define Hdim 8
#define HDim 32
#define Fdim 2048
#define Ldim 4
#define BHdim (Bdim*Hdim)     /* 1024 */
#define NR (Bdim*Sdim)        /* 16384 rows */
#define QKVS 768
#define EKN (Sdim*Sdim*HDim)  /* 524288 */

// ---------------- scratch (device globals) ---------------------------------
__device__ float g_x[NR*Ddim];
__device__ float g_ctx[NR*Ddim];
__device__ float g_tmp[NR*Ddim];
__device__ float g_eb[(size_t)BHdim*Sdim*Sdim];   // [bh][j][i]
__device__ __half g_ath[(size_t)BHdim*Sdim*Sdim]; // P hi [bh][i][j]
__device__ __half g_atl[(size_t)BHdim*Sdim*Sdim]; // P lo
__device__ __half g_qkvh[(size_t)NR*QKVS];
__device__ __half g_qkvl[(size_t)NR*QKVS];
__device__ __half g_xh[NR*Ddim];
__device__ __half g_xl[NR*Ddim];
__device__ __half g_ch[NR*Ddim];
__device__ __half g_cl[NR*Ddim];
__device__ __half g_ffh[(size_t)NR*Fdim];
__device__ __half g_ffl[(size_t)NR*Fdim];
__device__ __half g_ekh[EKN];
__device__ __half g_ekl[EKN];
__device__ __half g_wqkvT[(size_t)Ldim*3*Ddim*Ddim];
__device__ __half g_woT[(size_t)Ldim*Ddim*Ddim];
__device__ __half g_w1T[(size_t)Ldim*Fdim*Ddim];
__device__ __half g_w2T[(size_t)Ldim*Ddim*Fdim];
__device__ float g_bqkv[Ldim*QKVS];

// ==================== helpers =============================================
__device__ __forceinline__ uint32_t smem_u32(const void* p) {
    uint32_t a;
    asm("{ .reg .u64 t; cvta.to.shared.u64 t, %1; cvt.u32.u64 %0, t; }"
        : "=r"(a) : "l"(p));
    return a;
}
#define LDSM_X4(R0,R1,R2,R3,ADDR) \
    asm volatile("ldmatrix.sync.aligned.m8n8.x4.shared.b16 {%0,%1,%2,%3}, [%4];" \
        : "=r"(R0), "=r"(R1), "=r"(R2), "=r"(R3) : "r"(ADDR) : "memory")
#define CP16(dst, src) \
    asm volatile("cp.async.cg.shared.global [%0], [%1], 16;" :: "r"(dst), "l"(src))
#define CPCOMMIT() asm volatile("cp.async.commit_group;" ::: "memory")
#define CPWAIT1()  asm volatile("cp.async.wait_group 1;" ::: "memory")
#define CPWAIT0()  asm volatile("cp.async.wait_group 0;" ::: "memory")
#define CPWAITALL() asm volatile("cp.async.wait_all;" ::: "memory")

__device__ __forceinline__ void mma_f16(
    float& c0, float& c1, float& c2, float& c3,
    uint32_t a0, uint32_t a1, uint32_t a2, uint32_t a3,
    uint32_t b0, uint32_t b1)
{
    asm volatile(
        "mma.sync.aligned.m16n8k16.row.col.f32.f16.f16.f32 "
        "{%0,%1,%2,%3}, {%4,%5,%6,%7}, {%8,%9}, {%0,%1,%2,%3};"
        : "+f"(c0), "+f"(c1), "+f"(c2), "+f"(c3)
        : "r"(a0), "r"(a1), "r"(a2), "r"(a3), "r"(b0), "r"(b1));
}

__device__ __forceinline__ void split16(float v, __half& h, __half& l) {
    h = __float2half_rn(v);
    l = __float2half_rn(v - __half2float(h));
}

// ==================== fp16 split-A mma GEMM (cp.async, 3-stage) ============
#define CH 32
#define SKH 40
#define TILEB (128 * SKH * 2)
#define CHUNKB (3 * TILEB)
#define NSTG 3
#define GSMB (NSTG * CHUNKB)            /* 92160 B */

template<bool RELU, bool OUTH>
__global__ __launch_bounds__(256, 2) void mma_gemm(
    const __half* __restrict__ Ah, const __half* __restrict__ Al,
    const __half* __restrict__ BT, const float* __restrict__ bias,
    float* __restrict__ C, __half* __restrict__ Ch, __half* __restrict__ Cl,
    int M, int N, int K)
{
    extern __shared__ __half sh[];
    const uint32_t s0 = smem_u32(sh);
    const int tid = threadIdx.x;
    const int lane = tid & 31, wid = tid >> 5;
    const int wm = (wid >> 1) * 32, wn = (wid & 1) * 64;
    const int m0 = blockIdx.y * 128, n0 = blockIdx.x * 128;
    const int nch = K / CH;
    const int srow = tid >> 1, shalf = tid & 1;
    const int rev = wid & 1;

    const __half* Abase = Ah + (size_t)(m0 + srow) * K + shalf * 16;
    const __half* Lbase = Al + (size_t)(m0 + srow) * K + shalf * 16;
    const __half* Bbase = BT + (size_t)(n0 + srow) * K + shalf * 16;
    const uint32_t sdst = (uint32_t)((srow * SKH + shalf * 16) * 2);

    const uint32_t a_loff = (uint32_t)(((lane & 15) * SKH + ((lane >> 4) << 3)) * 2);
    const uint32_t b_loff = (uint32_t)((((lane & 7) + ((lane >> 4) << 3)) * SKH
                                        + (((lane >> 3) & 1) << 3)) * 2);

    auto issue = [&](int c) {
        const uint32_t base = s0 + (uint32_t)((c % NSTG) * CHUNKB) + sdst;
        const __half* ap = Abase + c * CH;
        const __half* lp = Lbase + c * CH;
        const __half* bp = Bbase + c * CH;
        CP16(base,              ap);     CP16(base + 16,              ap + 8);
        CP16(base + TILEB,      lp);     CP16(base + TILEB + 16,      lp + 8);
        CP16(base + 2 * TILEB,  bp);     CP16(base + 2 * TILEB + 16,  bp + 8);
        CPCOMMIT();
    };

    float acc[2][8][4];
#pragma unroll
    for (int mt = 0; mt < 2; ++mt)
#pragma unroll
        for (int nt = 0; nt < 8; ++nt)
#pragma unroll
            for (int e = 0; e < 4; ++e) acc[mt][nt][e] = 0.f;

    issue(0);
    if (nch > 1) issue(1);

    for (int c = 0; c < nch; ++c) {
        if (c + 1 < nch) { CPWAIT1(); } else { CPWAIT0(); }
        __syncthreads();
        if (c + 2 < nch) issue(c + 2);

        const uint32_t stg = s0 + (uint32_t)((c % NSTG) * CHUNKB);
        const uint32_t ahb = stg + (uint32_t)(wm * SKH * 2) + a_loff;
        const uint32_t alb = ahb + TILEB;
        const uint32_t bhb = stg + 2 * TILEB + (uint32_t)(wn * SKH * 2) + b_loff;
#pragma unroll
        for (int s0i = 0; s0i < 2; ++s0i) {
            const int s = rev ? (1 - s0i) : s0i;
            const uint32_t kb2 = s * 32;
            uint32_t bfr[8][2];
#pragma unroll
            for (int p = 0; p < 4; ++p) {
                uint32_t r0, r1, r2, r3;
                LDSM_X4(r0, r1, r2, r3,
                        bhb + (uint32_t)(p * 16 * SKH * 2) + kb2);
                bfr[p*2][0] = r0; bfr[p*2][1] = r1;
                bfr[p*2+1][0] = r2; bfr[p*2+1][1] = r3;
            }
            uint32_t ah[2][4], al[2][4];
#pragma unroll
            for (int mt = 0; mt < 2; ++mt) {
                LDSM_X4(ah[mt][0], ah[mt][1], ah[mt][2], ah[mt][3],
                        ahb + (uint32_t)(mt * 16 * SKH * 2) + kb2);
                LDSM_X4(al[mt][0], al[mt][1], al[mt][2], al[mt][3],
                        alb + (uint32_t)(mt * 16 * SKH * 2) + kb2);
            }
#pragma unroll
            for (int nt = 0; nt < 8; ++nt)
#pragma unroll
                for (int mt = 0; mt < 2; ++mt)
                    mma_f16(acc[mt][nt][0], acc[mt][nt][1],
                            acc[mt][nt][2], acc[mt][nt][3],
                            ah[mt][0], ah[mt][1], ah[mt][2], ah[mt][3],
                            bfr[nt][0], bfr[nt][1]);
#pragma unroll
            for (int nt = 0; nt < 8; ++nt)
#pragma unroll
                for (int mt = 0; mt < 2; ++mt)
                    mma_f16(acc[mt][nt][0], acc[mt][nt][1],
                            acc[mt][nt][2], acc[mt][nt][3],
                            al[mt][0], al[mt][1], al[mt][2], al[mt][3],
                            bfr[nt][0], bfr[nt][1]);
        }
    }

    const int qr = lane >> 2, qc = lane & 3;
#pragma unroll
    for (int mt = 0; mt < 2; ++mt) {
        const int r = m0 + wm + mt * 16 + qr;
#pragma unroll
        for (int nt = 0; nt < 8; ++nt) {
            const int col = n0 + wn + nt * 8 + qc * 2;
            float b0 = bias[col], b1 = bias[col + 1];
            float v00 = acc[mt][nt][0] + b0, v01 = acc[mt][nt][1] + b1;
            float v10 = acc[mt][nt][2] + b0, v11 = acc[mt][nt][3] + b1;
            if (RELU) {
                v00 = fmaxf(v00, 0.f); v01 = fmaxf(v01, 0.f);
                v10 = fmaxf(v10, 0.f); v11 = fmaxf(v11, 0.f);
            }
            if (OUTH) {
                __half h00, l00, h01, l01, h10, l10, h11, l11;
                split16(v00, h00, l00); split16(v01, h01, l01);
                split16(v10, h10, l10); split16(v11, h11, l11);
                *(__half2*)(Ch + (size_t)r * N + col)       = __halves2half2(h00, h01);
                *(__half2*)(Cl + (size_t)r * N + col)       = __halves2half2(l00, l01);
                *(__half2*)(Ch + (size_t)(r + 8) * N + col) = __halves2half2(h10, h11);
                *(__half2*)(Cl + (size_t)(r + 8) * N + col) = __halves2half2(l10, l11);
            } else {
                *(float2*)(C + (size_t)r * N + col)       = make_float2(v00, v01);
                *(float2*)(C + (size_t)(r + 8) * N + col) = make_float2(v10, v11);
            }
        }
    }
}

// ==================== ebias via fp16 3-pass mma ============================
#define EBT 5120
__global__ __launch_bounds__(256) void ebias_mma(
    const __half* __restrict__ qkvh, const __half* __restrict__ qkvl,
    const __half* __restrict__ ekh, const __half* __restrict__ ekl,
    float* __restrict__ eb)
{
    __shared__ __half sm[4 * EBT];     // Ah Al Bh Bl
    const uint32_t s0 = smem_u32(sm);
    const int j = blockIdx.x;
    const int bh0 = blockIdx.y * 128;
    const int tid = threadIdx.x;
    const int lane = tid & 31, wid = tid >> 5;
    const int wm = (wid >> 1) * 32, wn = (wid & 1) * 64;

    {
        const int t = tid >> 6, u = tid & 63;
#pragma unroll
        for (int rr = 0; rr < 2; ++rr) {
            const int r = u + rr * 64;
            const __half* srcb;
            size_t soff;
            if (t < 2) {
                const int bh = bh0 + r;
                const int b = bh >> 3, h = bh & 7;
                soff = (size_t)(b * Sdim + j) * QKVS + h * HDim;   // q section
                srcb = (t == 0 ? qkvh : qkvl);
            } else {
                soff = ((size_t)j * Sdim + r) * HDim;
                srcb = (t == 2 ? ekh : ekl);
            }
            const uint32_t dst = s0 + (uint32_t)((t * EBT + r * SKH) * 2);
#pragma unroll
            for (int sg = 0; sg < 4; ++sg)
                CP16(dst + sg * 16, srcb + soff + sg * 8);
        }
    }
    CPWAITALL();
    __syncthreads();

    const uint32_t a_loff = (uint32_t)(((lane & 15) * SKH + ((lane >> 4) << 3)) * 2);
    const uint32_t b_loff = (uint32_t)((((lane & 7) + ((lane >> 4) << 3)) * SKH
                                        + (((lane >> 3) & 1) << 3)) * 2);
    const uint32_t Ahb = s0 + (uint32_t)(wm * SKH * 2) + a_loff;
    const uint32_t Alb = Ahb + EBT * 2;
    const uint32_t Bhb = s0 + (uint32_t)(2 * EBT * 2) + (uint32_t)(wn * SKH * 2) + b_loff;
    const uint32_t Blb = Bhb + EBT * 2;

    float acc[2][8][4];
#pragma unroll
    for (int mt = 0; mt < 2; ++mt)
#pragma unroll
        for (int nt = 0; nt < 8; ++nt)
#pragma unroll
            for (int e = 0; e < 4; ++e) acc[mt][nt][e] = 0.f;

#pragma unroll
    for (int ss = 0; ss < 2; ++ss) {
        const uint32_t kb2 = ss * 32;
        uint32_t bhf[8][2], blf[8][2];
#pragma unroll
        for (int p = 0; p < 4; ++p) {
            uint32_t r0, r1, r2, r3;
            LDSM_X4(r0, r1, r2, r3, Bhb + (uint32_t)(p * 16 * SKH * 2) + kb2);
            bhf[p*2][0] = r0; bhf[p*2][1] = r1;
            bhf[p*2+1][0] = r2; bhf[p*2+1][1] = r3;
            LDSM_X4(r0, r1, r2, r3, Blb + (uint32_t)(p * 16 * SKH * 2) + kb2);
            blf[p*2][0] = r0; blf[p*2][1] = r1;
            blf[p*2+1][0] = r2; blf[p*2+1][1] = r3;
        }
        uint32_t ah[2][4], al[2][4];
#pragma unroll
        for (int mt = 0; mt < 2; ++mt) {
            LDSM_X4(ah[mt][0], ah[mt][1], ah[mt][2], ah[mt][3],
                    Ahb + (uint32_t)(mt * 16 * SKH * 2) + kb2);
            LDSM_X4(al[mt][0], al[mt][1], al[mt][2], al[mt][3],
                    Alb + (uint32_t)(mt * 16 * SKH * 2) + kb2);
        }
#pragma unroll
        for (int nt = 0; nt < 8; ++nt)
#pragma unroll
            for (int mt = 0; mt < 2; ++mt) {
                mma_f16(acc[mt][nt][0], acc[mt][nt][1], acc[mt][nt][2], acc[mt][nt][3],
                        ah[mt][0], ah[mt][1], ah[mt][2], ah[mt][3],
                        bhf[nt][0], bhf[nt][1]);
                mma_f16(acc[mt][nt][0], acc[mt][nt][1], acc[mt][nt][2], acc[mt][nt][3],
                        al[mt][0], al[mt][1], al[mt][2], al[mt][3],
                        bhf[nt][0], bhf[nt][1]);
                mma_f16(acc[mt][nt][0], acc[mt][nt][1], acc[mt][nt][2], acc[mt][nt][3],
                        ah[mt][0], ah[mt][1], ah[mt][2], ah[mt][3],
                        blf[nt][0], blf[nt][1]);
            }
    }

    const int qr = lane >> 2, qc = lane & 3;
#pragma unroll
    for (int mt = 0; mt < 2; ++mt) {
        const int row = wm + mt * 16 + qr;
#pragma unroll
        for (int nt = 0; nt < 8; ++nt) {
            const int col = wn + nt * 8 + qc * 2;
            float* p0 = eb + ((size_t)(bh0 + row) * Sdim + j) * Sdim + col;
            float* p1 = eb + ((size_t)(bh0 + row + 8) * Sdim + j) * Sdim + col;
            *(float2*)p0 = make_float2(acc[mt][nt][0], acc[mt][nt][1]);
            *(float2*)p1 = make_float2(acc[mt][nt][2], acc[mt][nt][3]);
        }
    }
}

// ==================== attention scores + softmax (QK via mma) ==============
// per (b,h): scores = Q@K^T (3-pass split mma) + eb, *scale, mask, softmax,
// P emitted hi/lo to global.
#define ATTM_BYTES (4 * EBT * 2 + 128 * 129 * 4)   /* 40960 + 66048 = 107008 */
__global__ __launch_bounds__(256) void attn_mma(
    const __half* __restrict__ qkvh, const __half* __restrict__ qkvl,
    const float* __restrict__ eb, const unsigned char* __restrict__ mask,
    __half* __restrict__ ath, __half* __restrict__ atl)
{
    extern __shared__ char asm_[];
    __half* hq = (__half*)asm_;                    // Qh Ql Kh Kl tiles
    float (*Sc)[129] = (float(*)[129])(asm_ + 4 * EBT * 2);
    const uint32_t s0 = smem_u32(hq);
    const int bh = blockIdx.x;
    const int b = bh >> 3, h = bh & 7;
    const int tid = threadIdx.x;
    const int lane = tid & 31, wid = tid >> 5;
    const int wm = (wid >> 1) * 32, wn = (wid & 1) * 64;

    {   // copy q/k hi/lo tiles via cp.async
        const int t = tid >> 6, u = tid & 63;
        const __half* srcb = (t == 0 || t == 2) ? qkvh : qkvl;
        const size_t sec = (t < 2) ? 0 : 256;
#pragma unroll
        for (int rr = 0; rr < 2; ++rr) {
            const int r = u + rr * 64;
            const size_t soff = (size_t)(b * Sdim + r) * QKVS + sec + h * HDim;
            const uint32_t dst = s0 + (uint32_t)((t * EBT + r * SKH) * 2);
#pragma unroll
            for (int sg = 0; sg < 4; ++sg)
                CP16(dst + sg * 16, srcb + soff + sg * 8);
        }
    }
    {   // eb transposed into Sc[i][j]
        for (int jj = wid; jj < Sdim; jj += 8) {
            float4 t4 = *(const float4*)(eb + ((size_t)bh * Sdim + jj) * Sdim + lane * 4);
            Sc[lane*4+0][jj] = t4.x; Sc[lane*4+1][jj] = t4.y;
            Sc[lane*4+2][jj] = t4.z; Sc[lane*4+3][jj] = t4.w;
        }
    }
    CPWAITALL();
    __syncthreads();

    const uint32_t a_loff = (uint32_t)(((lane & 15) * SKH + ((lane >> 4) << 3)) * 2);
    const uint32_t b_loff = (uint32_t)((((lane & 7) + ((lane >> 4) << 3)) * SKH
                                        + (((lane >> 3) & 1) << 3)) * 2);
    const uint32_t Ahb = s0 + (uint32_t)(wm * SKH * 2) + a_loff;
    const uint32_t Alb = Ahb + EBT * 2;
    const uint32_t Bhb = s0 + (uint32_t)(2 * EBT * 2) + (uint32_t)(wn * SKH * 2) + b_loff;
    const uint32_t Blb = Bhb + EBT * 2;

    float acc[2][8][4];
#pragma unroll
    for (int mt = 0; mt < 2; ++mt)
#pragma unroll
        for (int nt = 0; nt < 8; ++nt)
#pragma unroll
            for (int e = 0; e < 4; ++e) acc[mt][nt][e] = 0.f;

#pragma unroll
    for (int ss = 0; ss < 2; ++ss) {
        const uint32_t kb2 = ss * 32;
        uint32_t bhf[8][2], blf[8][2];
#pragma unroll
        for (int p = 0; p < 4; ++p) {
            uint32_t r0, r1, r2, r3;
            LDSM_X4(r0, r1, r2, r3, Bhb + (uint32_t)(p * 16 * SKH * 2) + kb2);
            bhf[p*2][0] = r0; bhf[p*2][1] = r1;
            bhf[p*2+1][0] = r2; bhf[p*2+1][1] = r3;
            LDSM_X4(r0, r1, r2, r3, Blb + (uint32_t)(p * 16 * SKH * 2) + kb2);
            blf[p*2][0] = r0; blf[p*2][1] = r1;
            blf[p*2+1][0] = r2; blf[p*2+1][1] = r3;
        }
        uint32_t ah[2][4], al[2][4];
#pragma unroll
        for (int mt = 0; mt < 2; ++mt) {
            LDSM_X4(ah[mt][0], ah[mt][1], ah[mt][2], ah[mt][3],
                    Ahb + (uint32_t)(mt * 16 * SKH * 2) + kb2);
            LDSM_X4(al[mt][0], al[mt][1], al[mt][2], al[mt][3],
                    Alb + (uint32_t)(mt * 16 * SKH * 2) + kb2);
        }
#pragma unroll
        for (int nt = 0; nt < 8; ++nt)
#pragma unroll
            for (int mt = 0; mt < 2; ++mt) {
                mma_f16(acc[mt][nt][0], acc[mt][nt][1], acc[mt][nt][2], acc[mt][nt][3],
                        ah[mt][0], ah[mt][1], ah[mt][2], ah[mt][3],
                        bhf[nt][0], bhf[nt][1]);
                mma_f16(acc[mt][nt][0], acc[mt][nt][1], acc[mt][nt][2], acc[mt][nt][3],
                        al[mt][0], al[mt][1], al[mt][2], al[mt][3],
                        bhf[nt][0], bhf[nt][1]);
                mma_f16(acc[mt][nt][0], acc[mt][nt][1], acc[mt][nt][2], acc[mt][nt][3],
                        ah[mt][0], ah[mt][1], ah[mt][2], ah[mt][3],
                        blf[nt][0], blf[nt][1]);
            }
    }

    // scores = (qk + eb) * scale, mask -> Sc
    const float scale = 0.17677669529663687f;
    const float NEGINF = -__int_as_float(0x7f800000);
    const int qr = lane >> 2, qc = lane & 3;
#pragma unroll
    for (int mt = 0; mt < 2; ++mt) {
        const int row = wm + mt * 16 + qr;
#pragma unroll
        for (int nt = 0; nt < 8; ++nt) {
            const int col = wn + nt * 8 + qc * 2;
#pragma unroll
            for (int rr = 0; rr < 2; ++rr) {
                const int r = row + rr * 8;
                const unsigned char* mp = mask + ((size_t)bh * Sdim + r) * Sdim + col;
                float s0v = (acc[mt][nt][rr*2+0] + Sc[r][col])     * scale;
                float s1v = (acc[mt][nt][rr*2+1] + Sc[r][col + 1]) * scale;
                if (mp[0]) s0v = NEGINF;
                if (mp[1]) s1v = NEGINF;
                Sc[r][col]     = s0v;
                Sc[r][col + 1] = s1v;
            }
        }
    }
    __syncthreads();

    // softmax rows; P hi/lo to global
    for (int r = wid; r < Sdim; r += 8) {
        float vals[4];
#pragma unroll
        for (int c = 0; c < 4; c++) vals[c] = Sc[r][lane + 32 * c];
        float m = fmaxf(fmaxf(vals[0], vals[1]), fmaxf(vals[2], vals[3]));
#pragma unroll
        for (int o = 16; o > 0; o >>= 1) m = fmaxf(m, __shfl_xor_sync(0xffffffffu, m, o));
        float ssum = 0.f;
#pragma unroll
        for (int c = 0; c < 4; c++) { vals[c] = __expf(vals[c] - m); ssum += vals[c]; }
#pragma unroll
        for (int o = 16; o > 0; o >>= 1) ssum += __shfl_xor_sync(0xffffffffu, ssum, o);
        float inv = 1.f / ssum;
        __half* hp = ath + ((size_t)bh * Sdim + r) * Sdim;
        __half* lp = atl + ((size_t)bh * Sdim + r) * Sdim;
#pragma unroll
        for (int c = 0; c < 4; c++) {
            float p = vals[c] * inv;
            __half hh_, ll_;
            split16(p, hh_, ll_);
            hp[lane + 32 * c] = hh_;
            lp[lane + 32 * c] = ll_;
        }
    }
}

// ==================== PV via fp16 3-pass mma (per bh) ======================
// ctx[i][d] = sum_j P[i][j] * v[j][d]
#define EVSK 136
#define EVA_B (128 * EVSK * 2)          /* 34816 B */
#define EVB_B (32 * EVSK * 2)           /* 8704 B */
#define EVM_BYTES (2 * EVA_B + 2 * EVB_B)  /* 87040 B */
__global__ __launch_bounds__(256) void pv_mma(
    const __half* __restrict__ ath, const __half* __restrict__ atl,
    const __half* __restrict__ qkvh, const __half* __restrict__ qkvl,
    float* __restrict__ ctx)
{
    extern __shared__ __half es[];
    const uint32_t s0 = smem_u32(es);
    const int bh = blockIdx.x;
    const int b = bh >> 3, h = bh & 7;
    const int tid = threadIdx.x, lane = tid & 31, wid = tid >> 5;

    // A copy (P hi/lo) via cp.async: rows = i
#pragma unroll
    for (int ss = 0; ss < 8; ++ss) {
        const int seg = tid + ss * 256;
        const int r = seg >> 4, sg = seg & 15;
        const size_t src = ((size_t)bh * Sdim + r) * Sdim + sg * 8;
        const uint32_t dst = s0 + (uint32_t)((r * EVSK + sg * 8) * 2);
        CP16(dst, ath + src);
        CP16(dst + EVA_B, atl + src);
    }
    // B transpose: vT[d][j] from v section of qkvh/qkvl
    {
        const uint32_t vth = 2 * EVA_B / 2;      // half-index of VTh base
#pragma unroll
        for (int e = 0; e < 8; ++e) {
            const int idx = e * 256 + tid;        // 0..2047, (j, dpair)
            const int j = idx >> 4, dp = (idx & 15) * 2;
            const size_t src = (size_t)(b * Sdim + j) * QKVS + 512 + h * HDim + dp;
            __half2 vh = *(const __half2*)(qkvh + src);
            __half2 vl = *(const __half2*)(qkvl + src);
            es[vth + dp * EVSK + j]       = __low2half(vh);
            es[vth + (dp + 1) * EVSK + j] = __high2half(vh);
            es[vth + EVB_B / 2 + dp * EVSK + j]       = __low2half(vl);
            es[vth + EVB_B / 2 + (dp + 1) * EVSK + j] = __high2half(vl);
        }
    }
    CPWAITALL();
    __syncthreads();

    const uint32_t a_loff = (uint32_t)(((lane & 15) * EVSK + ((lane >> 4) << 3)) * 2);
    const uint32_t b_loff = (uint32_t)((((lane & 7) + ((lane >> 4) << 3)) * EVSK
                                        + (((lane >> 3) & 1) << 3)) * 2);
    const uint32_t Ahb = s0 + (uint32_t)(wid * 16 * EVSK * 2) + a_loff;
    const uint32_t Alb = Ahb + EVA_B;
    const uint32_t Bhb = s0 + 2 * EVA_B + b_loff;
    const uint32_t Blb = Bhb + EVB_B;

    float acc[4][4];
#pragma unroll
    for (int nt = 0; nt < 4; ++nt)
#pragma unroll
        for (int e = 0; e < 4; ++e) acc[nt][e] = 0.f;

#pragma unroll
    for (int ks = 0; ks < 8; ++ks) {
        const uint32_t kb2 = ks * 32;
        uint32_t bhf[4][2], blf[4][2];
#pragma unroll
        for (int p = 0; p < 2; ++p) {
            uint32_t r0, r1, r2, r3;
            LDSM_X4(r0, r1, r2, r3, Bhb + (uint32_t)(p * 16 * EVSK * 2) + kb2);
            bhf[p*2][0] = r0; bhf[p*2][1] = r1;
            bhf[p*2+1][0] = r2; bhf[p*2+1][1] = r3;
            LDSM_X4(r0, r1, r2, r3, Blb + (uint32_t)(p * 16 * EVSK * 2) + kb2);
            blf[p*2][0] = r0; blf[p*2][1] = r1;
            blf[p*2+1][0] = r2; blf[p*2+1][1] = r3;
        }
        uint32_t ah[4], al[4];
        LDSM_X4(ah[0], ah[1], ah[2], ah[3], Ahb + kb2);
        LDSM_X4(al[0], al[1], al[2], al[3], Alb + kb2);
#pragma unroll
        for (int nt = 0; nt < 4; ++nt) {
            mma_f16(acc[nt][0], acc[nt][1], acc[nt][2], acc[nt][3],
                    ah[0], ah[1], ah[2], ah[3], bhf[nt][0], bhf[nt][1]);
            mma_f16(acc[nt][0], acc[nt][1], acc[nt][2], acc[nt][3],
                    al[0], al[1], al[2], al[3], bhf[nt][0], bhf[nt][1]);
            mma_f16(acc[nt][0], acc[nt][1], acc[nt][2], acc[nt][3],
                    ah[0], ah[1], ah[2], ah[3], blf[nt][0], blf[nt][1]);
        }
    }

    const int qr = lane >> 2, qc = lane & 3;
    const int row0 = wid * 16 + qr;
#pragma unroll
    for (int nt = 0; nt < 4; ++nt) {
        const int d0 = nt * 8 + qc * 2;
#pragma unroll
        for (int rr = 0; rr < 2; ++rr) {
            const int i = row0 + rr * 8;
            const size_t idx = (size_t)(b * Sdim + i) * Ddim + h * HDim + d0;
            *(float2*)(ctx + idx) =
                make_float2(acc[nt][rr * 2 + 0], acc[nt][rr * 2 + 1]);
        }
    }
}

// ==================== edge-value via fp16 3-pass mma (per i) ===============
__global__ __launch_bounds__(256) void ev_mma(
    const __half* __restrict__ ath, const __half* __restrict__ atl,
    const float* __restrict__ ev, const float* __restrict__ ctx,
    __half* __restrict__ ch, __half* __restrict__ cl)
{
    extern __shared__ __half es[];
    const uint32_t s0 = smem_u32(es);
    const int i = blockIdx.x, bh0 = blockIdx.y * 128;
    const int tid = threadIdx.x, lane = tid & 31, wid = tid >> 5;

#pragma unroll
    for (int ss = 0; ss < 8; ++ss) {
        const int seg = tid + ss * 256;
        const int r = seg >> 4, sg = seg & 15;
        const size_t src = ((size_t)(bh0 + r) * Sdim + i) * Sdim + sg * 8;
        const uint32_t dst = s0 + (uint32_t)((r * EVSK + sg * 8) * 2);
        CP16(dst, ath + src);
        CP16(dst + EVA_B, atl + src);
    }
    {
        const float* evp = ev + (size_t)i * Sdim * HDim;
        const uint32_t vth = 2 * EVA_B / 2;
#pragma unroll
        for (int e = 0; e < 16; ++e) {
            const int idx = e * 256 + tid;
            const int d = idx & 31, jj = idx >> 5;
            float v = evp[idx];
            __half h, l;
            split16(v, h, l);
            es[vth + d * EVSK + jj] = h;
            es[vth + EVB_B / 2 + d * EVSK + jj] = l;
        }
    }
    CPWAITALL();
    __syncthreads();

    const uint32_t a_loff = (uint32_t)(((lane & 15) * EVSK + ((lane >> 4) << 3)) * 2);
    const uint32_t b_loff = (uint32_t)((((lane & 7) + ((lane >> 4) << 3)) * EVSK
                                        + (((lane >> 3) & 1) << 3)) * 2);
    const uint32_t Ahb = s0 + (uint32_t)(wid * 16 * EVSK * 2) + a_loff;
    const uint32_t Alb = Ahb + EVA_B;
    const uint32_t Bhb = s0 + 2 * EVA_B + b_loff;
    const uint32_t Blb = Bhb + EVB_B;

    float acc[4][4];
#pragma unroll
    for (int nt = 0; nt < 4; ++nt)
#pragma unroll
        for (int e = 0; e < 4; ++e) acc[nt][e] = 0.f;

#pragma unroll
    for (int ks = 0; ks < 8; ++ks) {
        const uint32_t kb2 = ks * 32;
        uint32_t bhf[4][2], blf[4][2];
#pragma unroll
        for (int p = 0; p < 2; ++p) {
            uint32_t r0, r1, r2, r3;
            LDSM_X4(r0, r1, r2, r3, Bhb + (uint32_t)(p * 16 * EVSK * 2) + kb2);
            bhf[p*2][0] = r0; bhf[p*2][1] = r1;
            bhf[p*2+1][0] = r2; bhf[p*2+1][1] = r3;
            LDSM_X4(r0, r1, r2, r3, Blb + (uint32_t)(p * 16 * EVSK * 2) + kb2);
            blf[p*2][0] = r0; blf[p*2][1] = r1;
            blf[p*2+1][0] = r2; blf[p*2+1][1] = r3;
        }
        uint32_t ah[4], al[4];
        LDSM_X4(ah[0], ah[1], ah[2], ah[3], Ahb + kb2);
        LDSM_X4(al[0], al[1], al[2], al[3], Alb + kb2);
#pragma unroll
        for (int nt = 0; nt < 4; ++nt) {
            mma_f16(acc[nt][0], acc[nt][1], acc[nt][2], acc[nt][3],
                    ah[0], ah[1], ah[2], ah[3], bhf[nt][0], bhf[nt][1]);
            mma_f16(acc[nt][0], acc[nt][1], acc[nt][2], acc[nt][3],
                    al[0], al[1], al[2], al[3], bhf[nt][0], bhf[nt][1]);
            mma_f16(acc[nt][0], acc[nt][1], acc[nt][2], acc[nt][3],
                    ah[0], ah[1], ah[2], ah[3], blf[nt][0], blf[nt][1]);
        }
    }

    const int qr = lane >> 2, qc = lane & 3;
    const int row0 = wid * 16 + qr;
#pragma unroll
    for (int nt = 0; nt < 4; ++nt) {
        const int d0 = nt * 8 + qc * 2;
#pragma unroll
        for (int rr = 0; rr < 2; ++rr) {
            const int bh = bh0 + row0 + rr * 8;
            const int b = bh >> 3, h = bh & 7;
            const size_t idx = (size_t)(b * Sdim + i) * Ddim + h * HDim + d0;
            float2 cur = *(const float2*)(ctx + idx);
            float v0 = cur.x + acc[nt][rr * 2 + 0];
            float v1 = cur.y + acc[nt][rr * 2 + 1];
            __half h0, l0, h1, l1;
            split16(v0, h0, l0); split16(v1, h1, l1);
            *(__half2*)(ch + idx) = __halves2half2(h0, h1);
            *(__half2*)(cl + idx) = __halves2half2(l0, l1);
        }
    }
}

// ============ fused weight transpose -> fp16 [N][K] ========================
__global__ __launch_bounds__(256) void tr_all(
    const float* __restrict__ Wq, const float* __restrict__ Wk,
    const float* __restrict__ Wv, const float* __restrict__ Wo,
    const float* __restrict__ W1, const float* __restrict__ W2,
    __half* __restrict__ wqkvT, __half* __restrict__ woT,
    __half* __restrict__ w1T, __half* __restrict__ w2T)
{
    __shared__ float t[32][33];
    const int tb = blockIdx.x;
    const float* src; __half* dst; int K, N, kx, nx;
    if (tb < 768) {
        int w = tb / 256, r = tb % 256, l = r / 64, q = r % 64;
        src = (w == 0 ? Wq : (w == 1 ? Wk : Wv)) + (size_t)l * 65536;
        dst = wqkvT + (size_t)l * 196608 + (size_t)w * 65536;
        K = 256; N = 256; kx = (q / 8) * 32; nx = (q % 8) * 32;
    } else if (tb < 1024) {
        int r = tb - 768, l = r / 64, q = r % 64;
        src = Wo + (size_t)l * 65536; dst = woT + (size_t)l * 65536;
        K = 256; N = 256; kx = (q / 8) * 32; nx = (q % 8) * 32;
    } else if (tb < 3072) {
        int r = tb - 1024, l = r / 512, q = r % 512;
        src = W1 + (size_t)l * 524288; dst = w1T + (size_t)l * 524288;
        K = 256; N = 2048; kx = (q / 64) * 32; nx = (q % 64) * 32;
    } else {
        int r = tb - 3072, l = r / 512, q = r % 512;
        src = W2 + (size_t)l * 524288; dst = w2T + (size_t)l * 524288;
        K = 2048; N = 256; kx = (q / 8) * 32; nx = (q % 8) * 32;
    }
    const int x = threadIdx.x & 31, y = threadIdx.x >> 5;
#pragma unroll
    for (int yy = y; yy < 32; yy += 8)
        t[yy][x] = src[(size_t)(kx + yy) * N + nx + x];
    __syncthreads();
#pragma unroll
    for (int yy = y; yy < 32; yy += 8)
        dst[(size_t)(nx + yy) * K + kx + x] = __float2half_rn(t[x][yy]);
}

// ---- prep -----------------------------------------------------------------
__global__ void prep_kernel(const float* __restrict__ facts, float* __restrict__ x,
                            __half* __restrict__ xh, __half* __restrict__ xl,
                            const float* __restrict__ ekey,
                            __half* __restrict__ ekh, __half* __restrict__ ekl,
                            const float* __restrict__ bq, const float* __restrict__ bk,
                            const float* __restrict__ bv, float* __restrict__ bqkv)
{
    size_t idx = (size_t)blockIdx.x * 256 + threadIdx.x;
    float v = facts[idx];
    x[idx] = v;
    __half h, l;
    split16(v, h, l);
    xh[idx] = h; xl[idx] = l;
    if (idx < EKN) {
        float e = ekey[idx];
        __half eh, el;
        split16(e, eh, el);
        ekh[idx] = eh; ekl[idx] = el;
    }
    if (idx < Ldim * QKVS) {
        int li = (int)(idx / QKVS), ji = (int)(idx % QKVS);
        float bvv;
        if (ji < 256)      bvv = bq[li * 256 + ji];
        else if (ji < 512) bvv = bk[li * 256 + ji - 256];
        else               bvv = bv[li * 256 + ji - 512];
        bqkv[idx] = bvv;
    }
}

// ---------------- layer norm (+ hi/lo split out) ---------------------------
__global__ __launch_bounds__(256) void ln_kernel(
    const float* __restrict__ in1, const float* __restrict__ in2, float alpha,
    const float* __restrict__ g, const float* __restrict__ b,
    float* __restrict__ out, __half* __restrict__ outh, __half* __restrict__ outl)
{
    const int warp = threadIdx.x >> 5, lane = threadIdx.x & 31;
    const int row = blockIdx.x * 8 + warp;
    const float* p1 = in1 + (size_t)row * Ddim;
    float v[8];
#pragma unroll
    for (int c = 0; c < 8; c++) {
        int col = lane + 32 * c;
        float t = alpha * p1[col];
        if (in2) t += in2[(size_t)row * Ddim + col];
        v[c] = t;
    }
    float s = 0.f;
#pragma unroll
    for (int c = 0; c < 8; c++) s += v[c];
#pragma unroll
    for (int o = 16; o > 0; o >>= 1) s += __shfl_xor_sync(0xffffffffu, s, o);
    float mu = s * (1.f / Ddim);
    float var = 0.f;
#pragma unroll
    for (int c = 0; c < 8; c++) { float d = v[c] - mu; var += d * d; }
#pragma unroll
    for (int o = 16; o > 0; o >>= 1) var += __shfl_xor_sync(0xffffffffu, var, o);
    var *= (1.f / Ddim);
    float inv = rsqrtf(var + 1e-5f);
#pragma unroll
    for (int c = 0; c < 8; c++) {
        int col = lane + 32 * c;
        float r = (v[c] - mu) * inv * g[col] + b[col];
        out[(size_t)row * Ddim + col] = r;
        __half h, l;
        split16(r, h, l);
        outh[(size_t)row * Ddim + col] = h;
        outl[(size_t)row * Ddim + col] = l;
    }
}

__global__ void out_transpose(const float* __restrict__ x, float* __restrict__ out)
{
    size_t idx = (size_t)blockIdx.x * 256 + threadIdx.x;
    int d = (int)(idx % Ddim);
    size_t sb = idx / Ddim;
    int bcol = (int)(sb % Bdim);
    int s = (int)(sb / Bdim);
    out[idx] = x[((size_t)bcol * Sdim + s) * Ddim + d];
}

// ---------------- host -----------------------------------------------------
extern "C" void kernel_launch(void* const* d_in, const int* in_sizes, int n_in,
                              void* d_out, int out_size)
{
    const float* facts = (const float*)d_in[0];
    const float* ekey  = (const float*)d_in[1];
    const float* evalp = (const float*)d_in[2];
    const unsigned char* mask = (const unsigned char*)d_in[3];
    const float *Wq, *Wk, *Wv, *Wo, *bq, *bk, *bv, *bo;
    if (in_sizes[5] == Ldim * Ddim) {
        Wq = (const float*)d_in[4];  bq = (const float*)d_in[5];
        Wk = (const float*)d_in[6];  bk = (const float*)d_in[7];
        Wv = (const float*)d_in[8];  bv = (const float*)d_in[9];
        Wo = (const float*)d_in[10]; bo = (const float*)d_in[11];
    } else {
        Wq = (const float*)d_in[4];  Wk = (const float*)d_in[5];
        Wv = (const float*)d_in[6];  Wo = (const float*)d_in[7];
        bq = (const float*)d_in[8];  bk = (const float*)d_in[9];
        bv = (const float*)d_in[10]; bo = (const float*)d_in[11];
    }
    const float* ln1g = (const float*)d_in[12];
    const float* ln1b = (const float*)d_in[13];
    const float* W1   = (const float*)d_in[14];
    const float* b1   = (const float*)d_in[15];
    const float* W2   = (const float*)d_in[16];
    const float* b2   = (const float*)d_in[17];
    const float* ln2g = (const float*)d_in[18];
    const float* ln2b = (const float*)d_in[19];

    float *x, *ctx, *tmp, *eb, *bqkvp;
    __half *ath, *atl, *qkvh, *qkvl;
    __half *xh, *xl, *ch, *cl, *ffh, *ffl, *ekh, *ekl;
    __half *wqkvT, *woT, *w1T, *w2T;
    cudaGetSymbolAddress((void**)&x,    g_x);
    cudaGetSymbolAddress((void**)&ctx,  g_ctx);
    cudaGetSymbolAddress((void**)&tmp,  g_tmp);
    cudaGetSymbolAddress((void**)&eb,   g_eb);
    cudaGetSymbolAddress((void**)&ath,  g_ath);
    cudaGetSymbolAddress((void**)&atl,  g_atl);
    cudaGetSymbolAddress((void**)&qkvh, g_qkvh);
    cudaGetSymbolAddress((void**)&qkvl, g_qkvl);
    cudaGetSymbolAddress((void**)&xh,   g_xh);
    cudaGetSymbolAddress((void**)&xl,   g_xl);
    cudaGetSymbolAddress((void**)&ch,   g_ch);
    cudaGetSymbolAddress((void**)&cl,   g_cl);
    cudaGetSymbolAddress((void**)&ffh,  g_ffh);
    cudaGetSymbolAddress((void**)&ffl,  g_ffl);
    cudaGetSymbolAddress((void**)&ekh,  g_ekh);
    cudaGetSymbolAddress((void**)&ekl,  g_ekl);
    cudaGetSymbolAddress((void**)&wqkvT, g_wqkvT);
    cudaGetSymbolAddress((void**)&woT,  g_woT);
    cudaGetSymbolAddress((void**)&w1T,  g_w1T);
    cudaGetSymbolAddress((void**)&w2T,  g_w2T);
    cudaGetSymbolAddress((void**)&bqkvp, g_bqkv);

    cudaFuncSetAttribute(mma_gemm<false,false>, cudaFuncAttributeMaxDynamicSharedMemorySize, GSMB);
    cudaFuncSetAttribute(mma_gemm<false,true>,  cudaFuncAttributeMaxDynamicSharedMemorySize, GSMB);
    cudaFuncSetAttribute(mma_gemm<true,true>,   cudaFuncAttributeMaxDynamicSharedMemorySize, GSMB);
    cudaFuncSetAttribute(attn_mma, cudaFuncAttributeMaxDynamicSharedMemorySize, ATTM_BYTES);
    cudaFuncSetAttribute(pv_mma,   cudaFuncAttributeMaxDynamicSharedMemorySize, EVM_BYTES);
    cudaFuncSetAttribute(ev_mma,   cudaFuncAttributeMaxDynamicSharedMemorySize, EVM_BYTES);

    // launches: 0 tr_all, 1 prep, 2 QKV, 3 ebias_mma (ncu target)
    tr_all<<<5120, 256>>>(Wq, Wk, Wv, Wo, W1, W2, wqkvT, woT, w1T, w2T);        // 0
    prep_kernel<<<NR * Ddim / 256, 256>>>(facts, x, xh, xl,
                                          ekey, ekh, ekl, bq, bk, bv, bqkvp);   // 1

    for (int l = 0; l < Ldim; l++) {
        mma_gemm<false,true><<<dim3(QKVS / 128, NR / 128), 256, GSMB>>>(
            xh, xl, wqkvT + (size_t)l * 3 * Ddim * Ddim, bqkvp + l * QKVS,
            nullptr, qkvh, qkvl, NR, QKVS, Ddim);                               // 2 (l=0)

        ebias_mma<<<dim3(Sdim, BHdim / 128), 256>>>(qkvh, qkvl, ekh, ekl, eb);  // 3 (l=0)
        attn_mma<<<BHdim, 256, ATTM_BYTES>>>(qkvh, qkvl, eb, mask, ath, atl);
        pv_mma<<<BHdim, 256, EVM_BYTES>>>(ath, atl, qkvh, qkvl, ctx);
        ev_mma<<<dim3(Sdim, BHdim / 128), 256, EVM_BYTES>>>(ath, atl, evalp,
                                                            ctx, ch, cl);

        mma_gemm<false,false><<<dim3(Ddim / 128, NR / 128), 256, GSMB>>>(
            ch, cl, woT + (size_t)l * Ddim * Ddim, bo + l * Ddim,
            tmp, nullptr, nullptr, NR, Ddim, Ddim);
        ln_kernel<<<NR / 8, 256>>>(tmp, x, 1.f, ln1g + l * Ddim, ln1b + l * Ddim,
                                   x, xh, xl);

        mma_gemm<true,true><<<dim3(Fdim / 128, NR / 128), 256, GSMB>>>(
            xh, xl, w1T + (size_t)l * Fdim * Ddim, b1 + l * Fdim,
            nullptr, ffh, ffl, NR, Fdim, Ddim);
        mma_gemm<false,false><<<dim3(Ddim / 128, NR / 128), 256, GSMB>>>(
            ffh, ffl, w2T + (size_t)l * Ddim * Fdim, b2 + l * Ddim,
            tmp, nullptr, nullptr, NR, Ddim, Fdim);
        ln_kernel<<<NR / 8, 256>>>(tmp, nullptr, 2.f, ln2g + l * Ddim, ln2b + l * Ddim,
                                   x, xh, xl);
    }

    out_transpose<<<NR * Ddim / 256, 256>>>(x, (float*)d_out);
}

// round 16
// speedup vs baseline: 1.2327x; 1.0025x over previous
#include <cuda_runtime.h>
#include <cuda_fp16.h>
#include <cstdint>
#include <math.h>

#define Bdim 128
#define Sdim 128
#define Ddim 256
#define Hdim 8
#define HDim 32
#define Fdim 2048
#define Ldim 4
#define BHdim (Bdim*Hdim)     /* 1024 */
#define NR (Bdim*Sdim)        /* 16384 rows */
#define QKVS 768
#define EKN (Sdim*Sdim*HDim)  /* 524288 */

// ---------------- scratch (device globals) ---------------------------------
__device__ float g_x[NR*Ddim];
__device__ float g_ctx[NR*Ddim];
__device__ float g_tmp[NR*Ddim];
__device__ float g_eb[(size_t)BHdim*Sdim*Sdim];   // [bh][j][i]
__device__ __half g_ath[(size_t)BHdim*Sdim*Sdim]; // P hi [bh][i][j]
__device__ __half g_atl[(size_t)BHdim*Sdim*Sdim]; // P lo
__device__ __half g_qkvh[(size_t)NR*QKVS];
__device__ __half g_qkvl[(size_t)NR*QKVS];
__device__ __half g_xh[NR*Ddim];
__device__ __half g_xl[NR*Ddim];
__device__ __half g_ch[NR*Ddim];
__device__ __half g_cl[NR*Ddim];
__device__ __half g_ffh[(size_t)NR*Fdim];
__device__ __half g_ffl[(size_t)NR*Fdim];
__device__ __half g_ekh[EKN];
__device__ __half g_ekl[EKN];
__device__ __half g_wqkvT[(size_t)Ldim*3*Ddim*Ddim];
__device__ __half g_woT[(size_t)Ldim*Ddim*Ddim];
__device__ __half g_w1T[(size_t)Ldim*Fdim*Ddim];
__device__ __half g_w2T[(size_t)Ldim*Ddim*Fdim];
__device__ float g_bqkv[Ldim*QKVS];

// ==================== helpers =============================================
__device__ __forceinline__ uint32_t smem_u32(const void* p) {
    uint32_t a;
    asm("{ .reg .u64 t; cvta.to.shared.u64 t, %1; cvt.u32.u64 %0, t; }"
        : "=r"(a) : "l"(p));
    return a;
}
#define LDSM_X4(R0,R1,R2,R3,ADDR) \
    asm volatile("ldmatrix.sync.aligned.m8n8.x4.shared.b16 {%0,%1,%2,%3}, [%4];" \
        : "=r"(R0), "=r"(R1), "=r"(R2), "=r"(R3) : "r"(ADDR) : "memory")
#define CP16(dst, src) \
    asm volatile("cp.async.cg.shared.global [%0], [%1], 16;" :: "r"(dst), "l"(src))
#define CPCOMMIT() asm volatile("cp.async.commit_group;" ::: "memory")
#define CPWAIT1()  asm volatile("cp.async.wait_group 1;" ::: "memory")
#define CPWAIT0()  asm volatile("cp.async.wait_group 0;" ::: "memory")
#define CPWAITALL() asm volatile("cp.async.wait_all;" ::: "memory")

__device__ __forceinline__ void mma_f16(
    float& c0, float& c1, float& c2, float& c3,
    uint32_t a0, uint32_t a1, uint32_t a2, uint32_t a3,
    uint32_t b0, uint32_t b1)
{
    asm volatile(
        "mma.sync.aligned.m16n8k16.row.col.f32.f16.f16.f32 "
        "{%0,%1,%2,%3}, {%4,%5,%6,%7}, {%8,%9}, {%0,%1,%2,%3};"
        : "+f"(c0), "+f"(c1), "+f"(c2), "+f"(c3)
        : "r"(a0), "r"(a1), "r"(a2), "r"(a3), "r"(b0), "r"(b1));
}

__device__ __forceinline__ void split16(float v, __half& h, __half& l) {
    h = __float2half_rn(v);
    l = __float2half_rn(v - __half2float(h));
}

// ==================== fp16 split-A mma GEMM (cp.async, 3-stage) ============
#define CH 32
#define SKH 40
#define TILEB (128 * SKH * 2)
#define CHUNKB (3 * TILEB)
#define NSTG 3
#define GSMB (NSTG * CHUNKB)            /* 92160 B */

template<bool RELU, bool OUTH>
__global__ __launch_bounds__(256, 2) void mma_gemm(
    const __half* __restrict__ Ah, const __half* __restrict__ Al,
    const __half* __restrict__ BT, const float* __restrict__ bias,
    float* __restrict__ C, __half* __restrict__ Ch, __half* __restrict__ Cl,
    int M, int N, int K)
{
    extern __shared__ __half sh[];
    const uint32_t s0 = smem_u32(sh);
    const int tid = threadIdx.x;
    const int lane = tid & 31, wid = tid >> 5;
    const int wm = (wid >> 1) * 32, wn = (wid & 1) * 64;
    const int m0 = blockIdx.y * 128, n0 = blockIdx.x * 128;
    const int nch = K / CH;
    const int srow = tid >> 1, shalf = tid & 1;
    const int rev = wid & 1;

    const __half* Abase = Ah + (size_t)(m0 + srow) * K + shalf * 16;
    const __half* Lbase = Al + (size_t)(m0 + srow) * K + shalf * 16;
    const __half* Bbase = BT + (size_t)(n0 + srow) * K + shalf * 16;
    const uint32_t sdst = (uint32_t)((srow * SKH + shalf * 16) * 2);

    const uint32_t a_loff = (uint32_t)(((lane & 15) * SKH + ((lane >> 4) << 3)) * 2);
    const uint32_t b_loff = (uint32_t)((((lane & 7) + ((lane >> 4) << 3)) * SKH
                                        + (((lane >> 3) & 1) << 3)) * 2);

    auto issue = [&](int c) {
        const uint32_t base = s0 + (uint32_t)((c % NSTG) * CHUNKB) + sdst;
        const __half* ap = Abase + c * CH;
        const __half* lp = Lbase + c * CH;
        const __half* bp = Bbase + c * CH;
        CP16(base,              ap);     CP16(base + 16,              ap + 8);
        CP16(base + TILEB,      lp);     CP16(base + TILEB + 16,      lp + 8);
        CP16(base + 2 * TILEB,  bp);     CP16(base + 2 * TILEB + 16,  bp + 8);
        CPCOMMIT();
    };

    float acc[2][8][4];
#pragma unroll
    for (int mt = 0; mt < 2; ++mt)
#pragma unroll
        for (int nt = 0; nt < 8; ++nt)
#pragma unroll
            for (int e = 0; e < 4; ++e) acc[mt][nt][e] = 0.f;

    issue(0);
    if (nch > 1) issue(1);

    for (int c = 0; c < nch; ++c) {
        if (c + 1 < nch) { CPWAIT1(); } else { CPWAIT0(); }
        __syncthreads();
        if (c + 2 < nch) issue(c + 2);

        const uint32_t stg = s0 + (uint32_t)((c % NSTG) * CHUNKB);
        const uint32_t ahb = stg + (uint32_t)(wm * SKH * 2) + a_loff;
        const uint32_t alb = ahb + TILEB;
        const uint32_t bhb = stg + 2 * TILEB + (uint32_t)(wn * SKH * 2) + b_loff;
#pragma unroll
        for (int s0i = 0; s0i < 2; ++s0i) {
            const int s = rev ? (1 - s0i) : s0i;
            const uint32_t kb2 = s * 32;
            uint32_t bfr[8][2];
#pragma unroll
            for (int p = 0; p < 4; ++p) {
                uint32_t r0, r1, r2, r3;
                LDSM_X4(r0, r1, r2, r3,
                        bhb + (uint32_t)(p * 16 * SKH * 2) + kb2);
                bfr[p*2][0] = r0; bfr[p*2][1] = r1;
                bfr[p*2+1][0] = r2; bfr[p*2+1][1] = r3;
            }
            uint32_t ah[2][4], al[2][4];
#pragma unroll
            for (int mt = 0; mt < 2; ++mt) {
                LDSM_X4(ah[mt][0], ah[mt][1], ah[mt][2], ah[mt][3],
                        ahb + (uint32_t)(mt * 16 * SKH * 2) + kb2);
                LDSM_X4(al[mt][0], al[mt][1], al[mt][2], al[mt][3],
                        alb + (uint32_t)(mt * 16 * SKH * 2) + kb2);
            }
#pragma unroll
            for (int nt = 0; nt < 8; ++nt)
#pragma unroll
                for (int mt = 0; mt < 2; ++mt)
                    mma_f16(acc[mt][nt][0], acc[mt][nt][1],
                            acc[mt][nt][2], acc[mt][nt][3],
                            ah[mt][0], ah[mt][1], ah[mt][2], ah[mt][3],
                            bfr[nt][0], bfr[nt][1]);
#pragma unroll
            for (int nt = 0; nt < 8; ++nt)
#pragma unroll
                for (int mt = 0; mt < 2; ++mt)
                    mma_f16(acc[mt][nt][0], acc[mt][nt][1],
                            acc[mt][nt][2], acc[mt][nt][3],
                            al[mt][0], al[mt][1], al[mt][2], al[mt][3],
                            bfr[nt][0], bfr[nt][1]);
        }
    }

    const int qr = lane >> 2, qc = lane & 3;
#pragma unroll
    for (int mt = 0; mt < 2; ++mt) {
        const int r = m0 + wm + mt * 16 + qr;
#pragma unroll
        for (int nt = 0; nt < 8; ++nt) {
            const int col = n0 + wn + nt * 8 + qc * 2;
            float b0 = bias[col], b1 = bias[col + 1];
            float v00 = acc[mt][nt][0] + b0, v01 = acc[mt][nt][1] + b1;
            float v10 = acc[mt][nt][2] + b0, v11 = acc[mt][nt][3] + b1;
            if (RELU) {
                v00 = fmaxf(v00, 0.f); v01 = fmaxf(v01, 0.f);
                v10 = fmaxf(v10, 0.f); v11 = fmaxf(v11, 0.f);
            }
            if (OUTH) {
                __half h00, l00, h01, l01, h10, l10, h11, l11;
                split16(v00, h00, l00); split16(v01, h01, l01);
                split16(v10, h10, l10); split16(v11, h11, l11);
                *(__half2*)(Ch + (size_t)r * N + col)       = __halves2half2(h00, h01);
                *(__half2*)(Cl + (size_t)r * N + col)       = __halves2half2(l00, l01);
                *(__half2*)(Ch + (size_t)(r + 8) * N + col) = __halves2half2(h10, h11);
                *(__half2*)(Cl + (size_t)(r + 8) * N + col) = __halves2half2(l10, l11);
            } else {
                *(float2*)(C + (size_t)r * N + col)       = make_float2(v00, v01);
                *(float2*)(C + (size_t)(r + 8) * N + col) = make_float2(v10, v11);
            }
        }
    }
}

// ==================== ebias via fp16 3-pass mma ============================
#define EBT 5120
__global__ __launch_bounds__(256) void ebias_mma(
    const __half* __restrict__ qkvh, const __half* __restrict__ qkvl,
    const __half* __restrict__ ekh, const __half* __restrict__ ekl,
    float* __restrict__ eb)
{
    __shared__ __half sm[4 * EBT];     // Ah Al Bh Bl
    const uint32_t s0 = smem_u32(sm);
    const int j = blockIdx.x;
    const int bh0 = blockIdx.y * 128;
    const int tid = threadIdx.x;
    const int lane = tid & 31, wid = tid >> 5;
    const int wm = (wid >> 1) * 32, wn = (wid & 1) * 64;

    {
        const int t = tid >> 6, u = tid & 63;
#pragma unroll
        for (int rr = 0; rr < 2; ++rr) {
            const int r = u + rr * 64;
            const __half* srcb;
            size_t soff;
            if (t < 2) {
                const int bh = bh0 + r;
                const int b = bh >> 3, h = bh & 7;
                soff = (size_t)(b * Sdim + j) * QKVS + h * HDim;   // q section
                srcb = (t == 0 ? qkvh : qkvl);
            } else {
                soff = ((size_t)j * Sdim + r) * HDim;
                srcb = (t == 2 ? ekh : ekl);
            }
            const uint32_t dst = s0 + (uint32_t)((t * EBT + r * SKH) * 2);
#pragma unroll
            for (int sg = 0; sg < 4; ++sg)
                CP16(dst + sg * 16, srcb + soff + sg * 8);
        }
    }
    CPWAITALL();
    __syncthreads();

    const uint32_t a_loff = (uint32_t)(((lane & 15) * SKH + ((lane >> 4) << 3)) * 2);
    const uint32_t b_loff = (uint32_t)((((lane & 7) + ((lane >> 4) << 3)) * SKH
                                        + (((lane >> 3) & 1) << 3)) * 2);
    const uint32_t Ahb = s0 + (uint32_t)(wm * SKH * 2) + a_loff;
    const uint32_t Alb = Ahb + EBT * 2;
    const uint32_t Bhb = s0 + (uint32_t)(2 * EBT * 2) + (uint32_t)(wn * SKH * 2) + b_loff;
    const uint32_t Blb = Bhb + EBT * 2;

    float acc[2][8][4];
#pragma unroll
    for (int mt = 0; mt < 2; ++mt)
#pragma unroll
        for (int nt = 0; nt < 8; ++nt)
#pragma unroll
            for (int e = 0; e < 4; ++e) acc[mt][nt][e] = 0.f;

#pragma unroll
    for (int ss = 0; ss < 2; ++ss) {
        const uint32_t kb2 = ss * 32;
        uint32_t bhf[8][2], blf[8][2];
#pragma unroll
        for (int p = 0; p < 4; ++p) {
            uint32_t r0, r1, r2, r3;
            LDSM_X4(r0, r1, r2, r3, Bhb + (uint32_t)(p * 16 * SKH * 2) + kb2);
            bhf[p*2][0] = r0; bhf[p*2][1] = r1;
            bhf[p*2+1][0] = r2; bhf[p*2+1][1] = r3;
            LDSM_X4(r0, r1, r2, r3, Blb + (uint32_t)(p * 16 * SKH * 2) + kb2);
            blf[p*2][0] = r0; blf[p*2][1] = r1;
            blf[p*2+1][0] = r2; blf[p*2+1][1] = r3;
        }
        uint32_t ah[2][4], al[2][4];
#pragma unroll
        for (int mt = 0; mt < 2; ++mt) {
            LDSM_X4(ah[mt][0], ah[mt][1], ah[mt][2], ah[mt][3],
                    Ahb + (uint32_t)(mt * 16 * SKH * 2) + kb2);
            LDSM_X4(al[mt][0], al[mt][1], al[mt][2], al[mt][3],
                    Alb + (uint32_t)(mt * 16 * SKH * 2) + kb2);
        }
#pragma unroll
        for (int nt = 0; nt < 8; ++nt)
#pragma unroll
            for (int mt = 0; mt < 2; ++mt) {
                mma_f16(acc[mt][nt][0], acc[mt][nt][1], acc[mt][nt][2], acc[mt][nt][3],
                        ah[mt][0], ah[mt][1], ah[mt][2], ah[mt][3],
                        bhf[nt][0], bhf[nt][1]);
                mma_f16(acc[mt][nt][0], acc[mt][nt][1], acc[mt][nt][2], acc[mt][nt][3],
                        al[mt][0], al[mt][1], al[mt][2], al[mt][3],
                        bhf[nt][0], bhf[nt][1]);
                mma_f16(acc[mt][nt][0], acc[mt][nt][1], acc[mt][nt][2], acc[mt][nt][3],
                        ah[mt][0], ah[mt][1], ah[mt][2], ah[mt][3],
                        blf[nt][0], blf[nt][1]);
            }
    }

    const int qr = lane >> 2, qc = lane & 3;
#pragma unroll
    for (int mt = 0; mt < 2; ++mt) {
        const int row = wm + mt * 16 + qr;
#pragma unroll
        for (int nt = 0; nt < 8; ++nt) {
            const int col = wn + nt * 8 + qc * 2;
            float* p0 = eb + ((size_t)(bh0 + row) * Sdim + j) * Sdim + col;
            float* p1 = eb + ((size_t)(bh0 + row + 8) * Sdim + j) * Sdim + col;
            *(float2*)p0 = make_float2(acc[mt][nt][0], acc[mt][nt][1]);
            *(float2*)p1 = make_float2(acc[mt][nt][2], acc[mt][nt][3]);
        }
    }
}

// ==================== attention scores + softmax (QK via mma) ==============
// smem UNION: phase A uses QK tiles (40960 B); phase B reuses as Sc (66048 B)
#define ATTM_BYTES (128 * 129 * 4)      /* 66048 >= 4*EBT*2 = 40960 */
__global__ __launch_bounds__(256, 2) void attn_mma(
    const __half* __restrict__ qkvh, const __half* __restrict__ qkvl,
    const float* __restrict__ eb, const unsigned char* __restrict__ mask,
    __half* __restrict__ ath, __half* __restrict__ atl)
{
    extern __shared__ char asm_[];
    __half* hq = (__half*)asm_;                    // phase A: Qh Ql Kh Kl
    float (*Sc)[129] = (float(*)[129])asm_;        // phase B: scores (union)
    const uint32_t s0 = smem_u32(hq);
    const int bh = blockIdx.x;
    const int b = bh >> 3, h = bh & 7;
    const int tid = threadIdx.x;
    const int lane = tid & 31, wid = tid >> 5;
    const int wm = (wid >> 1) * 32, wn = (wid & 1) * 64;

    // ---- phase A: load QK tiles, mma into registers ----
    {
        const int t = tid >> 6, u = tid & 63;
        const __half* srcb = (t == 0 || t == 2) ? qkvh : qkvl;
        const size_t sec = (t < 2) ? 0 : 256;
#pragma unroll
        for (int rr = 0; rr < 2; ++rr) {
            const int r = u + rr * 64;
            const size_t soff = (size_t)(b * Sdim + r) * QKVS + sec + h * HDim;
            const uint32_t dst = s0 + (uint32_t)((t * EBT + r * SKH) * 2);
#pragma unroll
            for (int sg = 0; sg < 4; ++sg)
                CP16(dst + sg * 16, srcb + soff + sg * 8);
        }
    }
    CPWAITALL();
    __syncthreads();

    const uint32_t a_loff = (uint32_t)(((lane & 15) * SKH + ((lane >> 4) << 3)) * 2);
    const uint32_t b_loff = (uint32_t)((((lane & 7) + ((lane >> 4) << 3)) * SKH
                                        + (((lane >> 3) & 1) << 3)) * 2);
    const uint32_t Ahb = s0 + (uint32_t)(wm * SKH * 2) + a_loff;
    const uint32_t Alb = Ahb + EBT * 2;
    const uint32_t Bhb = s0 + (uint32_t)(2 * EBT * 2) + (uint32_t)(wn * SKH * 2) + b_loff;
    const uint32_t Blb = Bhb + EBT * 2;

    float acc[2][8][4];
#pragma unroll
    for (int mt = 0; mt < 2; ++mt)
#pragma unroll
        for (int nt = 0; nt < 8; ++nt)
#pragma unroll
            for (int e = 0; e < 4; ++e) acc[mt][nt][e] = 0.f;

#pragma unroll
    for (int ss = 0; ss < 2; ++ss) {
        const uint32_t kb2 = ss * 32;
        uint32_t bhf[8][2], blf[8][2];
#pragma unroll
        for (int p = 0; p < 4; ++p) {
            uint32_t r0, r1, r2, r3;
            LDSM_X4(r0, r1, r2, r3, Bhb + (uint32_t)(p * 16 * SKH * 2) + kb2);
            bhf[p*2][0] = r0; bhf[p*2][1] = r1;
            bhf[p*2+1][0] = r2; bhf[p*2+1][1] = r3;
            LDSM_X4(r0, r1, r2, r3, Blb + (uint32_t)(p * 16 * SKH * 2) + kb2);
            blf[p*2][0] = r0; blf[p*2][1] = r1;
            blf[p*2+1][0] = r2; blf[p*2+1][1] = r3;
        }
        uint32_t ah[2][4], al[2][4];
#pragma unroll
        for (int mt = 0; mt < 2; ++mt) {
            LDSM_X4(ah[mt][0], ah[mt][1], ah[mt][2], ah[mt][3],
                    Ahb + (uint32_t)(mt * 16 * SKH * 2) + kb2);
            LDSM_X4(al[mt][0], al[mt][1], al[mt][2], al[mt][3],
                    Alb + (uint32_t)(mt * 16 * SKH * 2) + kb2);
        }
#pragma unroll
        for (int nt = 0; nt < 8; ++nt)
#pragma unroll
            for (int mt = 0; mt < 2; ++mt) {
                mma_f16(acc[mt][nt][0], acc[mt][nt][1], acc[mt][nt][2], acc[mt][nt][3],
                        ah[mt][0], ah[mt][1], ah[mt][2], ah[mt][3],
                        bhf[nt][0], bhf[nt][1]);
                mma_f16(acc[mt][nt][0], acc[mt][nt][1], acc[mt][nt][2], acc[mt][nt][3],
                        al[mt][0], al[mt][1], al[mt][2], al[mt][3],
                        bhf[nt][0], bhf[nt][1]);
                mma_f16(acc[mt][nt][0], acc[mt][nt][1], acc[mt][nt][2], acc[mt][nt][3],
                        ah[mt][0], ah[mt][1], ah[mt][2], ah[mt][3],
                        blf[nt][0], blf[nt][1]);
            }
    }
    __syncthreads();          // all warps done reading QK tiles; Sc may reuse

    // ---- phase B: stage eb transposed into Sc ----
    for (int jj = wid; jj < Sdim; jj += 8) {
        float4 t4 = *(const float4*)(eb + ((size_t)bh * Sdim + jj) * Sdim + lane * 4);
        Sc[lane*4+0][jj] = t4.x; Sc[lane*4+1][jj] = t4.y;
        Sc[lane*4+2][jj] = t4.z; Sc[lane*4+3][jj] = t4.w;
    }
    __syncthreads();

    // scores = (qk + eb) * scale, mask -> Sc
    const float scale = 0.17677669529663687f;
    const float NEGINF = -__int_as_float(0x7f800000);
    const int qr = lane >> 2, qc = lane & 3;
#pragma unroll
    for (int mt = 0; mt < 2; ++mt) {
        const int row = wm + mt * 16 + qr;
#pragma unroll
        for (int nt = 0; nt < 8; ++nt) {
            const int col = wn + nt * 8 + qc * 2;
#pragma unroll
            for (int rr = 0; rr < 2; ++rr) {
                const int r = row + rr * 8;
                const unsigned char* mp = mask + ((size_t)bh * Sdim + r) * Sdim + col;
                float s0v = (acc[mt][nt][rr*2+0] + Sc[r][col])     * scale;
                float s1v = (acc[mt][nt][rr*2+1] + Sc[r][col + 1]) * scale;
                if (mp[0]) s0v = NEGINF;
                if (mp[1]) s1v = NEGINF;
                Sc[r][col]     = s0v;
                Sc[r][col + 1] = s1v;
            }
        }
    }
    __syncthreads();

    // softmax rows; P hi/lo to global
    for (int r = wid; r < Sdim; r += 8) {
        float vals[4];
#pragma unroll
        for (int c = 0; c < 4; c++) vals[c] = Sc[r][lane + 32 * c];
        float m = fmaxf(fmaxf(vals[0], vals[1]), fmaxf(vals[2], vals[3]));
#pragma unroll
        for (int o = 16; o > 0; o >>= 1) m = fmaxf(m, __shfl_xor_sync(0xffffffffu, m, o));
        float ssum = 0.f;
#pragma unroll
        for (int c = 0; c < 4; c++) { vals[c] = __expf(vals[c] - m); ssum += vals[c]; }
#pragma unroll
        for (int o = 16; o > 0; o >>= 1) ssum += __shfl_xor_sync(0xffffffffu, ssum, o);
        float inv = 1.f / ssum;
        __half* hp = ath + ((size_t)bh * Sdim + r) * Sdim;
        __half* lp = atl + ((size_t)bh * Sdim + r) * Sdim;
#pragma unroll
        for (int c = 0; c < 4; c++) {
            float p = vals[c] * inv;
            __half hh_, ll_;
            split16(p, hh_, ll_);
            hp[lane + 32 * c] = hh_;
            lp[lane + 32 * c] = ll_;
        }
    }
}

// ==================== PV via fp16 3-pass mma (per bh) ======================
#define EVSK 136
#define EVA_B (128 * EVSK * 2)          /* 34816 B */
#define EVB_B (32 * EVSK * 2)           /* 8704 B */
#define EVM_BYTES (2 * EVA_B + 2 * EVB_B)  /* 87040 B */
__global__ __launch_bounds__(256) void pv_mma(
    const __half* __restrict__ ath, const __half* __restrict__ atl,
    const __half* __restrict__ qkvh, const __half* __restrict__ qkvl,
    float* __restrict__ ctx)
{
    extern __shared__ __half es[];
    const uint32_t s0 = smem_u32(es);
    const int bh = blockIdx.x;
    const int b = bh >> 3, h = bh & 7;
    const int tid = threadIdx.x, lane = tid & 31, wid = tid >> 5;

#pragma unroll
    for (int ss = 0; ss < 8; ++ss) {
        const int seg = tid + ss * 256;
        const int r = seg >> 4, sg = seg & 15;
        const size_t src = ((size_t)bh * Sdim + r) * Sdim + sg * 8;
        const uint32_t dst = s0 + (uint32_t)((r * EVSK + sg * 8) * 2);
        CP16(dst, ath + src);
        CP16(dst + EVA_B, atl + src);
    }
    {
        const uint32_t vth = 2 * EVA_B / 2;
#pragma unroll
        for (int e = 0; e < 8; ++e) {
            const int idx = e * 256 + tid;
            const int j = idx >> 4, dp = (idx & 15) * 2;
            const size_t src = (size_t)(b * Sdim + j) * QKVS + 512 + h * HDim + dp;
            __half2 vh = *(const __half2*)(qkvh + src);
            __half2 vl = *(const __half2*)(qkvl + src);
            es[vth + dp * EVSK + j]       = __low2half(vh);
            es[vth + (dp + 1) * EVSK + j] = __high2half(vh);
            es[vth + EVB_B / 2 + dp * EVSK + j]       = __low2half(vl);
            es[vth + EVB_B / 2 + (dp + 1) * EVSK + j] = __high2half(vl);
        }
    }
    CPWAITALL();
    __syncthreads();

    const uint32_t a_loff = (uint32_t)(((lane & 15) * EVSK + ((lane >> 4) << 3)) * 2);
    const uint32_t b_loff = (uint32_t)((((lane & 7) + ((lane >> 4) << 3)) * EVSK
                                        + (((lane >> 3) & 1) << 3)) * 2);
    const uint32_t Ahb = s0 + (uint32_t)(wid * 16 * EVSK * 2) + a_loff;
    const uint32_t Alb = Ahb + EVA_B;
    const uint32_t Bhb = s0 + 2 * EVA_B + b_loff;
    const uint32_t Blb = Bhb + EVB_B;

    float acc[4][4];
#pragma unroll
    for (int nt = 0; nt < 4; ++nt)
#pragma unroll
        for (int e = 0; e < 4; ++e) acc[nt][e] = 0.f;

#pragma unroll
    for (int ks = 0; ks < 8; ++ks) {
        const uint32_t kb2 = ks * 32;
        uint32_t bhf[4][2], blf[4][2];
#pragma unroll
        for (int p = 0; p < 2; ++p) {
            uint32_t r0, r1, r2, r3;
            LDSM_X4(r0, r1, r2, r3, Bhb + (uint32_t)(p * 16 * EVSK * 2) + kb2);
            bhf[p*2][0] = r0; bhf[p*2][1] = r1;
            bhf[p*2+1][0] = r2; bhf[p*2+1][1] = r3;
            LDSM_X4(r0, r1, r2, r3, Blb + (uint32_t)(p * 16 * EVSK * 2) + kb2);
            blf[p*2][0] = r0; blf[p*2][1] = r1;
            blf[p*2+1][0] = r2; blf[p*2+1][1] = r3;
        }
        uint32_t ah[4], al[4];
        LDSM_X4(ah[0], ah[1], ah[2], ah[3], Ahb + kb2);
        LDSM_X4(al[0], al[1], al[2], al[3], Alb + kb2);
#pragma unroll
        for (int nt = 0; nt < 4; ++nt) {
            mma_f16(acc[nt][0], acc[nt][1], acc[nt][2], acc[nt][3],
                    ah[0], ah[1], ah[2], ah[3], bhf[nt][0], bhf[nt][1]);
            mma_f16(acc[nt][0], acc[nt][1], acc[nt][2], acc[nt][3],
                    al[0], al[1], al[2], al[3], bhf[nt][0], bhf[nt][1]);
            mma_f16(acc[nt][0], acc[nt][1], acc[nt][2], acc[nt][3],
                    ah[0], ah[1], ah[2], ah[3], blf[nt][0], blf[nt][1]);
        }
    }

    const int qr = lane >> 2, qc = lane & 3;
    const int row0 = wid * 16 + qr;
#pragma unroll
    for (int nt = 0; nt < 4; ++nt) {
        const int d0 = nt * 8 + qc * 2;
#pragma unroll
        for (int rr = 0; rr < 2; ++rr) {
            const int i = row0 + rr * 8;
            const size_t idx = (size_t)(b * Sdim + i) * Ddim + h * HDim + d0;
            *(float2*)(ctx + idx) =
                make_float2(acc[nt][rr * 2 + 0], acc[nt][rr * 2 + 1]);
        }
    }
}

// ==================== edge-value via fp16 3-pass mma (per i) ===============
__global__ __launch_bounds__(256) void ev_mma(
    const __half* __restrict__ ath, const __half* __restrict__ atl,
    const float* __restrict__ ev, const float* __restrict__ ctx,
    __half* __restrict__ ch, __half* __restrict__ cl)
{
    extern __shared__ __half es[];
    const uint32_t s0 = smem_u32(es);
    const int i = blockIdx.x, bh0 = blockIdx.y * 128;
    const int tid = threadIdx.x, lane = tid & 31, wid = tid >> 5;

#pragma unroll
    for (int ss = 0; ss < 8; ++ss) {
        const int seg = tid + ss * 256;
        const int r = seg >> 4, sg = seg & 15;
        const size_t src = ((size_t)(bh0 + r) * Sdim + i) * Sdim + sg * 8;
        const uint32_t dst = s0 + (uint32_t)((r * EVSK + sg * 8) * 2);
        CP16(dst, ath + src);
        CP16(dst + EVA_B, atl + src);
    }
    {
        const float* evp = ev + (size_t)i * Sdim * HDim;
        const uint32_t vth = 2 * EVA_B / 2;
#pragma unroll
        for (int e = 0; e < 16; ++e) {
            const int idx = e * 256 + tid;
            const int d = idx & 31, jj = idx >> 5;
            float v = evp[idx];
            __half h, l;
            split16(v, h, l);
            es[vth + d * EVSK + jj] = h;
            es[vth + EVB_B / 2 + d * EVSK + jj] = l;
        }
    }
    CPWAITALL();
    __syncthreads();

    const uint32_t a_loff = (uint32_t)(((lane & 15) * EVSK + ((lane >> 4) << 3)) * 2);
    const uint32_t b_loff = (uint32_t)((((lane & 7) + ((lane >> 4) << 3)) * EVSK
                                        + (((lane >> 3) & 1) << 3)) * 2);
    const uint32_t Ahb = s0 + (uint32_t)(wid * 16 * EVSK * 2) + a_loff;
    const uint32_t Alb = Ahb + EVA_B;
    const uint32_t Bhb = s0 + 2 * EVA_B + b_loff;
    const uint32_t Blb = Bhb + EVB_B;

    float acc[4][4];
#pragma unroll
    for (int nt = 0; nt < 4; ++nt)
#pragma unroll
        for (int e = 0; e < 4; ++e) acc[nt][e] = 0.f;

#pragma unroll
    for (int ks = 0; ks < 8; ++ks) {
        const uint32_t kb2 = ks * 32;
        uint32_t bhf[4][2], blf[4][2];
#pragma unroll
        for (int p = 0; p < 2; ++p) {
            uint32_t r0, r1, r2, r3;
            LDSM_X4(r0, r1, r2, r3, Bhb + (uint32_t)(p * 16 * EVSK * 2) + kb2);
            bhf[p*2][0] = r0; bhf[p*2][1] = r1;
            bhf[p*2+1][0] = r2; bhf[p*2+1][1] = r3;
            LDSM_X4(r0, r1, r2, r3, Blb + (uint32_t)(p * 16 * EVSK * 2) + kb2);
            blf[p*2][0] = r0; blf[p*2][1] = r1;
            blf[p*2+1][0] = r2; blf[p*2+1][1] = r3;
        }
        uint32_t ah[4], al[4];
        LDSM_X4(ah[0], ah[1], ah[2], ah[3], Ahb + kb2);
        LDSM_X4(al[0], al[1], al[2], al[3], Alb + kb2);
#pragma unroll
        for (int nt = 0; nt < 4; ++nt) {
            mma_f16(acc[nt][0], acc[nt][1], acc[nt][2], acc[nt][3],
                    ah[0], ah[1], ah[2], ah[3], bhf[nt][0], bhf[nt][1]);
            mma_f16(acc[nt][0], acc[nt][1], acc[nt][2], acc[nt][3],
                    al[0], al[1], al[2], al[3], bhf[nt][0], bhf[nt][1]);
            mma_f16(acc[nt][0], acc[nt][1], acc[nt][2], acc[nt][3],
                    ah[0], ah[1], ah[2], ah[3], blf[nt][0], blf[nt][1]);
        }
    }

    const int qr = lane >> 2, qc = lane & 3;
    const int row0 = wid * 16 + qr;
#pragma unroll
    for (int nt = 0; nt < 4; ++nt) {
        const int d0 = nt * 8 + qc * 2;
#pragma unroll
        for (int rr = 0; rr < 2; ++rr) {
            const int bh = bh0 + row0 + rr * 8;
            const int b = bh >> 3, h = bh & 7;
            const size_t idx = (size_t)(b * Sdim + i) * Ddim + h * HDim + d0;
            float2 cur = *(const float2*)(ctx + idx);
            float v0 = cur.x + acc[nt][rr * 2 + 0];
            float v1 = cur.y + acc[nt][rr * 2 + 1];
            __half h0, l0, h1, l1;
            split16(v0, h0, l0); split16(v1, h1, l1);
            *(__half2*)(ch + idx) = __halves2half2(h0, h1);
            *(__half2*)(cl + idx) = __halves2half2(l0, l1);
        }
    }
}

// ============ fused weight transpose -> fp16 [N][K] ========================
__global__ __launch_bounds__(256) void tr_all(
    const float* __restrict__ Wq, const float* __restrict__ Wk,
    const float* __restrict__ Wv, const float* __restrict__ Wo,
    const float* __restrict__ W1, const float* __restrict__ W2,
    __half* __restrict__ wqkvT, __half* __restrict__ woT,
    __half* __restrict__ w1T, __half* __restrict__ w2T)
{
    __shared__ float t[32][33];
    const int tb = blockIdx.x;
    const float* src; __half* dst; int K, N, kx, nx;
    if (tb < 768) {
        int w = tb / 256, r = tb % 256, l = r / 64, q = r % 64;
        src = (w == 0 ? Wq : (w == 1 ? Wk : Wv)) + (size_t)l * 65536;
        dst = wqkvT + (size_t)l * 196608 + (size_t)w * 65536;
        K = 256; N = 256; kx = (q / 8) * 32; nx = (q % 8) * 32;
    } else if (tb < 1024) {
        int r = tb - 768, l = r / 64, q = r % 64;
        src = Wo + (size_t)l * 65536; dst = woT + (size_t)l * 65536;
        K = 256; N = 256; kx = (q / 8) * 32; nx = (q % 8) * 32;
    } else if (tb < 3072) {
        int r = tb - 1024, l = r / 512, q = r % 512;
        src = W1 + (size_t)l * 524288; dst = w1T + (size_t)l * 524288;
        K = 256; N = 2048; kx = (q / 64) * 32; nx = (q % 64) * 32;
    } else {
        int r = tb - 3072, l = r / 512, q = r % 512;
        src = W2 + (size_t)l * 524288; dst = w2T + (size_t)l * 524288;
        K = 2048; N = 256; kx = (q / 8) * 32; nx = (q % 8) * 32;
    }
    const int x = threadIdx.x & 31, y = threadIdx.x >> 5;
#pragma unroll
    for (int yy = y; yy < 32; yy += 8)
        t[yy][x] = src[(size_t)(kx + yy) * N + nx + x];
    __syncthreads();
#pragma unroll
    for (int yy = y; yy < 32; yy += 8)
        dst[(size_t)(nx + yy) * K + kx + x] = __float2half_rn(t[x][yy]);
}

// ---- prep -----------------------------------------------------------------
__global__ void prep_kernel(const float* __restrict__ facts, float* __restrict__ x,
                            __half* __restrict__ xh, __half* __restrict__ xl,
                            const float* __restrict__ ekey,
                            __half* __restrict__ ekh, __half* __restrict__ ekl,
                            const float* __restrict__ bq, const float* __restrict__ bk,
                            const float* __restrict__ bv, float* __restrict__ bqkv)
{
    size_t idx = (size_t)blockIdx.x * 256 + threadIdx.x;
    float v = facts[idx];
    x[idx] = v;
    __half h, l;
    split16(v, h, l);
    xh[idx] = h; xl[idx] = l;
    if (idx < EKN) {
        float e = ekey[idx];
        __half eh, el;
        split16(e, eh, el);
        ekh[idx] = eh; ekl[idx] = el;
    }
    if (idx < Ldim * QKVS) {
        int li = (int)(idx / QKVS), ji = (int)(idx % QKVS);
        float bvv;
        if (ji < 256)      bvv = bq[li * 256 + ji];
        else if (ji < 512) bvv = bk[li * 256 + ji - 256];
        else               bvv = bv[li * 256 + ji - 512];
        bqkv[idx] = bvv;
    }
}

// ---------------- layer norm; outT != null -> write transposed only --------
__global__ __launch_bounds__(256) void ln_kernel(
    const float* __restrict__ in1, const float* __restrict__ in2, float alpha,
    const float* __restrict__ g, const float* __restrict__ b,
    float* __restrict__ out, __half* __restrict__ outh, __half* __restrict__ outl,
    float* __restrict__ outT)
{
    const int warp = threadIdx.x >> 5, lane = threadIdx.x & 31;
    const int row = blockIdx.x * 8 + warp;
    const float* p1 = in1 + (size_t)row * Ddim;
    float v[8];
#pragma unroll
    for (int c = 0; c < 8; c++) {
        int col = lane + 32 * c;
        float t = alpha * p1[col];
        if (in2) t += in2[(size_t)row * Ddim + col];
        v[c] = t;
    }
    float s = 0.f;
#pragma unroll
    for (int c = 0; c < 8; c++) s += v[c];
#pragma unroll
    for (int o = 16; o > 0; o >>= 1) s += __shfl_xor_sync(0xffffffffu, s, o);
    float mu = s * (1.f / Ddim);
    float var = 0.f;
#pragma unroll
    for (int c = 0; c < 8; c++) { float d = v[c] - mu; var += d * d; }
#pragma unroll
    for (int o = 16; o > 0; o >>= 1) var += __shfl_xor_sync(0xffffffffu, var, o);
    var *= (1.f / Ddim);
    float inv = rsqrtf(var + 1e-5f);
    if (outT) {
        const int bcol = row >> 7, srow = row & 127;
        float* op = outT + ((size_t)(srow * Bdim + bcol)) * Ddim;
#pragma unroll
        for (int c = 0; c < 8; c++) {
            int col = lane + 32 * c;
            op[col] = (v[c] - mu) * inv * g[col] + b[col];
        }
    } else {
#pragma unroll
        for (int c = 0; c < 8; c++) {
            int col = lane + 32 * c;
            float r = (v[c] - mu) * inv * g[col] + b[col];
            out[(size_t)row * Ddim + col] = r;
            __half h, l;
            split16(r, h, l);
            outh[(size_t)row * Ddim + col] = h;
            outl[(size_t)row * Ddim + col] = l;
        }
    }
}

// ---------------- host -----------------------------------------------------
extern "C" void kernel_launch(void* const* d_in, const int* in_sizes, int n_in,
                              void* d_out, int out_size)
{
    const float* facts = (const float*)d_in[0];
    const float* ekey  = (const float*)d_in[1];
    const float* evalp = (const float*)d_in[2];
    const unsigned char* mask = (const unsigned char*)d_in[3];
    const float *Wq, *Wk, *Wv, *Wo, *bq, *bk, *bv, *bo;
    if (in_sizes[5] == Ldim * Ddim) {
        Wq = (const float*)d_in[4];  bq = (const float*)d_in[5];
        Wk = (const float*)d_in[6];  bk = (const float*)d_in[7];
        Wv = (const float*)d_in[8];  bv = (const float*)d_in[9];
        Wo = (const float*)d_in[10]; bo = (const float*)d_in[11];
    } else {
        Wq = (const float*)d_in[4];  Wk = (const float*)d_in[5];
        Wv = (const float*)d_in[6];  Wo = (const float*)d_in[7];
        bq = (const float*)d_in[8];  bk = (const float*)d_in[9];
        bv = (const float*)d_in[10]; bo = (const float*)d_in[11];
    }
    const float* ln1g = (const float*)d_in[12];
    const float* ln1b = (const float*)d_in[13];
    const float* W1   = (const float*)d_in[14];
    const float* b1   = (const float*)d_in[15];
    const float* W2   = (const float*)d_in[16];
    const float* b2   = (const float*)d_in[17];
    const float* ln2g = (const float*)d_in[18];
    const float* ln2b = (const float*)d_in[19];

    float *x, *ctx, *tmp, *eb, *bqkvp;
    __half *ath, *atl, *qkvh, *qkvl;
    __half *xh, *xl, *ch, *cl, *ffh, *ffl, *ekh, *ekl;
    __half *wqkvT, *woT, *w1T, *w2T;
    cudaGetSymbolAddress((void**)&x,    g_x);
    cudaGetSymbolAddress((void**)&ctx,  g_ctx);
    cudaGetSymbolAddress((void**)&tmp,  g_tmp);
    cudaGetSymbolAddress((void**)&eb,   g_eb);
    cudaGetSymbolAddress((void**)&ath,  g_ath);
    cudaGetSymbolAddress((void**)&atl,  g_atl);
    cudaGetSymbolAddress((void**)&qkvh, g_qkvh);
    cudaGetSymbolAddress((void**)&qkvl, g_qkvl);
    cudaGetSymbolAddress((void**)&xh,   g_xh);
    cudaGetSymbolAddress((void**)&xl,   g_xl);
    cudaGetSymbolAddress((void**)&ch,   g_ch);
    cudaGetSymbolAddress((void**)&cl,   g_cl);
    cudaGetSymbolAddress((void**)&ffh,  g_ffh);
    cudaGetSymbolAddress((void**)&ffl,  g_ffl);
    cudaGetSymbolAddress((void**)&ekh,  g_ekh);
    cudaGetSymbolAddress((void**)&ekl,  g_ekl);
    cudaGetSymbolAddress((void**)&wqkvT, g_wqkvT);
    cudaGetSymbolAddress((void**)&woT,  g_woT);
    cudaGetSymbolAddress((void**)&w1T,  g_w1T);
    cudaGetSymbolAddress((void**)&w2T,  g_w2T);
    cudaGetSymbolAddress((void**)&bqkvp, g_bqkv);

    cudaFuncSetAttribute(mma_gemm<false,false>, cudaFuncAttributeMaxDynamicSharedMemorySize, GSMB);
    cudaFuncSetAttribute(mma_gemm<false,true>,  cudaFuncAttributeMaxDynamicSharedMemorySize, GSMB);
    cudaFuncSetAttribute(mma_gemm<true,true>,   cudaFuncAttributeMaxDynamicSharedMemorySize, GSMB);
    cudaFuncSetAttribute(attn_mma, cudaFuncAttributeMaxDynamicSharedMemorySize, ATTM_BYTES);
    cudaFuncSetAttribute(pv_mma,   cudaFuncAttributeMaxDynamicSharedMemorySize, EVM_BYTES);
    cudaFuncSetAttribute(ev_mma,   cudaFuncAttributeMaxDynamicSharedMemorySize, EVM_BYTES);

    // launches: 0 tr_all, 1 prep, 2 QKV, 3 ebias_mma (ncu target)
    tr_all<<<5120, 256>>>(Wq, Wk, Wv, Wo, W1, W2, wqkvT, woT, w1T, w2T);        // 0
    prep_kernel<<<NR * Ddim / 256, 256>>>(facts, x, xh, xl,
                                          ekey, ekh, ekl, bq, bk, bv, bqkvp);   // 1

    for (int l = 0; l < Ldim; l++) {
        mma_gemm<false,true><<<dim3(QKVS / 128, NR / 128), 256, GSMB>>>(
            xh, xl, wqkvT + (size_t)l * 3 * Ddim * Ddim, bqkvp + l * QKVS,
            nullptr, qkvh, qkvl, NR, QKVS, Ddim);                               // 2 (l=0)

        ebias_mma<<<dim3(Sdim, BHdim / 128), 256>>>(qkvh, qkvl, ekh, ekl, eb);  // 3 (l=0)
        attn_mma<<<BHdim, 256, ATTM_BYTES>>>(qkvh, qkvl, eb, mask, ath, atl);
        pv_mma<<<BHdim, 256, EVM_BYTES>>>(ath, atl, qkvh, qkvl, ctx);
        ev_mma<<<dim3(Sdim, BHdim / 128), 256, EVM_BYTES>>>(ath, atl, evalp,
                                                            ctx, ch, cl);

        mma_gemm<false,false><<<dim3(Ddim / 128, NR / 128), 256, GSMB>>>(
            ch, cl, woT + (size_t)l * Ddim * Ddim, bo + l * Ddim,
            tmp, nullptr, nullptr, NR, Ddim, Ddim);
        ln_kernel<<<NR / 8, 256>>>(tmp, x, 1.f, ln1g + l * Ddim, ln1b + l * Ddim,
                                   x, xh, xl, nullptr);

        mma_gemm<true,true><<<dim3(Fdim / 128, NR / 128), 256, GSMB>>>(
            xh, xl, w1T + (size_t)l * Fdim * Ddim, b1 + l * Fdim,
            nullptr, ffh, ffl, NR, Fdim, Ddim);
        mma_gemm<false,false><<<dim3(Ddim / 128, NR / 128), 256, GSMB>>>(
            ffh, ffl, w2T + (size_t)l * Ddim * Fdim, b2 + l * Ddim,
            tmp, nullptr, nullptr, NR, Ddim, Fdim);
        // final layer: LN2 writes the transposed output directly
        ln_kernel<<<NR / 8, 256>>>(tmp, nullptr, 2.f, ln2g + l * Ddim, ln2b + l * Ddim,
                                   x, xh, xl,
                                   (l == Ldim - 1) ? (float*)d_out : nullptr);
    }
}

// round 17
// speedup vs baseline: 1.2567x; 1.0195x over previous
#include <cuda_runtime.h>
#include <cuda_fp16.h>
#include <cstdint>
#include <math.h>

#define Bdim 128
#define Sdim 128
#define Ddim 256
#define Hdim 8
#define HDim 32
#define Fdim 2048
#define Ldim 4
#define BHdim (Bdim*Hdim)     /* 1024 */
#define NR (Bdim*Sdim)        /* 16384 rows */
#define QKVS 768
#define EKN (Sdim*Sdim*HDim)  /* 524288 */

// ---------------- scratch (device globals) ---------------------------------
__device__ float g_x[NR*Ddim];
__device__ float g_ctx[NR*Ddim];
__device__ float g_eb[(size_t)BHdim*Sdim*Sdim];   // [bh][j][i]
__device__ __half g_ath[(size_t)BHdim*Sdim*Sdim]; // P hi [bh][i][j]
__device__ __half g_atl[(size_t)BHdim*Sdim*Sdim]; // P lo
__device__ __half g_qkvh[(size_t)NR*QKVS];
__device__ __half g_qkvl[(size_t)NR*QKVS];
__device__ __half g_xh[NR*Ddim];
__device__ __half g_xl[NR*Ddim];
__device__ __half g_ch[NR*Ddim];
__device__ __half g_cl[NR*Ddim];
__device__ __half g_ffh[(size_t)NR*Fdim];
__device__ __half g_ffl[(size_t)NR*Fdim];
__device__ __half g_ekh[EKN];
__device__ __half g_ekl[EKN];
__device__ __half g_wqkvT[(size_t)Ldim*3*Ddim*Ddim];
__device__ __half g_woT[(size_t)Ldim*Ddim*Ddim];
__device__ __half g_w1T[(size_t)Ldim*Fdim*Ddim];
__device__ __half g_w2T[(size_t)Ldim*Ddim*Fdim];
__device__ float g_bqkv[Ldim*QKVS];

// ==================== helpers =============================================
__device__ __forceinline__ uint32_t smem_u32(const void* p) {
    uint32_t a;
    asm("{ .reg .u64 t; cvta.to.shared.u64 t, %1; cvt.u32.u64 %0, t; }"
        : "=r"(a) : "l"(p));
    return a;
}
#define LDSM_X4(R0,R1,R2,R3,ADDR) \
    asm volatile("ldmatrix.sync.aligned.m8n8.x4.shared.b16 {%0,%1,%2,%3}, [%4];" \
        : "=r"(R0), "=r"(R1), "=r"(R2), "=r"(R3) : "r"(ADDR) : "memory")
#define CP16(dst, src) \
    asm volatile("cp.async.cg.shared.global [%0], [%1], 16;" :: "r"(dst), "l"(src))
#define CPCOMMIT() asm volatile("cp.async.commit_group;" ::: "memory")
#define CPWAIT1()  asm volatile("cp.async.wait_group 1;" ::: "memory")
#define CPWAIT0()  asm volatile("cp.async.wait_group 0;" ::: "memory")
#define CPWAITALL() asm volatile("cp.async.wait_all;" ::: "memory")

__device__ __forceinline__ void mma_f16(
    float& c0, float& c1, float& c2, float& c3,
    uint32_t a0, uint32_t a1, uint32_t a2, uint32_t a3,
    uint32_t b0, uint32_t b1)
{
    asm volatile(
        "mma.sync.aligned.m16n8k16.row.col.f32.f16.f16.f32 "
        "{%0,%1,%2,%3}, {%4,%5,%6,%7}, {%8,%9}, {%0,%1,%2,%3};"
        : "+f"(c0), "+f"(c1), "+f"(c2), "+f"(c3)
        : "r"(a0), "r"(a1), "r"(a2), "r"(a3), "r"(b0), "r"(b1));
}

__device__ __forceinline__ void split16(float v, __half& h, __half& l) {
    h = __float2half_rn(v);
    l = __float2half_rn(v - __half2float(h));
}

// ==================== fp16 split-A mma GEMM (cp.async, 3-stage) ============
#define CH 32
#define SKH 40
#define TILEB (128 * SKH * 2)
#define CHUNKB (3 * TILEB)
#define NSTG 3
#define GSMB (NSTG * CHUNKB)            /* 92160 B */

template<bool RELU, bool OUTH>
__global__ __launch_bounds__(256, 2) void mma_gemm(
    const __half* __restrict__ Ah, const __half* __restrict__ Al,
    const __half* __restrict__ BT, const float* __restrict__ bias,
    float* __restrict__ C, __half* __restrict__ Ch, __half* __restrict__ Cl,
    int M, int N, int K)
{
    extern __shared__ __half sh[];
    const uint32_t s0 = smem_u32(sh);
    const int tid = threadIdx.x;
    const int lane = tid & 31, wid = tid >> 5;
    const int wm = (wid >> 1) * 32, wn = (wid & 1) * 64;
    const int m0 = blockIdx.y * 128, n0 = blockIdx.x * 128;
    const int nch = K / CH;
    const int srow = tid >> 1, shalf = tid & 1;
    const int rev = wid & 1;

    const __half* Abase = Ah + (size_t)(m0 + srow) * K + shalf * 16;
    const __half* Lbase = Al + (size_t)(m0 + srow) * K + shalf * 16;
    const __half* Bbase = BT + (size_t)(n0 + srow) * K + shalf * 16;
    const uint32_t sdst = (uint32_t)((srow * SKH + shalf * 16) * 2);

    const uint32_t a_loff = (uint32_t)(((lane & 15) * SKH + ((lane >> 4) << 3)) * 2);
    const uint32_t b_loff = (uint32_t)((((lane & 7) + ((lane >> 4) << 3)) * SKH
                                        + (((lane >> 3) & 1) << 3)) * 2);

    auto issue = [&](int c) {
        const uint32_t base = s0 + (uint32_t)((c % NSTG) * CHUNKB) + sdst;
        const __half* ap = Abase + c * CH;
        const __half* lp = Lbase + c * CH;
        const __half* bp = Bbase + c * CH;
        CP16(base,              ap);     CP16(base + 16,              ap + 8);
        CP16(base + TILEB,      lp);     CP16(base + TILEB + 16,      lp + 8);
        CP16(base + 2 * TILEB,  bp);     CP16(base + 2 * TILEB + 16,  bp + 8);
        CPCOMMIT();
    };

    float acc[2][8][4];
#pragma unroll
    for (int mt = 0; mt < 2; ++mt)
#pragma unroll
        for (int nt = 0; nt < 8; ++nt)
#pragma unroll
            for (int e = 0; e < 4; ++e) acc[mt][nt][e] = 0.f;

    issue(0);
    if (nch > 1) issue(1);

    for (int c = 0; c < nch; ++c) {
        if (c + 1 < nch) { CPWAIT1(); } else { CPWAIT0(); }
        __syncthreads();
        if (c + 2 < nch) issue(c + 2);

        const uint32_t stg = s0 + (uint32_t)((c % NSTG) * CHUNKB);
        const uint32_t ahb = stg + (uint32_t)(wm * SKH * 2) + a_loff;
        const uint32_t alb = ahb + TILEB;
        const uint32_t bhb = stg + 2 * TILEB + (uint32_t)(wn * SKH * 2) + b_loff;
#pragma unroll
        for (int s0i = 0; s0i < 2; ++s0i) {
            const int s = rev ? (1 - s0i) : s0i;
            const uint32_t kb2 = s * 32;
            uint32_t bfr[8][2];
#pragma unroll
            for (int p = 0; p < 4; ++p) {
                uint32_t r0, r1, r2, r3;
                LDSM_X4(r0, r1, r2, r3,
                        bhb + (uint32_t)(p * 16 * SKH * 2) + kb2);
                bfr[p*2][0] = r0; bfr[p*2][1] = r1;
                bfr[p*2+1][0] = r2; bfr[p*2+1][1] = r3;
            }
            uint32_t ah[2][4], al[2][4];
#pragma unroll
            for (int mt = 0; mt < 2; ++mt) {
                LDSM_X4(ah[mt][0], ah[mt][1], ah[mt][2], ah[mt][3],
                        ahb + (uint32_t)(mt * 16 * SKH * 2) + kb2);
                LDSM_X4(al[mt][0], al[mt][1], al[mt][2], al[mt][3],
                        alb + (uint32_t)(mt * 16 * SKH * 2) + kb2);
            }
#pragma unroll
            for (int nt = 0; nt < 8; ++nt)
#pragma unroll
                for (int mt = 0; mt < 2; ++mt)
                    mma_f16(acc[mt][nt][0], acc[mt][nt][1],
                            acc[mt][nt][2], acc[mt][nt][3],
                            ah[mt][0], ah[mt][1], ah[mt][2], ah[mt][3],
                            bfr[nt][0], bfr[nt][1]);
#pragma unroll
            for (int nt = 0; nt < 8; ++nt)
#pragma unroll
                for (int mt = 0; mt < 2; ++mt)
                    mma_f16(acc[mt][nt][0], acc[mt][nt][1],
                            acc[mt][nt][2], acc[mt][nt][3],
                            al[mt][0], al[mt][1], al[mt][2], al[mt][3],
                            bfr[nt][0], bfr[nt][1]);
        }
    }

    const int qr = lane >> 2, qc = lane & 3;
#pragma unroll
    for (int mt = 0; mt < 2; ++mt) {
        const int r = m0 + wm + mt * 16 + qr;
#pragma unroll
        for (int nt = 0; nt < 8; ++nt) {
            const int col = n0 + wn + nt * 8 + qc * 2;
            float b0 = bias[col], b1 = bias[col + 1];
            float v00 = acc[mt][nt][0] + b0, v01 = acc[mt][nt][1] + b1;
            float v10 = acc[mt][nt][2] + b0, v11 = acc[mt][nt][3] + b1;
            if (RELU) {
                v00 = fmaxf(v00, 0.f); v01 = fmaxf(v01, 0.f);
                v10 = fmaxf(v10, 0.f); v11 = fmaxf(v11, 0.f);
            }
            if (OUTH) {
                __half h00, l00, h01, l01, h10, l10, h11, l11;
                split16(v00, h00, l00); split16(v01, h01, l01);
                split16(v10, h10, l10); split16(v11, h11, l11);
                *(__half2*)(Ch + (size_t)r * N + col)       = __halves2half2(h00, h01);
                *(__half2*)(Cl + (size_t)r * N + col)       = __halves2half2(l00, l01);
                *(__half2*)(Ch + (size_t)(r + 8) * N + col) = __halves2half2(h10, h11);
                *(__half2*)(Cl + (size_t)(r + 8) * N + col) = __halves2half2(l10, l11);
            } else {
                *(float2*)(C + (size_t)r * N + col)       = make_float2(v00, v01);
                *(float2*)(C + (size_t)(r + 8) * N + col) = make_float2(v10, v11);
            }
        }
    }
}

// ==================== GEMM (N=256 full row) + fused LayerNorm ==============
// 512 threads, CTA tile 128x256 (16 warps, 4m x 4n). A copied once per chunk.
// Epilogue: v = acc + bias (+x residual | *2); per-row LN; write x/xh/xl or
// transposed d_out (final layer).
#define B2_TILEB (256 * SKH * 2)        /* 20480 */
#define CHUNK2B (2 * TILEB + B2_TILEB)  /* 40960 */
#define GSM2B (NSTG * CHUNK2B)          /* 122880 */

__global__ __launch_bounds__(512, 1) void mma_gemm_ln(
    const __half* __restrict__ Ah, const __half* __restrict__ Al,
    const __half* __restrict__ BT, const float* __restrict__ bias,
    const float* __restrict__ xres,       // non-null: +residual; null: *2
    const float* __restrict__ g, const float* __restrict__ bb,
    float* __restrict__ xout, __half* __restrict__ xh, __half* __restrict__ xl,
    float* __restrict__ outT, int K)
{
    extern __shared__ __half sh[];
    const uint32_t s0 = smem_u32(sh);
    const int tid = threadIdx.x;
    const int lane = tid & 31, wid = tid >> 5;
    const int wm = (wid >> 2) * 32, wn = (wid & 3) * 64;
    const int m0 = blockIdx.x * 128;
    const int nch = K / CH;

    const int arow = tid >> 2, aseg = tid & 3;
    const int brow = tid >> 1, bseg = (tid & 1) * 2;

    const __half* AHsrc = Ah + (size_t)(m0 + arow) * K + aseg * 8;
    const __half* ALsrc = Al + (size_t)(m0 + arow) * K + aseg * 8;
    const __half* Bsrc  = BT + (size_t)brow * K + bseg * 8;
    const uint32_t adst = (uint32_t)(arow * SKH * 2 + aseg * 16);
    const uint32_t bdst = (uint32_t)(brow * SKH * 2 + bseg * 16);

    const uint32_t a_loff = (uint32_t)(((lane & 15) * SKH + ((lane >> 4) << 3)) * 2);
    const uint32_t b_loff = (uint32_t)((((lane & 7) + ((lane >> 4) << 3)) * SKH
                                        + (((lane >> 3) & 1) << 3)) * 2);

    auto issue = [&](int c) {
        const uint32_t stg = s0 + (uint32_t)((c % NSTG) * CHUNK2B);
        CP16(stg + adst,                    AHsrc + c * CH);
        CP16(stg + TILEB + adst,            ALsrc + c * CH);
        CP16(stg + 2 * TILEB + bdst,        Bsrc + c * CH);
        CP16(stg + 2 * TILEB + bdst + 16,   Bsrc + c * CH + 8);
        CPCOMMIT();
    };

    float acc[2][8][4];
#pragma unroll
    for (int mt = 0; mt < 2; ++mt)
#pragma unroll
        for (int nt = 0; nt < 8; ++nt)
#pragma unroll
            for (int e = 0; e < 4; ++e) acc[mt][nt][e] = 0.f;

    issue(0);
    if (nch > 1) issue(1);

    for (int c = 0; c < nch; ++c) {
        if (c + 1 < nch) { CPWAIT1(); } else { CPWAIT0(); }
        __syncthreads();
        if (c + 2 < nch) issue(c + 2);

        const uint32_t stg = s0 + (uint32_t)((c % NSTG) * CHUNK2B);
        const uint32_t ahb = stg + (uint32_t)(wm * SKH * 2) + a_loff;
        const uint32_t alb = ahb + TILEB;
        const uint32_t bhb = stg + 2 * TILEB + (uint32_t)(wn * SKH * 2) + b_loff;
#pragma unroll
        for (int ss = 0; ss < 2; ++ss) {
            const uint32_t kb2 = ss * 32;
            uint32_t bfr[8][2];
#pragma unroll
            for (int p = 0; p < 4; ++p) {
                uint32_t r0, r1, r2, r3;
                LDSM_X4(r0, r1, r2, r3,
                        bhb + (uint32_t)(p * 16 * SKH * 2) + kb2);
                bfr[p*2][0] = r0; bfr[p*2][1] = r1;
                bfr[p*2+1][0] = r2; bfr[p*2+1][1] = r3;
            }
            uint32_t ah[2][4], al[2][4];
#pragma unroll
            for (int mt = 0; mt < 2; ++mt) {
                LDSM_X4(ah[mt][0], ah[mt][1], ah[mt][2], ah[mt][3],
                        ahb + (uint32_t)(mt * 16 * SKH * 2) + kb2);
                LDSM_X4(al[mt][0], al[mt][1], al[mt][2], al[mt][3],
                        alb + (uint32_t)(mt * 16 * SKH * 2) + kb2);
            }
#pragma unroll
            for (int nt = 0; nt < 8; ++nt)
#pragma unroll
                for (int mt = 0; mt < 2; ++mt)
                    mma_f16(acc[mt][nt][0], acc[mt][nt][1],
                            acc[mt][nt][2], acc[mt][nt][3],
                            ah[mt][0], ah[mt][1], ah[mt][2], ah[mt][3],
                            bfr[nt][0], bfr[nt][1]);
#pragma unroll
            for (int nt = 0; nt < 8; ++nt)
#pragma unroll
                for (int mt = 0; mt < 2; ++mt)
                    mma_f16(acc[mt][nt][0], acc[mt][nt][1],
                            acc[mt][nt][2], acc[mt][nt][3],
                            al[mt][0], al[mt][1], al[mt][2], al[mt][3],
                            bfr[nt][0], bfr[nt][1]);
        }
    }

    // ---------------- fused LayerNorm epilogue ----------------
    __syncthreads();                       // smem reuse after mainloop
    float* psum = (float*)sh;              // [128][16]
    float* psq  = psum + 128 * 16;         // [128][16]
    float* mus  = psq + 128 * 16;          // [128]
    float* invs = mus + 128;               // [128]

    const int qr = lane >> 2, qc = lane & 3;
    const int slot = (wid & 3) * 4 + qc;

    // bias + residual/scale (in place in acc)
#pragma unroll
    for (int mt = 0; mt < 2; ++mt)
#pragma unroll
        for (int nt = 0; nt < 8; ++nt) {
            const int col = wn + nt * 8 + qc * 2;
            const float b0 = bias[col], b1 = bias[col + 1];
#pragma unroll
            for (int rr = 0; rr < 2; ++rr) {
                const int row = wm + mt * 16 + rr * 8 + qr;
                float a0 = acc[mt][nt][rr*2+0] + b0;
                float a1 = acc[mt][nt][rr*2+1] + b1;
                if (xres) {
                    const size_t idx = (size_t)(m0 + row) * Ddim + col;
                    a0 += xres[idx];
                    a1 += xres[idx + 1];
                } else {
                    a0 *= 2.f; a1 *= 2.f;
                }
                acc[mt][nt][rr*2+0] = a0;
                acc[mt][nt][rr*2+1] = a1;
            }
        }

    // per-(row, slot) partials (deterministic: each slot written once)
#pragma unroll
    for (int mt = 0; mt < 2; ++mt)
#pragma unroll
        for (int rr = 0; rr < 2; ++rr) {
            const int row = wm + mt * 16 + rr * 8 + qr;
            float s = 0.f, sq = 0.f;
#pragma unroll
            for (int nt = 0; nt < 8; ++nt) {
                float a0 = acc[mt][nt][rr*2+0];
                float a1 = acc[mt][nt][rr*2+1];
                s += a0 + a1;
                sq += a0 * a0 + a1 * a1;
            }
            psum[row * 16 + slot] = s;
            psq[row * 16 + slot]  = sq;
        }
    __syncthreads();

    if (tid < 128) {
        float s = 0.f, sq = 0.f;
#pragma unroll
        for (int k = 0; k < 16; ++k) {
            s  += psum[tid * 16 + k];
            sq += psq[tid * 16 + k];
        }
        const float mu = s * (1.f / Ddim);
        const float var = sq * (1.f / Ddim) - mu * mu;
        mus[tid]  = mu;
        invs[tid] = rsqrtf(var + 1e-5f);
    }
    __syncthreads();

    // normalize + write
#pragma unroll
    for (int mt = 0; mt < 2; ++mt)
#pragma unroll
        for (int rr = 0; rr < 2; ++rr) {
            const int row = wm + mt * 16 + rr * 8 + qr;
            const float mu = mus[row], inv = invs[row];
            const int grow = m0 + row;
#pragma unroll
            for (int nt = 0; nt < 8; ++nt) {
                const int col = wn + nt * 8 + qc * 2;
                float r0 = (acc[mt][nt][rr*2+0] - mu) * inv * g[col]     + bb[col];
                float r1 = (acc[mt][nt][rr*2+1] - mu) * inv * g[col + 1] + bb[col + 1];
                if (outT) {
                    const int bcol = grow >> 7, srow = grow & 127;
                    float* op = outT + ((size_t)(srow * Bdim + bcol)) * Ddim + col;
                    op[0] = r0; op[1] = r1;
                } else {
                    const size_t idx = (size_t)grow * Ddim + col;
                    *(float2*)(xout + idx) = make_float2(r0, r1);
                    __half h0, l0, h1, l1;
                    split16(r0, h0, l0); split16(r1, h1, l1);
                    *(__half2*)(xh + idx) = __halves2half2(h0, h1);
                    *(__half2*)(xl + idx) = __halves2half2(l0, l1);
                }
            }
        }
}

// ==================== ebias via fp16 3-pass mma ============================
#define EBT 5120
__global__ __launch_bounds__(256) void ebias_mma(
    const __half* __restrict__ qkvh, const __half* __restrict__ qkvl,
    const __half* __restrict__ ekh, const __half* __restrict__ ekl,
    float* __restrict__ eb)
{
    __shared__ __half sm[4 * EBT];     // Ah Al Bh Bl
    const uint32_t s0 = smem_u32(sm);
    const int j = blockIdx.x;
    const int bh0 = blockIdx.y * 128;
    const int tid = threadIdx.x;
    const int lane = tid & 31, wid = tid >> 5;
    const int wm = (wid >> 1) * 32, wn = (wid & 1) * 64;

    {
        const int t = tid >> 6, u = tid & 63;
#pragma unroll
        for (int rr = 0; rr < 2; ++rr) {
            const int r = u + rr * 64;
            const __half* srcb;
            size_t soff;
            if (t < 2) {
                const int bh = bh0 + r;
                const int b = bh >> 3, h = bh & 7;
                soff = (size_t)(b * Sdim + j) * QKVS + h * HDim;   // q section
                srcb = (t == 0 ? qkvh : qkvl);
            } else {
                soff = ((size_t)j * Sdim + r) * HDim;
                srcb = (t == 2 ? ekh : ekl);
            }
            const uint32_t dst = s0 + (uint32_t)((t * EBT + r * SKH) * 2);
#pragma unroll
            for (int sg = 0; sg < 4; ++sg)
                CP16(dst + sg * 16, srcb + soff + sg * 8);
        }
    }
    CPWAITALL();
    __syncthreads();

    const uint32_t a_loff = (uint32_t)(((lane & 15) * SKH + ((lane >> 4) << 3)) * 2);
    const uint32_t b_loff = (uint32_t)((((lane & 7) + ((lane >> 4) << 3)) * SKH
                                        + (((lane >> 3) & 1) << 3)) * 2);
    const uint32_t Ahb = s0 + (uint32_t)(wm * SKH * 2) + a_loff;
    const uint32_t Alb = Ahb + EBT * 2;
    const uint32_t Bhb = s0 + (uint32_t)(2 * EBT * 2) + (uint32_t)(wn * SKH * 2) + b_loff;
    const uint32_t Blb = Bhb + EBT * 2;

    float acc[2][8][4];
#pragma unroll
    for (int mt = 0; mt < 2; ++mt)
#pragma unroll
        for (int nt = 0; nt < 8; ++nt)
#pragma unroll
            for (int e = 0; e < 4; ++e) acc[mt][nt][e] = 0.f;

#pragma unroll
    for (int ss = 0; ss < 2; ++ss) {
        const uint32_t kb2 = ss * 32;
        uint32_t bhf[8][2], blf[8][2];
#pragma unroll
        for (int p = 0; p < 4; ++p) {
            uint32_t r0, r1, r2, r3;
            LDSM_X4(r0, r1, r2, r3, Bhb + (uint32_t)(p * 16 * SKH * 2) + kb2);
            bhf[p*2][0] = r0; bhf[p*2][1] = r1;
            bhf[p*2+1][0] = r2; bhf[p*2+1][1] = r3;
            LDSM_X4(r0, r1, r2, r3, Blb + (uint32_t)(p * 16 * SKH * 2) + kb2);
            blf[p*2][0] = r0; blf[p*2][1] = r1;
            blf[p*2+1][0] = r2; blf[p*2+1][1] = r3;
        }
        uint32_t ah[2][4], al[2][4];
#pragma unroll
        for (int mt = 0; mt < 2; ++mt) {
            LDSM_X4(ah[mt][0], ah[mt][1], ah[mt][2], ah[mt][3],
                    Ahb + (uint32_t)(mt * 16 * SKH * 2) + kb2);
            LDSM_X4(al[mt][0], al[mt][1], al[mt][2], al[mt][3],
                    Alb + (uint32_t)(mt * 16 * SKH * 2) + kb2);
        }
#pragma unroll
        for (int nt = 0; nt < 8; ++nt)
#pragma unroll
            for (int mt = 0; mt < 2; ++mt) {
                mma_f16(acc[mt][nt][0], acc[mt][nt][1], acc[mt][nt][2], acc[mt][nt][3],
                        ah[mt][0], ah[mt][1], ah[mt][2], ah[mt][3],
                        bhf[nt][0], bhf[nt][1]);
                mma_f16(acc[mt][nt][0], acc[mt][nt][1], acc[mt][nt][2], acc[mt][nt][3],
                        al[mt][0], al[mt][1], al[mt][2], al[mt][3],
                        bhf[nt][0], bhf[nt][1]);
                mma_f16(acc[mt][nt][0], acc[mt][nt][1], acc[mt][nt][2], acc[mt][nt][3],
                        ah[mt][0], ah[mt][1], ah[mt][2], ah[mt][3],
                        blf[nt][0], blf[nt][1]);
            }
    }

    const int qr = lane >> 2, qc = lane & 3;
#pragma unroll
    for (int mt = 0; mt < 2; ++mt) {
        const int row = wm + mt * 16 + qr;
#pragma unroll
        for (int nt = 0; nt < 8; ++nt) {
            const int col = wn + nt * 8 + qc * 2;
            float* p0 = eb + ((size_t)(bh0 + row) * Sdim + j) * Sdim + col;
            float* p1 = eb + ((size_t)(bh0 + row + 8) * Sdim + j) * Sdim + col;
            *(float2*)p0 = make_float2(acc[mt][nt][0], acc[mt][nt][1]);
            *(float2*)p1 = make_float2(acc[mt][nt][2], acc[mt][nt][3]);
        }
    }
}

// ==================== attention scores + softmax (QK via mma) ==============
#define ATTM_BYTES (128 * 129 * 4)      /* 66048 >= 4*EBT*2 = 40960 */
__global__ __launch_bounds__(256, 2) void attn_mma(
    const __half* __restrict__ qkvh, const __half* __restrict__ qkvl,
    const float* __restrict__ eb, const unsigned char* __restrict__ mask,
    __half* __restrict__ ath, __half* __restrict__ atl)
{
    extern __shared__ char asm_[];
    __half* hq = (__half*)asm_;                    // phase A: Qh Ql Kh Kl
    float (*Sc)[129] = (float(*)[129])asm_;        // phase B: scores (union)
    const uint32_t s0 = smem_u32(hq);
    const int bh = blockIdx.x;
    const int b = bh >> 3, h = bh & 7;
    const int tid = threadIdx.x;
    const int lane = tid & 31, wid = tid >> 5;
    const int wm = (wid >> 1) * 32, wn = (wid & 1) * 64;

    {
        const int t = tid >> 6, u = tid & 63;
        const __half* srcb = (t == 0 || t == 2) ? qkvh : qkvl;
        const size_t sec = (t < 2) ? 0 : 256;
#pragma unroll
        for (int rr = 0; rr < 2; ++rr) {
            const int r = u + rr * 64;
            const size_t soff = (size_t)(b * Sdim + r) * QKVS + sec + h * HDim;
            const uint32_t dst = s0 + (uint32_t)((t * EBT + r * SKH) * 2);
#pragma unroll
            for (int sg = 0; sg < 4; ++sg)
                CP16(dst + sg * 16, srcb + soff + sg * 8);
        }
    }
    CPWAITALL();
    __syncthreads();

    const uint32_t a_loff = (uint32_t)(((lane & 15) * SKH + ((lane >> 4) << 3)) * 2);
    const uint32_t b_loff = (uint32_t)((((lane & 7) + ((lane >> 4) << 3)) * SKH
                                        + (((lane >> 3) & 1) << 3)) * 2);
    const uint32_t Ahb = s0 + (uint32_t)(wm * SKH * 2) + a_loff;
    const uint32_t Alb = Ahb + EBT * 2;
    const uint32_t Bhb = s0 + (uint32_t)(2 * EBT * 2) + (uint32_t)(wn * SKH * 2) + b_loff;
    const uint32_t Blb = Bhb + EBT * 2;

    float acc[2][8][4];
#pragma unroll
    for (int mt = 0; mt < 2; ++mt)
#pragma unroll
        for (int nt = 0; nt < 8; ++nt)
#pragma unroll
            for (int e = 0; e < 4; ++e) acc[mt][nt][e] = 0.f;

#pragma unroll
    for (int ss = 0; ss < 2; ++ss) {
        const uint32_t kb2 = ss * 32;
        uint32_t bhf[8][2], blf[8][2];
#pragma unroll
        for (int p = 0; p < 4; ++p) {
            uint32_t r0, r1, r2, r3;
            LDSM_X4(r0, r1, r2, r3, Bhb + (uint32_t)(p * 16 * SKH * 2) + kb2);
            bhf[p*2][0] = r0; bhf[p*2][1] = r1;
            bhf[p*2+1][0] = r2; bhf[p*2+1][1] = r3;
            LDSM_X4(r0, r1, r2, r3, Blb + (uint32_t)(p * 16 * SKH * 2) + kb2);
            blf[p*2][0] = r0; blf[p*2][1] = r1;
            blf[p*2+1][0] = r2; blf[p*2+1][1] = r3;
        }
        uint32_t ah[2][4], al[2][4];
#pragma unroll
        for (int mt = 0; mt < 2; ++mt) {
            LDSM_X4(ah[mt][0], ah[mt][1], ah[mt][2], ah[mt][3],
                    Ahb + (uint32_t)(mt * 16 * SKH * 2) + kb2);
            LDSM_X4(al[mt][0], al[mt][1], al[mt][2], al[mt][3],
                    Alb + (uint32_t)(mt * 16 * SKH * 2) + kb2);
        }
#pragma unroll
        for (int nt = 0; nt < 8; ++nt)
#pragma unroll
            for (int mt = 0; mt < 2; ++mt) {
                mma_f16(acc[mt][nt][0], acc[mt][nt][1], acc[mt][nt][2], acc[mt][nt][3],
                        ah[mt][0], ah[mt][1], ah[mt][2], ah[mt][3],
                        bhf[nt][0], bhf[nt][1]);
                mma_f16(acc[mt][nt][0], acc[mt][nt][1], acc[mt][nt][2], acc[mt][nt][3],
                        al[mt][0], al[mt][1], al[mt][2], al[mt][3],
                        bhf[nt][0], bhf[nt][1]);
                mma_f16(acc[mt][nt][0], acc[mt][nt][1], acc[mt][nt][2], acc[mt][nt][3],
                        ah[mt][0], ah[mt][1], ah[mt][2], ah[mt][3],
                        blf[nt][0], blf[nt][1]);
            }
    }
    __syncthreads();          // QK tiles dead; Sc may reuse

    for (int jj = wid; jj < Sdim; jj += 8) {
        float4 t4 = *(const float4*)(eb + ((size_t)bh * Sdim + jj) * Sdim + lane * 4);
        Sc[lane*4+0][jj] = t4.x; Sc[lane*4+1][jj] = t4.y;
        Sc[lane*4+2][jj] = t4.z; Sc[lane*4+3][jj] = t4.w;
    }
    __syncthreads();

    const float scale = 0.17677669529663687f;
    const float NEGINF = -__int_as_float(0x7f800000);
    const int qr = lane >> 2, qc = lane & 3;
#pragma unroll
    for (int mt = 0; mt < 2; ++mt) {
        const int row = wm + mt * 16 + qr;
#pragma unroll
        for (int nt = 0; nt < 8; ++nt) {
            const int col = wn + nt * 8 + qc * 2;
#pragma unroll
            for (int rr = 0; rr < 2; ++rr) {
                const int r = row + rr * 8;
                const unsigned char* mp = mask + ((size_t)bh * Sdim + r) * Sdim + col;
                float s0v = (acc[mt][nt][rr*2+0] + Sc[r][col])     * scale;
                float s1v = (acc[mt][nt][rr*2+1] + Sc[r][col + 1]) * scale;
                if (mp[0]) s0v = NEGINF;
                if (mp[1]) s1v = NEGINF;
                Sc[r][col]     = s0v;
                Sc[r][col + 1] = s1v;
            }
        }
    }
    __syncthreads();

    for (int r = wid; r < Sdim; r += 8) {
        float vals[4];
#pragma unroll
        for (int c = 0; c < 4; c++) vals[c] = Sc[r][lane + 32 * c];
        float m = fmaxf(fmaxf(vals[0], vals[1]), fmaxf(vals[2], vals[3]));
#pragma unroll
        for (int o = 16; o > 0; o >>= 1) m = fmaxf(m, __shfl_xor_sync(0xffffffffu, m, o));
        float ssum = 0.f;
#pragma unroll
        for (int c = 0; c < 4; c++) { vals[c] = __expf(vals[c] - m); ssum += vals[c]; }
#pragma unroll
        for (int o = 16; o > 0; o >>= 1) ssum += __shfl_xor_sync(0xffffffffu, ssum, o);
        float inv = 1.f / ssum;
        __half* hp = ath + ((size_t)bh * Sdim + r) * Sdim;
        __half* lp = atl + ((size_t)bh * Sdim + r) * Sdim;
#pragma unroll
        for (int c = 0; c < 4; c++) {
            float p = vals[c] * inv;
            __half hh_, ll_;
            split16(p, hh_, ll_);
            hp[lane + 32 * c] = hh_;
            lp[lane + 32 * c] = ll_;
        }
    }
}

// ==================== PV via fp16 3-pass mma (per bh) ======================
#define EVSK 136
#define EVA_B (128 * EVSK * 2)          /* 34816 B */
#define EVB_B (32 * EVSK * 2)           /* 8704 B */
#define EVM_BYTES (2 * EVA_B + 2 * EVB_B)  /* 87040 B */
__global__ __launch_bounds__(256) void pv_mma(
    const __half* __restrict__ ath, const __half* __restrict__ atl,
    const __half* __restrict__ qkvh, const __half* __restrict__ qkvl,
    float* __restrict__ ctx)
{
    extern __shared__ __half es[];
    const uint32_t s0 = smem_u32(es);
    const int bh = blockIdx.x;
    const int b = bh >> 3, h = bh & 7;
    const int tid = threadIdx.x, lane = tid & 31, wid = tid >> 5;

#pragma unroll
    for (int ss = 0; ss < 8; ++ss) {
        const int seg = tid + ss * 256;
        const int r = seg >> 4, sg = seg & 15;
        const size_t src = ((size_t)bh * Sdim + r) * Sdim + sg * 8;
        const uint32_t dst = s0 + (uint32_t)((r * EVSK + sg * 8) * 2);
        CP16(dst, ath + src);
        CP16(dst + EVA_B, atl + src);
    }
    {
        const uint32_t vth = 2 * EVA_B / 2;
#pragma unroll
        for (int e = 0; e < 8; ++e) {
            const int idx = e * 256 + tid;
            const int j = idx >> 4, dp = (idx & 15) * 2;
            const size_t src = (size_t)(b * Sdim + j) * QKVS + 512 + h * HDim + dp;
            __half2 vh = *(const __half2*)(qkvh + src);
            __half2 vl = *(const __half2*)(qkvl + src);
            es[vth + dp * EVSK + j]       = __low2half(vh);
            es[vth + (dp + 1) * EVSK + j] = __high2half(vh);
            es[vth + EVB_B / 2 + dp * EVSK + j]       = __low2half(vl);
            es[vth + EVB_B / 2 + (dp + 1) * EVSK + j] = __high2half(vl);
        }
    }
    CPWAITALL();
    __syncthreads();

    const uint32_t a_loff = (uint32_t)(((lane & 15) * EVSK + ((lane >> 4) << 3)) * 2);
    const uint32_t b_loff = (uint32_t)((((lane & 7) + ((lane >> 4) << 3)) * EVSK
                                        + (((lane >> 3) & 1) << 3)) * 2);
    const uint32_t Ahb = s0 + (uint32_t)(wid * 16 * EVSK * 2) + a_loff;
    const uint32_t Alb = Ahb + EVA_B;
    const uint32_t Bhb = s0 + 2 * EVA_B + b_loff;
    const uint32_t Blb = Bhb + EVB_B;

    float acc[4][4];
#pragma unroll
    for (int nt = 0; nt < 4; ++nt)
#pragma unroll
        for (int e = 0; e < 4; ++e) acc[nt][e] = 0.f;

#pragma unroll
    for (int ks = 0; ks < 8; ++ks) {
        const uint32_t kb2 = ks * 32;
        uint32_t bhf[4][2], blf[4][2];
#pragma unroll
        for (int p = 0; p < 2; ++p) {
            uint32_t r0, r1, r2, r3;
            LDSM_X4(r0, r1, r2, r3, Bhb + (uint32_t)(p * 16 * EVSK * 2) + kb2);
            bhf[p*2][0] = r0; bhf[p*2][1] = r1;
            bhf[p*2+1][0] = r2; bhf[p*2+1][1] = r3;
            LDSM_X4(r0, r1, r2, r3, Blb + (uint32_t)(p * 16 * EVSK * 2) + kb2);
            blf[p*2][0] = r0; blf[p*2][1] = r1;
            blf[p*2+1][0] = r2; blf[p*2+1][1] = r3;
        }
        uint32_t ah[4], al[4];
        LDSM_X4(ah[0], ah[1], ah[2], ah[3], Ahb + kb2);
        LDSM_X4(al[0], al[1], al[2], al[3], Alb + kb2);
#pragma unroll
        for (int nt = 0; nt < 4; ++nt) {
            mma_f16(acc[nt][0], acc[nt][1], acc[nt][2], acc[nt][3],
                    ah[0], ah[1], ah[2], ah[3], bhf[nt][0], bhf[nt][1]);
            mma_f16(acc[nt][0], acc[nt][1], acc[nt][2], acc[nt][3],
                    al[0], al[1], al[2], al[3], bhf[nt][0], bhf[nt][1]);
            mma_f16(acc[nt][0], acc[nt][1], acc[nt][2], acc[nt][3],
                    ah[0], ah[1], ah[2], ah[3], blf[nt][0], blf[nt][1]);
        }
    }

    const int qr = lane >> 2, qc = lane & 3;
    const int row0 = wid * 16 + qr;
#pragma unroll
    for (int nt = 0; nt < 4; ++nt) {
        const int d0 = nt * 8 + qc * 2;
#pragma unroll
        for (int rr = 0; rr < 2; ++rr) {
            const int i = row0 + rr * 8;
            const size_t idx = (size_t)(b * Sdim + i) * Ddim + h * HDim + d0;
            *(float2*)(ctx + idx) =
                make_float2(acc[nt][rr * 2 + 0], acc[nt][rr * 2 + 1]);
        }
    }
}

// ==================== edge-value via fp16 3-pass mma (per i) ===============
__global__ __launch_bounds__(256) void ev_mma(
    const __half* __restrict__ ath, const __half* __restrict__ atl,
    const float* __restrict__ ev, const float* __restrict__ ctx,
    __half* __restrict__ ch, __half* __restrict__ cl)
{
    extern __shared__ __half es[];
    const uint32_t s0 = smem_u32(es);
    const int i = blockIdx.x, bh0 = blockIdx.y * 128;
    const int tid = threadIdx.x, lane = tid & 31, wid = tid >> 5;

#pragma unroll
    for (int ss = 0; ss < 8; ++ss) {
        const int seg = tid + ss * 256;
        const int r = seg >> 4, sg = seg & 15;
        const size_t src = ((size_t)(bh0 + r) * Sdim + i) * Sdim + sg * 8;
        const uint32_t dst = s0 + (uint32_t)((r * EVSK + sg * 8) * 2);
        CP16(dst, ath + src);
        CP16(dst + EVA_B, atl + src);
    }
    {
        const float* evp = ev + (size_t)i * Sdim * HDim;
        const uint32_t vth = 2 * EVA_B / 2;
#pragma unroll
        for (int e = 0; e < 16; ++e) {
            const int idx = e * 256 + tid;
            const int d = idx & 31, jj = idx >> 5;
            float v = evp[idx];
            __half h, l;
            split16(v, h, l);
            es[vth + d * EVSK + jj] = h;
            es[vth + EVB_B / 2 + d * EVSK + jj] = l;
        }
    }
    CPWAITALL();
    __syncthreads();

    const uint32_t a_loff = (uint32_t)(((lane & 15) * EVSK + ((lane >> 4) << 3)) * 2);
    const uint32_t b_loff = (uint32_t)((((lane & 7) + ((lane >> 4) << 3)) * EVSK
                                        + (((lane >> 3) & 1) << 3)) * 2);
    const uint32_t Ahb = s0 + (uint32_t)(wid * 16 * EVSK * 2) + a_loff;
    const uint32_t Alb = Ahb + EVA_B;
    const uint32_t Bhb = s0 + 2 * EVA_B + b_loff;
    const uint32_t Blb = Bhb + EVB_B;

    float acc[4][4];
#pragma unroll
    for (int nt = 0; nt < 4; ++nt)
#pragma unroll
        for (int e = 0; e < 4; ++e) acc[nt][e] = 0.f;

#pragma unroll
    for (int ks = 0; ks < 8; ++ks) {
        const uint32_t kb2 = ks * 32;
        uint32_t bhf[4][2], blf[4][2];
#pragma unroll
        for (int p = 0; p < 2; ++p) {
            uint32_t r0, r1, r2, r3;
            LDSM_X4(r0, r1, r2, r3, Bhb + (uint32_t)(p * 16 * EVSK * 2) + kb2);
            bhf[p*2][0] = r0; bhf[p*2][1] = r1;
            bhf[p*2+1][0] = r2; bhf[p*2+1][1] = r3;
            LDSM_X4(r0, r1, r2, r3, Blb + (uint32_t)(p * 16 * EVSK * 2) + kb2);
            blf[p*2][0] = r0; blf[p*2][1] = r1;
            blf[p*2+1][0] = r2; blf[p*2+1][1] = r3;
        }
        uint32_t ah[4], al[4];
        LDSM_X4(ah[0], ah[1], ah[2], ah[3], Ahb + kb2);
        LDSM_X4(al[0], al[1], al[2], al[3], Alb + kb2);
#pragma unroll
        for (int nt = 0; nt < 4; ++nt) {
            mma_f16(acc[nt][0], acc[nt][1], acc[nt][2], acc[nt][3],
                    ah[0], ah[1], ah[2], ah[3], bhf[nt][0], bhf[nt][1]);
            mma_f16(acc[nt][0], acc[nt][1], acc[nt][2], acc[nt][3],
                    al[0], al[1], al[2], al[3], bhf[nt][0], bhf[nt][1]);
            mma_f16(acc[nt][0], acc[nt][1], acc[nt][2], acc[nt][3],
                    ah[0], ah[1], ah[2], ah[3], blf[nt][0], blf[nt][1]);
        }
    }

    const int qr = lane >> 2, qc = lane & 3;
    const int row0 = wid * 16 + qr;
#pragma unroll
    for (int nt = 0; nt < 4; ++nt) {
        const int d0 = nt * 8 + qc * 2;
#pragma unroll
        for (int rr = 0; rr < 2; ++rr) {
            const int bh = bh0 + row0 + rr * 8;
            const int b = bh >> 3, h = bh & 7;
            const size_t idx = (size_t)(b * Sdim + i) * Ddim + h * HDim + d0;
            float2 cur = *(const float2*)(ctx + idx);
            float v0 = cur.x + acc[nt][rr * 2 + 0];
            float v1 = cur.y + acc[nt][rr * 2 + 1];
            __half h0, l0, h1, l1;
            split16(v0, h0, l0); split16(v1, h1, l1);
            *(__half2*)(ch + idx) = __halves2half2(h0, h1);
            *(__half2*)(cl + idx) = __halves2half2(l0, l1);
        }
    }
}

// ============ fused weight transpose -> fp16 [N][K] ========================
__global__ __launch_bounds__(256) void tr_all(
    const float* __restrict__ Wq, const float* __restrict__ Wk,
    const float* __restrict__ Wv, const float* __restrict__ Wo,
    const float* __restrict__ W1, const float* __restrict__ W2,
    __half* __restrict__ wqkvT, __half* __restrict__ woT,
    __half* __restrict__ w1T, __half* __restrict__ w2T)
{
    __shared__ float t[32][33];
    const int tb = blockIdx.x;
    const float* src; __half* dst; int K, N, kx, nx;
    if (tb < 768) {
        int w = tb / 256, r = tb % 256, l = r / 64, q = r % 64;
        src = (w == 0 ? Wq : (w == 1 ? Wk : Wv)) + (size_t)l * 65536;
        dst = wqkvT + (size_t)l * 196608 + (size_t)w * 65536;
        K = 256; N = 256; kx = (q / 8) * 32; nx = (q % 8) * 32;
    } else if (tb < 1024) {
        int r = tb - 768, l = r / 64, q = r % 64;
        src = Wo + (size_t)l * 65536; dst = woT + (size_t)l * 65536;
        K = 256; N = 256; kx = (q / 8) * 32; nx = (q % 8) * 32;
    } else if (tb < 3072) {
        int r = tb - 1024, l = r / 512, q = r % 512;
        src = W1 + (size_t)l * 524288; dst = w1T + (size_t)l * 524288;
        K = 256; N = 2048; kx = (q / 64) * 32; nx = (q % 64) * 32;
    } else {
        int r = tb - 3072, l = r / 512, q = r % 512;
        src = W2 + (size_t)l * 524288; dst = w2T + (size_t)l * 524288;
        K = 2048; N = 256; kx = (q / 8) * 32; nx = (q % 8) * 32;
    }
    const int x = threadIdx.x & 31, y = threadIdx.x >> 5;
#pragma unroll
    for (int yy = y; yy < 32; yy += 8)
        t[yy][x] = src[(size_t)(kx + yy) * N + nx + x];
    __syncthreads();
#pragma unroll
    for (int yy = y; yy < 32; yy += 8)
        dst[(size_t)(nx + yy) * K + kx + x] = __float2half_rn(t[x][yy]);
}

// ---- prep -----------------------------------------------------------------
__global__ void prep_kernel(const float* __restrict__ facts, float* __restrict__ x,
                            __half* __restrict__ xh, __half* __restrict__ xl,
                            const float* __restrict__ ekey,
                            __half* __restrict__ ekh, __half* __restrict__ ekl,
                            const float* __restrict__ bq, const float* __restrict__ bk,
                            const float* __restrict__ bv, float* __restrict__ bqkv)
{
    size_t idx = (size_t)blockIdx.x * 256 + threadIdx.x;
    float v = facts[idx];
    x[idx] = v;
    __half h, l;
    split16(v, h, l);
    xh[idx] = h; xl[idx] = l;
    if (idx < EKN) {
        float e = ekey[idx];
        __half eh, el;
        split16(e, eh, el);
        ekh[idx] = eh; ekl[idx] = el;
    }
    if (idx < Ldim * QKVS) {
        int li = (int)(idx / QKVS), ji = (int)(idx % QKVS);
        float bvv;
        if (ji < 256)      bvv = bq[li * 256 + ji];
        else if (ji < 512) bvv = bk[li * 256 + ji - 256];
        else               bvv = bv[li * 256 + ji - 512];
        bqkv[idx] = bvv;
    }
}

// ---------------- host -----------------------------------------------------
extern "C" void kernel_launch(void* const* d_in, const int* in_sizes, int n_in,
                              void* d_out, int out_size)
{
    const float* facts = (const float*)d_in[0];
    const float* ekey  = (const float*)d_in[1];
    const float* evalp = (const float*)d_in[2];
    const unsigned char* mask = (const unsigned char*)d_in[3];
    const float *Wq, *Wk, *Wv, *Wo, *bq, *bk, *bv, *bo;
    if (in_sizes[5] == Ldim * Ddim) {
        Wq = (const float*)d_in[4];  bq = (const float*)d_in[5];
        Wk = (const float*)d_in[6];  bk = (const float*)d_in[7];
        Wv = (const float*)d_in[8];  bv = (const float*)d_in[9];
        Wo = (const float*)d_in[10]; bo = (const float*)d_in[11];
    } else {
        Wq = (const float*)d_in[4];  Wk = (const float*)d_in[5];
        Wv = (const float*)d_in[6];  Wo = (const float*)d_in[7];
        bq = (const float*)d_in[8];  bk = (const float*)d_in[9];
        bv = (const float*)d_in[10]; bo = (const float*)d_in[11];
    }
    const float* ln1g = (const float*)d_in[12];
    const float* ln1b = (const float*)d_in[13];
    const float* W1   = (const float*)d_in[14];
    const float* b1   = (const float*)d_in[15];
    const float* W2   = (const float*)d_in[16];
    const float* b2   = (const float*)d_in[17];
    const float* ln2g = (const float*)d_in[18];
    const float* ln2b = (const float*)d_in[19];

    float *x, *ctx, *eb, *bqkvp;
    __half *ath, *atl, *qkvh, *qkvl;
    __half *xh, *xl, *ch, *cl, *ffh, *ffl, *ekh, *ekl;
    __half *wqkvT, *woT, *w1T, *w2T;
    cudaGetSymbolAddress((void**)&x,    g_x);
    cudaGetSymbolAddress((void**)&ctx,  g_ctx);
    cudaGetSymbolAddress((void**)&eb,   g_eb);
    cudaGetSymbolAddress((void**)&ath,  g_ath);
    cudaGetSymbolAddress((void**)&atl,  g_atl);
    cudaGetSymbolAddress((void**)&qkvh, g_qkvh);
    cudaGetSymbolAddress((void**)&qkvl, g_qkvl);
    cudaGetSymbolAddress((void**)&xh,   g_xh);
    cudaGetSymbolAddress((void**)&xl,   g_xl);
    cudaGetSymbolAddress((void**)&ch,   g_ch);
    cudaGetSymbolAddress((void**)&cl,   g_cl);
    cudaGetSymbolAddress((void**)&ffh,  g_ffh);
    cudaGetSymbolAddress((void**)&ffl,  g_ffl);
    cudaGetSymbolAddress((void**)&ekh,  g_ekh);
    cudaGetSymbolAddress((void**)&ekl,  g_ekl);
    cudaGetSymbolAddress((void**)&wqkvT, g_wqkvT);
    cudaGetSymbolAddress((void**)&woT,  g_woT);
    cudaGetSymbolAddress((void**)&w1T,  g_w1T);
    cudaGetSymbolAddress((void**)&w2T,  g_w2T);
    cudaGetSymbolAddress((void**)&bqkvp, g_bqkv);

    cudaFuncSetAttribute(mma_gemm<false,true>,  cudaFuncAttributeMaxDynamicSharedMemorySize, GSMB);
    cudaFuncSetAttribute(mma_gemm<true,true>,   cudaFuncAttributeMaxDynamicSharedMemorySize, GSMB);
    cudaFuncSetAttribute(mma_gemm_ln, cudaFuncAttributeMaxDynamicSharedMemorySize, GSM2B);
    cudaFuncSetAttribute(attn_mma, cudaFuncAttributeMaxDynamicSharedMemorySize, ATTM_BYTES);
    cudaFuncSetAttribute(pv_mma,   cudaFuncAttributeMaxDynamicSharedMemorySize, EVM_BYTES);
    cudaFuncSetAttribute(ev_mma,   cudaFuncAttributeMaxDynamicSharedMemorySize, EVM_BYTES);

    // launches: 0 tr_all, 1 prep, 2 QKV, 3 ebias_mma (ncu target)
    tr_all<<<5120, 256>>>(Wq, Wk, Wv, Wo, W1, W2, wqkvT, woT, w1T, w2T);        // 0
    prep_kernel<<<NR * Ddim / 256, 256>>>(facts, x, xh, xl,
                                          ekey, ekh, ekl, bq, bk, bv, bqkvp);   // 1

    for (int l = 0; l < Ldim; l++) {
        mma_gemm<false,true><<<dim3(QKVS / 128, NR / 128), 256, GSMB>>>(
            xh, xl, wqkvT + (size_t)l * 3 * Ddim * Ddim, bqkvp + l * QKVS,
            nullptr, qkvh, qkvl, NR, QKVS, Ddim);                               // 2 (l=0)

        ebias_mma<<<dim3(Sdim, BHdim / 128), 256>>>(qkvh, qkvl, ekh, ekl, eb);  // 3 (l=0)
        attn_mma<<<BHdim, 256, ATTM_BYTES>>>(qkvh, qkvl, eb, mask, ath, atl);
        pv_mma<<<BHdim, 256, EVM_BYTES>>>(ath, atl, qkvh, qkvl, ctx);
        ev_mma<<<dim3(Sdim, BHdim / 128), 256, EVM_BYTES>>>(ath, atl, evalp,
                                                            ctx, ch, cl);

        // Wo GEMM + LN1 (residual x) fused
        mma_gemm_ln<<<NR / 128, 512, GSM2B>>>(
            ch, cl, woT + (size_t)l * Ddim * Ddim, bo + l * Ddim,
            x, ln1g + l * Ddim, ln1b + l * Ddim,
            x, xh, xl, nullptr, Ddim);

        mma_gemm<true,true><<<dim3(Fdim / 128, NR / 128), 256, GSMB>>>(
            xh, xl, w1T + (size_t)l * Fdim * Ddim, b1 + l * Fdim,
            nullptr, ffh, ffl, NR, Fdim, Ddim);

        // FFN2 GEMM + LN2 (x2) fused; final layer writes transposed d_out
        mma_gemm_ln<<<NR / 128, 512, GSM2B>>>(
            ffh, ffl, w2T + (size_t)l * Ddim * Fdim, b2 + l * Ddim,
            nullptr, ln2g + l * Ddim, ln2b + l * Ddim,
            x, xh, xl, (l == Ldim - 1) ? (float*)d_out : nullptr, Fdim);
    }
}